// round 5
// baseline (speedup 1.0000x reference)
#include <cuda_runtime.h>

#define NN   100000
#define EE   1600000
#define ET   (EE + NN)          // edges + self loops = 1,700,000
#define HID  128
#define NT   32                 // nodes per block in per-node kernels
#define TS   36                 // transposed smem row stride (floats)

// ---------------- scratch (device globals: no allocation allowed) -------------
__device__ __align__(16) float g_xw1 [(size_t)NN * HID];
__device__ __align__(16) float g_es1 [NN * 4];
__device__ __align__(16) float g_ed1 [NN * 4];
__device__ __align__(16) float g_out1[(size_t)NN * HID];
__device__ __align__(16) float g_xw2 [(size_t)NN * HID];
__device__ __align__(16) float g_es2 [NN];
__device__ __align__(16) float g_ed2 [NN];
__device__ __align__(16) float g_out2[(size_t)NN * HID];

// CSR (dst-grouped), rebuilt every launch (graph-capture safe, no allocs)
__device__ int g_cnt[NN];
__device__ int g_rs [NN + 1];
__device__ int g_cur[NN];
__device__ int g_csrc[ET];

__device__ __forceinline__ float lrelu01(float v) { return v > 0.f ? v : 0.01f * v; }
__device__ __forceinline__ float lrelu2 (float v) { return v > 0.f ? v : 0.2f  * v; }

// ---- packed fp32x2 helpers ---------------------------------------------------
__device__ __forceinline__ unsigned long long pack2(float x, float y) {
    unsigned long long r;
    asm("mov.b64 %0,{%1,%2};" : "=l"(r) : "f"(x), "f"(y));
    return r;
}
__device__ __forceinline__ float2 unpack2(unsigned long long v) {
    float2 r;
    asm("mov.b64 {%0,%1},%2;" : "=f"(r.x), "=f"(r.y) : "l"(v));
    return r;
}
__device__ __forceinline__ void ffma2(unsigned long long& d,
                                      unsigned long long a, unsigned long long b) {
    asm("fma.rn.f32x2 %0,%1,%2,%0;" : "+l"(d) : "l"(a), "l"(b));
}

// K-step over transposed activation tile: acc2[16] covers 32 nodes (16 pairs)
__device__ __forceinline__ void gemm_kstep(const float* __restrict__ arow,
                                           unsigned long long wp,
                                           unsigned long long* acc2) {
#pragma unroll
    for (int q = 0; q < 8; q++) {
        const ulonglong2 av = *(const ulonglong2*)(arow + 4 * q);
        ffma2(acc2[2 * q],     av.x, wp);
        ffma2(acc2[2 * q + 1], av.y, wp);
    }
}

template <int KLEN>
__device__ __forceinline__ void gemm_col(const float* __restrict__ w,
                                         const float* __restrict__ a_t,
                                         unsigned long long* acc2) {
#pragma unroll 4
    for (int k = 0; k < KLEN; k += 4) {
        const float4 wv = *(const float4*)(w + k);
        gemm_kstep(a_t + (k + 0) * TS, pack2(wv.x, wv.x), acc2);
        gemm_kstep(a_t + (k + 1) * TS, pack2(wv.y, wv.y), acc2);
        gemm_kstep(a_t + (k + 2) * TS, pack2(wv.z, wv.z), acc2);
        gemm_kstep(a_t + (k + 3) * TS, pack2(wv.w, wv.w), acc2);
    }
}

// ---------------- CSR build ---------------------------------------------------
__global__ void k_init_cnt() {
    int i = blockIdx.x * blockDim.x + threadIdx.x;
    if (i < NN) g_cnt[i] = 1;            // self loop pre-counted
}

__global__ void k_count(const int* __restrict__ ei) {
    int i = blockIdx.x * blockDim.x + threadIdx.x;
    if (i < EE) atomicAdd(&g_cnt[ei[EE + i]], 1);
}

__global__ void __launch_bounds__(1024, 1) k_scan() {  // single block
    __shared__ int ssum[1024];
    const int t = threadIdx.x;
    const int C = (NN + 1023) / 1024;
    const int beg = t * C;
    const int end = (beg + C < NN) ? beg + C : NN;
    int s = 0;
    for (int i = beg; i < end; i++) s += g_cnt[i];
    ssum[t] = s;
    __syncthreads();
    for (int o = 1; o < 1024; o <<= 1) {
        int v = (t >= o) ? ssum[t - o] : 0;
        __syncthreads();
        ssum[t] += v;
        __syncthreads();
    }
    int pre = (t == 0) ? 0 : ssum[t - 1];
    for (int i = beg; i < end; i++) {
        g_rs[i] = pre;
        g_cur[i] = pre;
        pre += g_cnt[i];
    }
    if (t == 0) g_rs[NN] = ET;
}

__global__ void k_fill(const int* __restrict__ ei) {
    int i = blockIdx.x * blockDim.x + threadIdx.x;
    if (i >= ET) return;
    int src, dst;
    if (i < EE) { src = ei[i]; dst = ei[EE + i]; }
    else        { src = dst = i - EE; }
    const int slot = atomicAdd(&g_cur[dst], 1);
    g_csrc[slot] = src;
}

// ---------------- features -> x -> Wi -> g1 projection + attn logits ---------
__global__ void __launch_bounds__(128) k_features(
    const float* __restrict__ des, const float* __restrict__ twt,
    const float* __restrict__ npr, const float* __restrict__ cpr,
    const float* __restrict__ Wd, const float* __restrict__ bd,
    const float* __restrict__ Wt, const float* __restrict__ bt,
    const float* __restrict__ Wn, const float* __restrict__ bn,
    const float* __restrict__ Wc, const float* __restrict__ bc,
    const float* __restrict__ Wi, const float* __restrict__ bi,
    const float* __restrict__ g1W, const float* __restrict__ g1as,
    const float* __restrict__ g1ad)
{
    __shared__ __align__(16) float sh_t[128 * TS];     // x transposed [feat][node]
    __shared__ __align__(16) float sbuf[2 * 96 * TS];  // stage1 tiles / red / x2_t

    const int tid  = threadIdx.x;
    const int n0   = blockIdx.x * NT;
    const int j    = tid & 63;          // stage-1 column
    const int half = tid >> 6;          // stage-1 K half

    unsigned long long acc2[16];
#pragma unroll
    for (int p = 0; p < 16; p++) acc2[p] = 0ull;

    // ---- stage 1: d/t columns, 8 chunks of K=96, split across thread halves --
    {
        const float* wrow  = (j < 32) ? Wd + (size_t)j * 768
                                      : Wt + (size_t)(j - 32) * 768;
        const float* sbase = (j < 32) ? sbuf : sbuf + 96 * TS;

        for (int c = 0; c < 8; c++) {
            const int kb = c * 96;
            // float4 tile loads: 32 nodes x 24 float4 per array
            for (int idx = tid; idx < 32 * 24; idx += 128) {
                const int r = idx / 24, c4 = idx - r * 24;
                const float4 dv = *(const float4*)(des + (size_t)(n0 + r) * 768 + kb + 4 * c4);
                const float4 tv = *(const float4*)(twt + (size_t)(n0 + r) * 768 + kb + 4 * c4);
                float* s0 = sbuf + (4 * c4) * TS + r;
                s0[0]      = dv.x; s0[TS]     = dv.y;
                s0[2 * TS] = dv.z; s0[3 * TS] = dv.w;
                float* s1 = s0 + 96 * TS;
                s1[0]      = tv.x; s1[TS]     = tv.y;
                s1[2 * TS] = tv.z; s1[3 * TS] = tv.w;
            }
            __syncthreads();
            if ((c >> 2) == half) {
                gemm_col<96>(wrow + kb, sbase, acc2);
            }
            __syncthreads();
        }
    }

    // ---- stage 1 epilogue: cross-half reduce + num/cat columns ---------------
    {
        float* red = sbuf;   // 64 cols x 32 nodes
        if (half == 1) {
#pragma unroll
            for (int p = 0; p < 16; p++)
                *(unsigned long long*)(red + j * 32 + 2 * p) = acc2[p];
        }
        __syncthreads();
        if (half == 0) {
            const float b = (j < 32) ? bd[j] : bt[j - 32];
#pragma unroll
            for (int p = 0; p < 16; p++) {
                const float2 o  = unpack2(acc2[p]);
                const float2 r2 = *(const float2*)(red + j * 32 + 2 * p);
                sh_t[j * TS + 2 * p]     = lrelu01(o.x + r2.x + b);
                sh_t[j * TS + 2 * p + 1] = lrelu01(o.y + r2.y + b);
            }
        } else if (j < 32) {     // num_prop -> column 64+j
            const float w0 = Wn[j * 5], w1 = Wn[j * 5 + 1], w2 = Wn[j * 5 + 2],
                        w3 = Wn[j * 5 + 3], w4 = Wn[j * 5 + 4];
            const float b = bn[j];
            for (int m = 0; m < NT; m++) {
                const float* r = npr + (size_t)(n0 + m) * 5;
                sh_t[(64 + j) * TS + m] =
                    lrelu01(r[0]*w0 + r[1]*w1 + r[2]*w2 + r[3]*w3 + r[4]*w4 + b);
            }
        } else {                 // cat_prop -> column 96+(j-32)
            const int jj = j - 32;
            const float w0 = Wc[jj * 3], w1 = Wc[jj * 3 + 1], w2 = Wc[jj * 3 + 2];
            const float b = bc[jj];
            for (int m = 0; m < NT; m++) {
                const float* r = cpr + (size_t)(n0 + m) * 3;
                sh_t[(96 + jj) * TS + m] = lrelu01(r[0]*w0 + r[1]*w1 + r[2]*w2 + b);
            }
        }
    }
    __syncthreads();

    // ---- stage 2: x2 = lrelu(x @ Wi^T + bi), column = tid -------------------
    {
#pragma unroll
        for (int p = 0; p < 16; p++) acc2[p] = 0ull;
        gemm_col<128>(Wi + (size_t)tid * HID, sh_t, acc2);
        const float b = bi[tid];
        float* x2_t = sbuf;   // 128 x TS fits
#pragma unroll
        for (int p = 0; p < 16; p++) {
            const float2 o = unpack2(acc2[p]);
            x2_t[tid * TS + 2 * p]     = lrelu01(o.x + b);
            x2_t[tid * TS + 2 * p + 1] = lrelu01(o.y + b);
        }
    }
    __syncthreads();

    // ---- stage 3: xw1 = x2 @ g1_W^T ; per-head logits -----------------------
    {
#pragma unroll
        for (int p = 0; p < 16; p++) acc2[p] = 0ull;
        gemm_col<128>(g1W + (size_t)tid * HID, sbuf, acc2);

        float vals[NT];
#pragma unroll
        for (int p = 0; p < 16; p++) {
            const float2 o = unpack2(acc2[p]);
            vals[2 * p] = o.x; vals[2 * p + 1] = o.y;
        }
#pragma unroll
        for (int m = 0; m < NT; m++)
            g_xw1[(size_t)(n0 + m) * HID + tid] = vals[m];

        const float aj = g1as[tid], dj = g1ad[tid];
        const int h = tid >> 5, lane = tid & 31;    // warp == head
#pragma unroll
        for (int m = 0; m < NT; m++) {
            float vs = vals[m] * aj, vd = vals[m] * dj;
#pragma unroll
            for (int o = 16; o > 0; o >>= 1) {
                vs += __shfl_xor_sync(0xffffffffu, vs, o);
                vd += __shfl_xor_sync(0xffffffffu, vd, o);
            }
            if (lane == 0) {
                g_es1[(n0 + m) * 4 + h] = vs;
                g_ed1[(n0 + m) * 4 + h] = vd;
            }
        }
    }
}

// ---------------- GAT1 aggregation: warp-per-dst gather, fused exp, MLP4 ------
__global__ void __launch_bounds__(256) k_agg1(const float* __restrict__ g1b) {
    const int d = (blockIdx.x * blockDim.x + threadIdx.x) >> 5;
    const int lane = threadIdx.x & 31;
    if (d >= NN) return;
    const int beg = g_rs[d], end = g_rs[d + 1];
    const int h = lane >> 3;                 // head for dims 4*lane..4*lane+3
    const float edv = g_ed1[d * 4 + h];
    float4 acc = {0.f, 0.f, 0.f, 0.f};
    float den = 0.f;
    int s = beg;
    for (; s + 4 <= end; s += 4) {
        const int i0 = __ldg(&g_csrc[s]),     i1 = __ldg(&g_csrc[s + 1]);
        const int i2 = __ldg(&g_csrc[s + 2]), i3 = __ldg(&g_csrc[s + 3]);
        const float e0 = __ldg(&g_es1[i0 * 4 + h]);
        const float e1 = __ldg(&g_es1[i1 * 4 + h]);
        const float e2 = __ldg(&g_es1[i2 * 4 + h]);
        const float e3 = __ldg(&g_es1[i3 * 4 + h]);
        const float4 x0 = *(const float4*)(g_xw1 + (size_t)i0 * HID + lane * 4);
        const float4 x1 = *(const float4*)(g_xw1 + (size_t)i1 * HID + lane * 4);
        const float4 x2 = *(const float4*)(g_xw1 + (size_t)i2 * HID + lane * 4);
        const float4 x3 = *(const float4*)(g_xw1 + (size_t)i3 * HID + lane * 4);
        const float v0 = __expf(lrelu2(e0 + edv));
        const float v1 = __expf(lrelu2(e1 + edv));
        const float v2 = __expf(lrelu2(e2 + edv));
        const float v3 = __expf(lrelu2(e3 + edv));
        acc.x += x0.x*v0 + x1.x*v1 + x2.x*v2 + x3.x*v3;
        acc.y += x0.y*v0 + x1.y*v1 + x2.y*v2 + x3.y*v3;
        acc.z += x0.z*v0 + x1.z*v1 + x2.z*v2 + x3.z*v3;
        acc.w += x0.w*v0 + x1.w*v1 + x2.w*v2 + x3.w*v3;
        den += v0 + v1 + v2 + v3;
    }
    for (; s < end; s++) {
        const int src = __ldg(&g_csrc[s]);
        const float es = __ldg(&g_es1[src * 4 + h]);
        const float ev = __expf(lrelu2(es + edv));
        const float4 xs = *(const float4*)(g_xw1 + (size_t)src * HID + lane * 4);
        acc.x += xs.x * ev; acc.y += xs.y * ev;
        acc.z += xs.z * ev; acc.w += xs.w * ev;
        den += ev;
    }
    const float inv = 1.f / den;
    const float4 b = ((const float4*)g1b)[lane];
    float4 o;
    o.x = acc.x * inv + b.x; o.y = acc.y * inv + b.y;
    o.z = acc.z * inv + b.z; o.w = acc.w * inv + b.w;
    *(float4*)(g_out1 + (size_t)d * HID + lane * 4) = o;
}

// ---------------- GAT2 projection + attn logits -------------------------------
__global__ void __launch_bounds__(128) k_gat2_prep(
    const float* __restrict__ g2W,
    const float* __restrict__ g2as, const float* __restrict__ g2ad)
{
    __shared__ __align__(16) float sx_t[128 * TS];
    __shared__ float sp[2][4][NT];
    const int tid = threadIdx.x, n0 = blockIdx.x * NT;

    for (int idx = tid; idx < NT * HID; idx += 128) {
        const int m = idx >> 7, c = idx & 127;
        sx_t[c * TS + m] = g_out1[(size_t)(n0 + m) * HID + c];
    }
    __syncthreads();

    unsigned long long acc2[16];
#pragma unroll
    for (int p = 0; p < 16; p++) acc2[p] = 0ull;
    gemm_col<128>(g2W + (size_t)tid * HID, sx_t, acc2);

    float vals[NT];
#pragma unroll
    for (int p = 0; p < 16; p++) {
        const float2 o = unpack2(acc2[p]);
        vals[2 * p] = o.x; vals[2 * p + 1] = o.y;
    }
#pragma unroll
    for (int m = 0; m < NT; m++)
        g_xw2[(size_t)(n0 + m) * HID + tid] = vals[m];

    const float aj = g2as[tid], dj = g2ad[tid];
    const int wp = tid >> 5, lane = tid & 31;
#pragma unroll
    for (int m = 0; m < NT; m++) {
        float vs = vals[m] * aj, vd = vals[m] * dj;
#pragma unroll
        for (int o = 16; o > 0; o >>= 1) {
            vs += __shfl_xor_sync(0xffffffffu, vs, o);
            vd += __shfl_xor_sync(0xffffffffu, vd, o);
        }
        if (lane == 0) { sp[0][wp][m] = vs; sp[1][wp][m] = vd; }
    }
    __syncthreads();
    if (tid < 32) {
        g_es2[n0 + tid] = sp[0][0][tid] + sp[0][1][tid] + sp[0][2][tid] + sp[0][3][tid];
    } else if (tid < 64) {
        const int m = tid - 32;
        g_ed2[n0 + m] = sp[1][0][m] + sp[1][1][m] + sp[1][2][m] + sp[1][3][m];
    }
}

// ---------------- GAT2 aggregation: fused exp, MLP4 ---------------------------
__global__ void __launch_bounds__(256) k_agg2(const float* __restrict__ g2b) {
    const int d = (blockIdx.x * blockDim.x + threadIdx.x) >> 5;
    const int lane = threadIdx.x & 31;
    if (d >= NN) return;
    const int beg = g_rs[d], end = g_rs[d + 1];
    const float edv = g_ed2[d];
    float4 acc = {0.f, 0.f, 0.f, 0.f};
    float den = 0.f;
    int s = beg;
    for (; s + 4 <= end; s += 4) {
        const int i0 = __ldg(&g_csrc[s]),     i1 = __ldg(&g_csrc[s + 1]);
        const int i2 = __ldg(&g_csrc[s + 2]), i3 = __ldg(&g_csrc[s + 3]);
        const float e0 = __ldg(&g_es2[i0]);
        const float e1 = __ldg(&g_es2[i1]);
        const float e2 = __ldg(&g_es2[i2]);
        const float e3 = __ldg(&g_es2[i3]);
        const float4 x0 = *(const float4*)(g_xw2 + (size_t)i0 * HID + lane * 4);
        const float4 x1 = *(const float4*)(g_xw2 + (size_t)i1 * HID + lane * 4);
        const float4 x2 = *(const float4*)(g_xw2 + (size_t)i2 * HID + lane * 4);
        const float4 x3 = *(const float4*)(g_xw2 + (size_t)i3 * HID + lane * 4);
        const float v0 = __expf(lrelu2(e0 + edv));
        const float v1 = __expf(lrelu2(e1 + edv));
        const float v2 = __expf(lrelu2(e2 + edv));
        const float v3 = __expf(lrelu2(e3 + edv));
        acc.x += x0.x*v0 + x1.x*v1 + x2.x*v2 + x3.x*v3;
        acc.y += x0.y*v0 + x1.y*v1 + x2.y*v2 + x3.y*v3;
        acc.z += x0.z*v0 + x1.z*v1 + x2.z*v2 + x3.z*v3;
        acc.w += x0.w*v0 + x1.w*v1 + x2.w*v2 + x3.w*v3;
        den += v0 + v1 + v2 + v3;
    }
    for (; s < end; s++) {
        const int src = __ldg(&g_csrc[s]);
        const float es = __ldg(&g_es2[src]);
        const float ev = __expf(lrelu2(es + edv));
        const float4 xs = *(const float4*)(g_xw2 + (size_t)src * HID + lane * 4);
        acc.x += xs.x * ev; acc.y += xs.y * ev;
        acc.z += xs.z * ev; acc.w += xs.w * ev;
        den += ev;
    }
    const float inv = 1.f / den;
    const float4 b = ((const float4*)g2b)[lane];
    float4 o;
    o.x = acc.x * inv + b.x; o.y = acc.y * inv + b.y;
    o.z = acc.z * inv + b.z; o.w = acc.w * inv + b.w;
    *(float4*)(g_out2 + (size_t)d * HID + lane * 4) = o;
}

// ---------------- output head ------------------------------------------------
__global__ void __launch_bounds__(128) k_final(
    const float* __restrict__ Wo1,
    const float* __restrict__ bo1, const float* __restrict__ Wo2,
    const float* __restrict__ bo2, float* __restrict__ out)
{
    __shared__ __align__(16) float sx_t[128 * TS];
    __shared__ float sp[2][4][NT];
    const int tid = threadIdx.x, n0 = blockIdx.x * NT;

    for (int idx = tid; idx < NT * HID; idx += 128) {
        const int m = idx >> 7, c = idx & 127;
        sx_t[c * TS + m] = g_out2[(size_t)(n0 + m) * HID + c];
    }
    __syncthreads();

    unsigned long long acc2[16];
#pragma unroll
    for (int p = 0; p < 16; p++) acc2[p] = 0ull;
    gemm_col<128>(Wo1 + (size_t)tid * HID, sx_t, acc2);

    const float b1 = bo1[tid];
    const float w0o = Wo2[tid], w1o = Wo2[HID + tid];
    const int wp = tid >> 5, lane = tid & 31;
    float vals[NT];
#pragma unroll
    for (int p = 0; p < 16; p++) {
        const float2 o = unpack2(acc2[p]);
        vals[2 * p]     = lrelu01(o.x + b1);
        vals[2 * p + 1] = lrelu01(o.y + b1);
    }
#pragma unroll
    for (int m = 0; m < NT; m++) {
        float v0 = vals[m] * w0o, v1 = vals[m] * w1o;
#pragma unroll
        for (int o = 16; o > 0; o >>= 1) {
            v0 += __shfl_xor_sync(0xffffffffu, v0, o);
            v1 += __shfl_xor_sync(0xffffffffu, v1, o);
        }
        if (lane == 0) { sp[0][wp][m] = v0; sp[1][wp][m] = v1; }
    }
    __syncthreads();
    if (tid < 32) {
        out[(size_t)(n0 + tid) * 2] =
            sp[0][0][tid] + sp[0][1][tid] + sp[0][2][tid] + sp[0][3][tid] + bo2[0];
    } else if (tid < 64) {
        const int m = tid - 32;
        out[(size_t)(n0 + m) * 2 + 1] =
            sp[1][0][m] + sp[1][1][m] + sp[1][2][m] + sp[1][3][m] + bo2[1];
    }
}

// ---------------- launch ------------------------------------------------------
extern "C" void kernel_launch(void* const* d_in, const int* in_sizes, int n_in,
                              void* d_out, int out_size) {
    const float* des  = (const float*)d_in[0];
    const float* twt  = (const float*)d_in[1];
    const float* npr  = (const float*)d_in[2];
    const float* cpr  = (const float*)d_in[3];
    const int*   ei   = (const int*)d_in[4];   // JAX x64 disabled -> int32
    const float* Wd = (const float*)d_in[5];   const float* bd = (const float*)d_in[6];
    const float* Wt = (const float*)d_in[7];   const float* bt = (const float*)d_in[8];
    const float* Wn = (const float*)d_in[9];   const float* bn = (const float*)d_in[10];
    const float* Wc = (const float*)d_in[11];  const float* bc = (const float*)d_in[12];
    const float* Wi = (const float*)d_in[13];  const float* bi = (const float*)d_in[14];
    const float* g1W  = (const float*)d_in[15];
    const float* g1as = (const float*)d_in[16];
    const float* g1ad = (const float*)d_in[17];
    const float* g1b  = (const float*)d_in[18];
    const float* g2W  = (const float*)d_in[19];
    const float* g2as = (const float*)d_in[20];
    const float* g2ad = (const float*)d_in[21];
    const float* g2b  = (const float*)d_in[22];
    const float* Wo1  = (const float*)d_in[23]; const float* bo1 = (const float*)d_in[24];
    const float* Wo2  = (const float*)d_in[25]; const float* bo2 = (const float*)d_in[26];
    float* out = (float*)d_out;

    // order chosen so k_features sits at the ncu-captured launch index (3)
    k_init_cnt<<<(NN + 255) / 256, 256>>>();
    k_count<<<(EE + 255) / 256, 256>>>(ei);
    k_scan<<<1, 1024>>>();
    k_features<<<NN / NT, 128>>>(des, twt, npr, cpr, Wd, bd, Wt, bt, Wn, bn,
                                 Wc, bc, Wi, bi, g1W, g1as, g1ad);
    k_fill<<<(ET + 255) / 256, 256>>>(ei);     // before agg1, after features
    k_agg1<<<(NN * 32 + 255) / 256, 256>>>(g1b);
    k_gat2_prep<<<NN / NT, 128>>>(g2W, g2as, g2ad);
    k_agg2<<<(NN * 32 + 255) / 256, 256>>>(g2b);
    k_final<<<NN / NT, 128>>>(Wo1, bo1, Wo2, bo2, out);
}

// round 6
// speedup vs baseline: 1.1828x; 1.1828x over previous
#include <cuda_runtime.h>

#define NN   100000
#define EE   1600000
#define ET   (EE + NN)
#define HID  128
#define NT   32                 // nodes per block
#define TS   36                 // transposed activation stride (floats)

// ---------------- scratch globals --------------------------------------------
__device__ __align__(16) float g_xw1 [(size_t)NN * HID];
__device__ __align__(16) float g_es1 [NN * 4];
__device__ __align__(16) float g_ed1 [NN * 4];
__device__ __align__(16) float g_out1[(size_t)NN * HID];
__device__ __align__(16) float g_xw2 [(size_t)NN * HID];
__device__ __align__(16) float g_es2 [NN];
__device__ __align__(16) float g_ed2 [NN];
__device__ __align__(16) float g_out2[(size_t)NN * HID];

// pre-transposed weights: w_t[k][col]
__device__ __align__(16) float g_W1t [768 * 64];    // [k][col] col<32:Wd col>=32:Wt
__device__ __align__(16) float g_Wit [128 * 128];
__device__ __align__(16) float g_g1t [128 * 128];
__device__ __align__(16) float g_g2t [128 * 128];
__device__ __align__(16) float g_Wo1t[128 * 128];

// CSR (dst-grouped)
__device__ int g_cnt[NN];
__device__ int g_rs [NN + 1];
__device__ int g_cur[NN];
__device__ int g_csrc[ET];

__device__ __forceinline__ float lrelu01(float v) { return v > 0.f ? v : 0.01f * v; }
__device__ __forceinline__ float lrelu2 (float v) { return v > 0.f ? v : 0.2f  * v; }

// ---- packed fp32x2 helpers ---------------------------------------------------
__device__ __forceinline__ unsigned long long pack2(float x, float y) {
    unsigned long long r;
    asm("mov.b64 %0,{%1,%2};" : "=l"(r) : "f"(x), "f"(y));
    return r;
}
__device__ __forceinline__ float2 unpack2(unsigned long long v) {
    float2 r;
    asm("mov.b64 {%0,%1},%2;" : "=f"(r.x), "=f"(r.y) : "l"(v));
    return r;
}
__device__ __forceinline__ void ffma2(unsigned long long& d,
                                      unsigned long long a, unsigned long long b) {
    asm("fma.rn.f32x2 %0,%1,%2,%0;" : "+l"(d) : "l"(a), "l"(b));
}

// 4 cols x 8 nodes tile GEMM over K=128; wt global [k][128], a_t smem stride TS
__device__ __forceinline__ void gemm_tile128(const float* __restrict__ wt,
                                             const float* __restrict__ a_t,
                                             int cg4, int ng8,
                                             unsigned long long acc[4][4]) {
#pragma unroll 4
    for (int k = 0; k < 128; k++) {
        const float4 wv = *(const float4*)(wt + k * 128 + cg4);
        const ulonglong2 a01 = *(const ulonglong2*)(a_t + k * TS + ng8);
        const ulonglong2 a23 = *(const ulonglong2*)(a_t + k * TS + ng8 + 4);
        const unsigned long long w0 = pack2(wv.x, wv.x), w1 = pack2(wv.y, wv.y);
        const unsigned long long w2 = pack2(wv.z, wv.z), w3 = pack2(wv.w, wv.w);
        ffma2(acc[0][0], a01.x, w0); ffma2(acc[0][1], a01.y, w0);
        ffma2(acc[0][2], a23.x, w0); ffma2(acc[0][3], a23.y, w0);
        ffma2(acc[1][0], a01.x, w1); ffma2(acc[1][1], a01.y, w1);
        ffma2(acc[1][2], a23.x, w1); ffma2(acc[1][3], a23.y, w1);
        ffma2(acc[2][0], a01.x, w2); ffma2(acc[2][1], a01.y, w2);
        ffma2(acc[2][2], a23.x, w2); ffma2(acc[2][3], a23.y, w2);
        ffma2(acc[3][0], a01.x, w3); ffma2(acc[3][1], a01.y, w3);
        ffma2(acc[3][2], a23.x, w3); ffma2(acc[3][3], a23.y, w3);
    }
}

// ---------------- weight transpose (once per launch) --------------------------
__global__ void k_wprep(const float* __restrict__ Wd, const float* __restrict__ Wt,
                        const float* __restrict__ Wi, const float* __restrict__ g1W,
                        const float* __restrict__ g2W, const float* __restrict__ Wo1) {
    const int i = blockIdx.x * blockDim.x + threadIdx.x;
    if (i < 768 * 64) {
        const int col = i & 63, k = i >> 6;
        g_W1t[i] = (col < 32) ? Wd[col * 768 + k] : Wt[(col - 32) * 768 + k];
    } else if (i < 768 * 64 + 4 * 128 * 128) {
        const int j = i - 768 * 64;
        const int a = j >> 14, r = j & 16383;
        const int col = r & 127, k = r >> 7;
        const float v = (a == 0 ? Wi : a == 1 ? g1W : a == 2 ? g2W : Wo1)[col * 128 + k];
        (a == 0 ? g_Wit : a == 1 ? g_g1t : a == 2 ? g_g2t : g_Wo1t)[r] = v;
    }
}

// ---------------- CSR build ---------------------------------------------------
__global__ void k_init_cnt() {
    int i = blockIdx.x * blockDim.x + threadIdx.x;
    if (i < NN) g_cnt[i] = 1;
}
__global__ void k_count(const int* __restrict__ ei) {
    int i = blockIdx.x * blockDim.x + threadIdx.x;
    if (i < EE) atomicAdd(&g_cnt[ei[EE + i]], 1);
}
__global__ void __launch_bounds__(1024, 1) k_scan() {
    __shared__ int ssum[1024];
    const int t = threadIdx.x;
    const int C = (NN + 1023) / 1024;
    const int beg = t * C;
    const int end = (beg + C < NN) ? beg + C : NN;
    int s = 0;
    for (int i = beg; i < end; i++) s += g_cnt[i];
    ssum[t] = s;
    __syncthreads();
    for (int o = 1; o < 1024; o <<= 1) {
        int v = (t >= o) ? ssum[t - o] : 0;
        __syncthreads();
        ssum[t] += v;
        __syncthreads();
    }
    int pre = (t == 0) ? 0 : ssum[t - 1];
    for (int i = beg; i < end; i++) {
        g_rs[i] = pre; g_cur[i] = pre; pre += g_cnt[i];
    }
    if (t == 0) g_rs[NN] = ET;
}
__global__ void k_fill(const int* __restrict__ ei) {
    int i = blockIdx.x * blockDim.x + threadIdx.x;
    if (i >= ET) return;
    int src, dst;
    if (i < EE) { src = ei[i]; dst = ei[EE + i]; }
    else        { src = dst = i - EE; }
    g_csrc[atomicAdd(&g_cur[dst], 1)] = src;
}

// ---------------- features -> x -> Wi -> g1 projection + attn logits ---------
__global__ void __launch_bounds__(128) k_features(
    const float* __restrict__ des, const float* __restrict__ twt,
    const float* __restrict__ npr, const float* __restrict__ cpr,
    const float* __restrict__ bd,  const float* __restrict__ bt,
    const float* __restrict__ Wn,  const float* __restrict__ bn,
    const float* __restrict__ Wc,  const float* __restrict__ bc,
    const float* __restrict__ bi,
    const float* __restrict__ g1as, const float* __restrict__ g1ad)
{
    __shared__ __align__(16) float x_t [128 * TS];   // x transposed [feat][node]
    __shared__ __align__(16) float x2_t[128 * TS];
    __shared__ __align__(16) float a_d [32 * TS];    // des chunk [k][node]
    __shared__ __align__(16) float a_t2[32 * TS];    // twt chunk

    const int tid = threadIdx.x;
    const int n0  = blockIdx.x * NT;
    const int cg  = tid >> 2;          // 0..31
    const int ng8 = (tid & 3) * 8;     // node offset
    const int cg4 = cg * 4;

    // ---- stage 1: 64 cols (d|t), 2 cols x 8 nodes per thread, 24 k-chunks ----
    unsigned long long acc2[2][4];
#pragma unroll
    for (int c = 0; c < 2; c++)
#pragma unroll
        for (int p = 0; p < 4; p++) acc2[c][p] = 0ull;

    for (int ch = 0; ch < 24; ch++) {
        const int kb = ch * 32;
#pragma unroll
        for (int it = 0; it < 2; it++) {
            const int idx = tid + it * 128;      // 256 float4 per array
            const int c4 = idx & 7, r = idx >> 3;
            const float4 dv = *(const float4*)(des + (size_t)(n0 + r) * 768 + kb + 4 * c4);
            const float4 tv = *(const float4*)(twt + (size_t)(n0 + r) * 768 + kb + 4 * c4);
            float* p0 = a_d + (4 * c4) * TS + r;
            p0[0] = dv.x; p0[TS] = dv.y; p0[2 * TS] = dv.z; p0[3 * TS] = dv.w;
            float* p1 = a_t2 + (4 * c4) * TS + r;
            p1[0] = tv.x; p1[TS] = tv.y; p1[2 * TS] = tv.z; p1[3 * TS] = tv.w;
        }
        __syncthreads();
        const float* at = (cg < 16) ? a_d : a_t2;
        const float* wt = g_W1t + (size_t)kb * 64 + 2 * cg;
#pragma unroll 4
        for (int k = 0; k < 32; k++) {
            const float2 wv = *(const float2*)(wt + k * 64);
            const unsigned long long w0 = pack2(wv.x, wv.x), w1 = pack2(wv.y, wv.y);
            const ulonglong2 a01 = *(const ulonglong2*)(at + k * TS + ng8);
            const ulonglong2 a23 = *(const ulonglong2*)(at + k * TS + ng8 + 4);
            ffma2(acc2[0][0], a01.x, w0); ffma2(acc2[0][1], a01.y, w0);
            ffma2(acc2[0][2], a23.x, w0); ffma2(acc2[0][3], a23.y, w0);
            ffma2(acc2[1][0], a01.x, w1); ffma2(acc2[1][1], a01.y, w1);
            ffma2(acc2[1][2], a23.x, w1); ffma2(acc2[1][3], a23.y, w1);
        }
        __syncthreads();
    }

    // ---- stage 1 epilogue ----------------------------------------------------
#pragma unroll
    for (int c = 0; c < 2; c++) {
        const int col = 2 * cg + c;
        const float b = (col < 32) ? bd[col] : bt[col - 32];
#pragma unroll
        for (int p = 0; p < 4; p++) {
            const float2 v = unpack2(acc2[c][p]);
            x_t[col * TS + ng8 + 2 * p]     = lrelu01(v.x + b);
            x_t[col * TS + ng8 + 2 * p + 1] = lrelu01(v.y + b);
        }
    }
    {   // num/cat: 64 cols x 2 node-halves over 128 threads
        const int col = tid >> 1, mh = (tid & 1) * 16;
        if (col < 32) {
            const float w0 = Wn[col * 5], w1 = Wn[col * 5 + 1], w2 = Wn[col * 5 + 2],
                        w3 = Wn[col * 5 + 3], w4 = Wn[col * 5 + 4];
            const float b = bn[col];
            for (int m = 0; m < 16; m++) {
                const float* r = npr + (size_t)(n0 + mh + m) * 5;
                x_t[(64 + col) * TS + mh + m] =
                    lrelu01(r[0]*w0 + r[1]*w1 + r[2]*w2 + r[3]*w3 + r[4]*w4 + b);
            }
        } else {
            const int jj = col - 32;
            const float w0 = Wc[jj * 3], w1 = Wc[jj * 3 + 1], w2 = Wc[jj * 3 + 2];
            const float b = bc[jj];
            for (int m = 0; m < 16; m++) {
                const float* r = cpr + (size_t)(n0 + mh + m) * 3;
                x_t[(96 + jj) * TS + mh + m] = lrelu01(r[0]*w0 + r[1]*w1 + r[2]*w2 + b);
            }
        }
    }
    __syncthreads();

    // ---- stage 2: x2 = lrelu(x @ Wi^T + bi) ---------------------------------
    {
        unsigned long long acc[4][4];
#pragma unroll
        for (int c = 0; c < 4; c++)
#pragma unroll
            for (int p = 0; p < 4; p++) acc[c][p] = 0ull;
        gemm_tile128(g_Wit, x_t, cg4, ng8, acc);
#pragma unroll
        for (int c = 0; c < 4; c++) {
            const int col = cg4 + c;
            const float b = bi[col];
#pragma unroll
            for (int p = 0; p < 4; p++) {
                const float2 v = unpack2(acc[c][p]);
                x2_t[col * TS + ng8 + 2 * p]     = lrelu01(v.x + b);
                x2_t[col * TS + ng8 + 2 * p + 1] = lrelu01(v.y + b);
            }
        }
    }
    __syncthreads();

    // ---- stage 3: xw1 = x2 @ g1_W^T + logits --------------------------------
    {
        unsigned long long acc[4][4];
#pragma unroll
        for (int c = 0; c < 4; c++)
#pragma unroll
            for (int p = 0; p < 4; p++) acc[c][p] = 0ull;
        gemm_tile128(g_g1t, x2_t, cg4, ng8, acc);

        float vals[4][8];
#pragma unroll
        for (int c = 0; c < 4; c++)
#pragma unroll
            for (int p = 0; p < 4; p++) {
                const float2 v = unpack2(acc[c][p]);
                vals[c][2 * p] = v.x; vals[c][2 * p + 1] = v.y;
            }
#pragma unroll
        for (int m = 0; m < 8; m++) {
            float4 o = {vals[0][m], vals[1][m], vals[2][m], vals[3][m]};
            *(float4*)(g_xw1 + (size_t)(n0 + ng8 + m) * HID + cg4) = o;
        }
        const float a0 = g1as[cg4], a1 = g1as[cg4 + 1], a2 = g1as[cg4 + 2], a3 = g1as[cg4 + 3];
        const float d0 = g1ad[cg4], d1 = g1ad[cg4 + 1], d2 = g1ad[cg4 + 2], d3 = g1ad[cg4 + 3];
        const int w = tid >> 5, lane = tid & 31;
#pragma unroll
        for (int m = 0; m < 8; m++) {
            float ps = vals[0][m]*a0 + vals[1][m]*a1 + vals[2][m]*a2 + vals[3][m]*a3;
            float pd = vals[0][m]*d0 + vals[1][m]*d1 + vals[2][m]*d2 + vals[3][m]*d3;
#pragma unroll
            for (int o = 4; o < 32; o <<= 1) {
                ps += __shfl_xor_sync(0xffffffffu, ps, o);
                pd += __shfl_xor_sync(0xffffffffu, pd, o);
            }
            if (lane < 4) {
                g_es1[(n0 + ng8 + m) * 4 + w] = ps;
                g_ed1[(n0 + ng8 + m) * 4 + w] = pd;
            }
        }
    }
}

// ---------------- GAT1 aggregation: warp-per-dst gather, fused exp ------------
__global__ void __launch_bounds__(256) k_agg1(const float* __restrict__ g1b) {
    const int d = (blockIdx.x * blockDim.x + threadIdx.x) >> 5;
    const int lane = threadIdx.x & 31;
    if (d >= NN) return;
    const int beg = g_rs[d], end = g_rs[d + 1];
    const int h = lane >> 3;
    const float edv = g_ed1[d * 4 + h];
    float4 acc = {0.f, 0.f, 0.f, 0.f};
    float den = 0.f;
#pragma unroll 2
    for (int s = beg; s < end; s++) {
        const int src = __ldg(&g_csrc[s]);
        const float es = __ldg(&g_es1[src * 4 + h]);
        const float ev = __expf(lrelu2(es + edv));
        const float4 xs = *(const float4*)(g_xw1 + (size_t)src * HID + lane * 4);
        acc.x += xs.x * ev; acc.y += xs.y * ev;
        acc.z += xs.z * ev; acc.w += xs.w * ev;
        den += ev;
    }
    const float inv = 1.f / den;
    const float4 b = ((const float4*)g1b)[lane];
    float4 o;
    o.x = acc.x * inv + b.x; o.y = acc.y * inv + b.y;
    o.z = acc.z * inv + b.z; o.w = acc.w * inv + b.w;
    *(float4*)(g_out1 + (size_t)d * HID + lane * 4) = o;
}

// ---------------- GAT2 projection + attn logits -------------------------------
__global__ void __launch_bounds__(128) k_gat2_prep(
    const float* __restrict__ g2as, const float* __restrict__ g2ad)
{
    __shared__ __align__(16) float x_t[128 * TS];
    __shared__ float sp[2][4][NT];
    const int tid = threadIdx.x, n0 = blockIdx.x * NT;
    const int cg = tid >> 2, ng8 = (tid & 3) * 8, cg4 = cg * 4;

    for (int idx = tid; idx < NT * HID; idx += 128) {
        const int node = idx >> 7, c = idx & 127;
        x_t[c * TS + node] = g_out1[(size_t)(n0 + node) * HID + c];
    }
    __syncthreads();

    unsigned long long acc[4][4];
#pragma unroll
    for (int c = 0; c < 4; c++)
#pragma unroll
        for (int p = 0; p < 4; p++) acc[c][p] = 0ull;
    gemm_tile128(g_g2t, x_t, cg4, ng8, acc);

    float vals[4][8];
#pragma unroll
    for (int c = 0; c < 4; c++)
#pragma unroll
        for (int p = 0; p < 4; p++) {
            const float2 v = unpack2(acc[c][p]);
            vals[c][2 * p] = v.x; vals[c][2 * p + 1] = v.y;
        }
#pragma unroll
    for (int m = 0; m < 8; m++) {
        float4 o = {vals[0][m], vals[1][m], vals[2][m], vals[3][m]};
        *(float4*)(g_xw2 + (size_t)(n0 + ng8 + m) * HID + cg4) = o;
    }
    const float a0 = g2as[cg4], a1 = g2as[cg4 + 1], a2 = g2as[cg4 + 2], a3 = g2as[cg4 + 3];
    const float d0 = g2ad[cg4], d1 = g2ad[cg4 + 1], d2 = g2ad[cg4 + 2], d3 = g2ad[cg4 + 3];
    const int w = tid >> 5, lane = tid & 31;
#pragma unroll
    for (int m = 0; m < 8; m++) {
        float ps = vals[0][m]*a0 + vals[1][m]*a1 + vals[2][m]*a2 + vals[3][m]*a3;
        float pd = vals[0][m]*d0 + vals[1][m]*d1 + vals[2][m]*d2 + vals[3][m]*d3;
#pragma unroll
        for (int o = 4; o < 32; o <<= 1) {
            ps += __shfl_xor_sync(0xffffffffu, ps, o);
            pd += __shfl_xor_sync(0xffffffffu, pd, o);
        }
        if (lane < 4) { sp[0][w][ng8 + m] = ps; sp[1][w][ng8 + m] = pd; }
    }
    __syncthreads();
    if (tid < 32) {
        g_es2[n0 + tid] = sp[0][0][tid] + sp[0][1][tid] + sp[0][2][tid] + sp[0][3][tid];
    } else if (tid < 64) {
        const int m = tid - 32;
        g_ed2[n0 + m] = sp[1][0][m] + sp[1][1][m] + sp[1][2][m] + sp[1][3][m];
    }
}

// ---------------- GAT2 aggregation --------------------------------------------
__global__ void __launch_bounds__(256) k_agg2(const float* __restrict__ g2b) {
    const int d = (blockIdx.x * blockDim.x + threadIdx.x) >> 5;
    const int lane = threadIdx.x & 31;
    if (d >= NN) return;
    const int beg = g_rs[d], end = g_rs[d + 1];
    const float edv = g_ed2[d];
    float4 acc = {0.f, 0.f, 0.f, 0.f};
    float den = 0.f;
#pragma unroll 2
    for (int s = beg; s < end; s++) {
        const int src = __ldg(&g_csrc[s]);
        const float es = __ldg(&g_es2[src]);
        const float ev = __expf(lrelu2(es + edv));
        const float4 xs = *(const float4*)(g_xw2 + (size_t)src * HID + lane * 4);
        acc.x += xs.x * ev; acc.y += xs.y * ev;
        acc.z += xs.z * ev; acc.w += xs.w * ev;
        den += ev;
    }
    const float inv = 1.f / den;
    const float4 b = ((const float4*)g2b)[lane];
    float4 o;
    o.x = acc.x * inv + b.x; o.y = acc.y * inv + b.y;
    o.z = acc.z * inv + b.z; o.w = acc.w * inv + b.w;
    *(float4*)(g_out2 + (size_t)d * HID + lane * 4) = o;
}

// ---------------- output head ------------------------------------------------
__global__ void __launch_bounds__(128) k_final(
    const float* __restrict__ bo1, const float* __restrict__ Wo2,
    const float* __restrict__ bo2, float* __restrict__ out)
{
    __shared__ __align__(16) float x_t[128 * TS];
    __shared__ float sp[2][4][NT];
    const int tid = threadIdx.x, n0 = blockIdx.x * NT;
    const int cg = tid >> 2, ng8 = (tid & 3) * 8, cg4 = cg * 4;

    for (int idx = tid; idx < NT * HID; idx += 128) {
        const int node = idx >> 7, c = idx & 127;
        x_t[c * TS + node] = g_out2[(size_t)(n0 + node) * HID + c];
    }
    __syncthreads();

    unsigned long long acc[4][4];
#pragma unroll
    for (int c = 0; c < 4; c++)
#pragma unroll
        for (int p = 0; p < 4; p++) acc[c][p] = 0ull;
    gemm_tile128(g_Wo1t, x_t, cg4, ng8, acc);

    float vals[4][8];
#pragma unroll
    for (int c = 0; c < 4; c++) {
        const float b = bo1[cg4 + c];
#pragma unroll
        for (int p = 0; p < 4; p++) {
            const float2 v = unpack2(acc[c][p]);
            vals[c][2 * p]     = lrelu01(v.x + b);
            vals[c][2 * p + 1] = lrelu01(v.y + b);
        }
    }
    const float a0 = Wo2[cg4],       a1 = Wo2[cg4 + 1],       a2 = Wo2[cg4 + 2],       a3 = Wo2[cg4 + 3];
    const float d0 = Wo2[128 + cg4], d1 = Wo2[128 + cg4 + 1], d2 = Wo2[128 + cg4 + 2], d3 = Wo2[128 + cg4 + 3];
    const int w = tid >> 5, lane = tid & 31;
#pragma unroll
    for (int m = 0; m < 8; m++) {
        float v0 = vals[0][m]*a0 + vals[1][m]*a1 + vals[2][m]*a2 + vals[3][m]*a3;
        float v1 = vals[0][m]*d0 + vals[1][m]*d1 + vals[2][m]*d2 + vals[3][m]*d3;
#pragma unroll
        for (int o = 4; o < 32; o <<= 1) {
            v0 += __shfl_xor_sync(0xffffffffu, v0, o);
            v1 += __shfl_xor_sync(0xffffffffu, v1, o);
        }
        if (lane < 4) { sp[0][w][ng8 + m] = v0; sp[1][w][ng8 + m] = v1; }
    }
    __syncthreads();
    if (tid < 32) {
        out[(size_t)(n0 + tid) * 2] =
            sp[0][0][tid] + sp[0][1][tid] + sp[0][2][tid] + sp[0][3][tid] + bo2[0];
    } else if (tid < 64) {
        const int m = tid - 32;
        out[(size_t)(n0 + m) * 2 + 1] =
            sp[1][0][m] + sp[1][1][m] + sp[1][2][m] + sp[1][3][m] + bo2[1];
    }
}

// ---------------- launch ------------------------------------------------------
extern "C" void kernel_launch(void* const* d_in, const int* in_sizes, int n_in,
                              void* d_out, int out_size) {
    const float* des  = (const float*)d_in[0];
    const float* twt  = (const float*)d_in[1];
    const float* npr  = (const float*)d_in[2];
    const float* cpr  = (const float*)d_in[3];
    const int*   ei   = (const int*)d_in[4];   // JAX x64 disabled -> int32
    const float* Wd = (const float*)d_in[5];   const float* bd = (const float*)d_in[6];
    const float* Wt = (const float*)d_in[7];   const float* bt = (const float*)d_in[8];
    const float* Wn = (const float*)d_in[9];   const float* bn = (const float*)d_in[10];
    const float* Wc = (const float*)d_in[11];  const float* bc = (const float*)d_in[12];
    const float* Wi = (const float*)d_in[13];  const float* bi = (const float*)d_in[14];
    const float* g1W  = (const float*)d_in[15];
    const float* g1as = (const float*)d_in[16];
    const float* g1ad = (const float*)d_in[17];
    const float* g1b  = (const float*)d_in[18];
    const float* g2W  = (const float*)d_in[19];
    const float* g2as = (const float*)d_in[20];
    const float* g2ad = (const float*)d_in[21];
    const float* g2b  = (const float*)d_in[22];
    const float* Wo1  = (const float*)d_in[23]; const float* bo1 = (const float*)d_in[24];
    const float* Wo2  = (const float*)d_in[25]; const float* bo2 = (const float*)d_in[26];
    float* out = (float*)d_out;

    const int WPN = 768 * 64 + 4 * 128 * 128;
    k_wprep<<<(WPN + 255) / 256, 256>>>(Wd, Wt, Wi, g1W, g2W, Wo1);
    k_init_cnt<<<(NN + 255) / 256, 256>>>();
    k_count<<<(EE + 255) / 256, 256>>>(ei);
    k_features<<<NN / NT, 128>>>(des, twt, npr, cpr, bd, bt, Wn, bn, Wc, bc,
                                 bi, g1as, g1ad);          // ncu-captured slot
    k_scan<<<1, 1024>>>();
    k_fill<<<(ET + 255) / 256, 256>>>(ei);
    k_agg1<<<(NN * 32 + 255) / 256, 256>>>(g1b);
    k_gat2_prep<<<NN / NT, 128>>>(g2as, g2ad);
    k_agg2<<<(NN * 32 + 255) / 256, 256>>>(g2b);
    k_final<<<NN / NT, 128>>>(bo1, Wo2, bo2, out);
}

// round 7
// speedup vs baseline: 1.3062x; 1.1044x over previous
#include <cuda_runtime.h>

#define NN   100000
#define EE   1600000
#define ET   (EE + NN)
#define HID  128
#define NT   32                 // nodes per block
#define TS   36                 // transposed activation stride (floats)

// ---------------- scratch globals --------------------------------------------
__device__ __align__(16) float g_xw1 [(size_t)NN * HID];
__device__ __align__(16) float g_es1 [NN * 4];
__device__ __align__(16) float g_ed1 [NN * 4];
__device__ __align__(16) float g_out1[(size_t)NN * HID];
__device__ __align__(16) float g_xw2 [(size_t)NN * HID];
__device__ __align__(16) float g_es2 [NN];
__device__ __align__(16) float g_ed2 [NN];
__device__ __align__(16) float g_out2[(size_t)NN * HID];

// pre-transposed weights: w_t[k][col]
__device__ __align__(16) float g_W1t [768 * 64];    // [k][col] col<32:Wd col>=32:Wt
__device__ __align__(16) float g_Wit [128 * 128];
__device__ __align__(16) float g_g1t [128 * 128];
__device__ __align__(16) float g_g2t [128 * 128];
__device__ __align__(16) float g_Wo1t[128 * 128];

// CSR (dst-grouped)
__device__ int g_cnt[NN];
__device__ int g_rs [NN + 1];
__device__ int g_cur[NN];
__device__ int g_csrc[ET];

__device__ __forceinline__ float lrelu01(float v) { return v > 0.f ? v : 0.01f * v; }
__device__ __forceinline__ float lrelu2 (float v) { return v > 0.f ? v : 0.2f  * v; }

// ---- packed fp32x2 helpers ---------------------------------------------------
__device__ __forceinline__ unsigned long long pack2(float x, float y) {
    unsigned long long r;
    asm("mov.b64 %0,{%1,%2};" : "=l"(r) : "f"(x), "f"(y));
    return r;
}
__device__ __forceinline__ float2 unpack2(unsigned long long v) {
    float2 r;
    asm("mov.b64 {%0,%1},%2;" : "=f"(r.x), "=f"(r.y) : "l"(v));
    return r;
}
__device__ __forceinline__ void ffma2(unsigned long long& d,
                                      unsigned long long a, unsigned long long b) {
    asm("fma.rn.f32x2 %0,%1,%2,%0;" : "+l"(d) : "l"(a), "l"(b));
}

// 4 cols x 8 nodes tile GEMM over K=128; wt global [k][128], a_t smem stride TS
__device__ __forceinline__ void gemm_tile128(const float* __restrict__ wt,
                                             const float* __restrict__ a_t,
                                             int cg4, int ng8,
                                             unsigned long long acc[4][4]) {
#pragma unroll 4
    for (int k = 0; k < 128; k++) {
        const float4 wv = *(const float4*)(wt + k * 128 + cg4);
        const ulonglong2 a01 = *(const ulonglong2*)(a_t + k * TS + ng8);
        const ulonglong2 a23 = *(const ulonglong2*)(a_t + k * TS + ng8 + 4);
        const unsigned long long w0 = pack2(wv.x, wv.x), w1 = pack2(wv.y, wv.y);
        const unsigned long long w2 = pack2(wv.z, wv.z), w3 = pack2(wv.w, wv.w);
        ffma2(acc[0][0], a01.x, w0); ffma2(acc[0][1], a01.y, w0);
        ffma2(acc[0][2], a23.x, w0); ffma2(acc[0][3], a23.y, w0);
        ffma2(acc[1][0], a01.x, w1); ffma2(acc[1][1], a01.y, w1);
        ffma2(acc[1][2], a23.x, w1); ffma2(acc[1][3], a23.y, w1);
        ffma2(acc[2][0], a01.x, w2); ffma2(acc[2][1], a01.y, w2);
        ffma2(acc[2][2], a23.x, w2); ffma2(acc[2][3], a23.y, w2);
        ffma2(acc[3][0], a01.x, w3); ffma2(acc[3][1], a01.y, w3);
        ffma2(acc[3][2], a23.x, w3); ffma2(acc[3][3], a23.y, w3);
    }
}

// ---------------- weight transpose (once per launch) --------------------------
__global__ void k_wprep(const float* __restrict__ Wd, const float* __restrict__ Wt,
                        const float* __restrict__ Wi, const float* __restrict__ g1W,
                        const float* __restrict__ g2W, const float* __restrict__ Wo1) {
    const int i = blockIdx.x * blockDim.x + threadIdx.x;
    if (i < 768 * 64) {
        const int col = i & 63, k = i >> 6;
        g_W1t[i] = (col < 32) ? Wd[col * 768 + k] : Wt[(col - 32) * 768 + k];
    } else if (i < 768 * 64 + 4 * 128 * 128) {
        const int j = i - 768 * 64;
        const int a = j >> 14, r = j & 16383;
        const int col = r & 127, k = r >> 7;
        const float v = (a == 0 ? Wi : a == 1 ? g1W : a == 2 ? g2W : Wo1)[col * 128 + k];
        (a == 0 ? g_Wit : a == 1 ? g_g1t : a == 2 ? g_g2t : g_Wo1t)[r] = v;
    }
}

// ---------------- CSR build ---------------------------------------------------
__global__ void k_init_cnt() {
    int i = blockIdx.x * blockDim.x + threadIdx.x;
    if (i < NN) g_cnt[i] = 1;
}
__global__ void k_count(const int* __restrict__ ei) {
    int i = blockIdx.x * blockDim.x + threadIdx.x;
    if (i < EE) atomicAdd(&g_cnt[ei[EE + i]], 1);
}
__global__ void __launch_bounds__(1024, 1) k_scan() {
    __shared__ int ssum[1024];
    const int t = threadIdx.x;
    const int C = (NN + 1023) / 1024;
    const int beg = t * C;
    const int end = (beg + C < NN) ? beg + C : NN;
    int s = 0;
    for (int i = beg; i < end; i++) s += g_cnt[i];
    ssum[t] = s;
    __syncthreads();
    for (int o = 1; o < 1024; o <<= 1) {
        int v = (t >= o) ? ssum[t - o] : 0;
        __syncthreads();
        ssum[t] += v;
        __syncthreads();
    }
    int pre = (t == 0) ? 0 : ssum[t - 1];
    for (int i = beg; i < end; i++) {
        g_rs[i] = pre; g_cur[i] = pre; pre += g_cnt[i];
    }
    if (t == 0) g_rs[NN] = ET;
}
__global__ void k_fill(const int* __restrict__ ei) {
    int i = blockIdx.x * blockDim.x + threadIdx.x;
    if (i >= ET) return;
    int src, dst;
    if (i < EE) { src = ei[i]; dst = ei[EE + i]; }
    else        { src = dst = i - EE; }
    g_csrc[atomicAdd(&g_cur[dst], 1)] = src;
}

// ---------------- features -> x -> Wi -> g1 projection + attn logits ---------
__global__ void __launch_bounds__(128) k_features(
    const float* __restrict__ des, const float* __restrict__ twt,
    const float* __restrict__ npr, const float* __restrict__ cpr,
    const float* __restrict__ bd,  const float* __restrict__ bt,
    const float* __restrict__ Wn,  const float* __restrict__ bn,
    const float* __restrict__ Wc,  const float* __restrict__ bc,
    const float* __restrict__ bi,
    const float* __restrict__ g1as, const float* __restrict__ g1ad)
{
    __shared__ __align__(16) float x_t [128 * TS];   // x transposed [feat][node]
    __shared__ __align__(16) float x2_t[128 * TS];   // stage-2 out; stage-1 staging

    const int tid = threadIdx.x;
    const int n0  = blockIdx.x * NT;

    // stage-1 thread roles: kh (K-half) | arr (des/twt) | cg (col grp) | ng
    const int s1_ng8 = (tid & 3) * 8;
    const int s1_cg4 = ((tid >> 2) & 7) * 4;
    const int s1_arr = (tid >> 5) & 1;
    const int s1_kh  = tid >> 6;

    // staging buffers (double): set s at x2_t + s*2304; [arr] at +1152
    float* bufs = x2_t;
    const int ld_c4 = tid & 7, ld_r0 = tid >> 3;        // it=0: node ld_r0
    // it=1: idx=tid+128 -> c4 same, node ld_r0+16

    float4 pd0, pt0, pd1, pt1;
    {   // prefetch chunk 0
        const float* dp = des + (size_t)(n0 + ld_r0) * 768 + 4 * ld_c4;
        const float* tp = twt + (size_t)(n0 + ld_r0) * 768 + 4 * ld_c4;
        pd0 = *(const float4*)(dp);
        pt0 = *(const float4*)(tp);
        pd1 = *(const float4*)(dp + 16 * 768);
        pt1 = *(const float4*)(tp + 16 * 768);
    }
    {   // store chunk 0 into set 0
        float* b0 = bufs + (4 * ld_c4) * TS;
        float* p = b0 + ld_r0;
        p[0] = pd0.x; p[TS] = pd0.y; p[2 * TS] = pd0.z; p[3 * TS] = pd0.w;
        p += 16;
        p[0] = pd1.x; p[TS] = pd1.y; p[2 * TS] = pd1.z; p[3 * TS] = pd1.w;
        p = b0 + 1152 + ld_r0;
        p[0] = pt0.x; p[TS] = pt0.y; p[2 * TS] = pt0.z; p[3 * TS] = pt0.w;
        p += 16;
        p[0] = pt1.x; p[TS] = pt1.y; p[2 * TS] = pt1.z; p[3 * TS] = pt1.w;
    }
    __syncthreads();

    unsigned long long acc2[4][4];
#pragma unroll
    for (int c = 0; c < 4; c++)
#pragma unroll
        for (int p = 0; p < 4; p++) acc2[c][p] = 0ull;

    for (int ch = 0; ch < 24; ch++) {
        if (ch < 23) {   // prefetch chunk ch+1
            const int kb2 = (ch + 1) * 32;
            const float* dp = des + (size_t)(n0 + ld_r0) * 768 + kb2 + 4 * ld_c4;
            const float* tp = twt + (size_t)(n0 + ld_r0) * 768 + kb2 + 4 * ld_c4;
            pd0 = *(const float4*)(dp);
            pt0 = *(const float4*)(tp);
            pd1 = *(const float4*)(dp + 16 * 768);
            pt1 = *(const float4*)(tp + 16 * 768);
        }
        // compute: 16 k of this chunk's K-half
        {
            const float* abase = bufs + (ch & 1) * 2304 + s1_arr * 1152
                               + (s1_kh * 16) * TS + s1_ng8;
            const float* wbase = g_W1t + (size_t)(ch * 32 + s1_kh * 16) * 64
                               + s1_arr * 32 + s1_cg4;
#pragma unroll 4
            for (int k = 0; k < 16; k++) {
                const float4 wv = *(const float4*)(wbase + k * 64);
                const ulonglong2 a01 = *(const ulonglong2*)(abase + k * TS);
                const ulonglong2 a23 = *(const ulonglong2*)(abase + k * TS + 4);
                const unsigned long long w0 = pack2(wv.x, wv.x), w1 = pack2(wv.y, wv.y);
                const unsigned long long w2 = pack2(wv.z, wv.z), w3 = pack2(wv.w, wv.w);
                ffma2(acc2[0][0], a01.x, w0); ffma2(acc2[0][1], a01.y, w0);
                ffma2(acc2[0][2], a23.x, w0); ffma2(acc2[0][3], a23.y, w0);
                ffma2(acc2[1][0], a01.x, w1); ffma2(acc2[1][1], a01.y, w1);
                ffma2(acc2[1][2], a23.x, w1); ffma2(acc2[1][3], a23.y, w1);
                ffma2(acc2[2][0], a01.x, w2); ffma2(acc2[2][1], a01.y, w2);
                ffma2(acc2[2][2], a23.x, w2); ffma2(acc2[2][3], a23.y, w2);
                ffma2(acc2[3][0], a01.x, w3); ffma2(acc2[3][1], a01.y, w3);
                ffma2(acc2[3][2], a23.x, w3); ffma2(acc2[3][3], a23.y, w3);
            }
        }
        if (ch < 23) {   // stage chunk ch+1 into the other set
            float* b0 = bufs + ((ch + 1) & 1) * 2304 + (4 * ld_c4) * TS;
            float* p = b0 + ld_r0;
            p[0] = pd0.x; p[TS] = pd0.y; p[2 * TS] = pd0.z; p[3 * TS] = pd0.w;
            p += 16;
            p[0] = pd1.x; p[TS] = pd1.y; p[2 * TS] = pd1.z; p[3 * TS] = pd1.w;
            p = b0 + 1152 + ld_r0;
            p[0] = pt0.x; p[TS] = pt0.y; p[2 * TS] = pt0.z; p[3 * TS] = pt0.w;
            p += 16;
            p[0] = pt1.x; p[TS] = pt1.y; p[2 * TS] = pt1.z; p[3 * TS] = pt1.w;
        }
        __syncthreads();
    }

    // ---- stage-1 epilogue: cross-K-half reduction + bias + num/cat ----------
    {
        unsigned long long* red = (unsigned long long*)x2_t;  // 64 thr x 16 ull = 8KB
        if (s1_kh == 1) {
#pragma unroll
            for (int c = 0; c < 4; c++)
#pragma unroll
                for (int p = 0; p < 4; p++)
                    red[(tid & 63) * 16 + c * 4 + p] = acc2[c][p];
        }
        __syncthreads();
        if (s1_kh == 0) {
#pragma unroll
            for (int c = 0; c < 4; c++) {
                const int col = s1_arr * 32 + s1_cg4 + c;
                const float b = (col < 32) ? bd[col] : bt[col - 32];
#pragma unroll
                for (int p = 0; p < 4; p++) {
                    const float2 v = unpack2(acc2[c][p]);
                    const float2 o = unpack2(red[tid * 16 + c * 4 + p]);
                    x_t[col * TS + s1_ng8 + 2 * p]     = lrelu01(v.x + o.x + b);
                    x_t[col * TS + s1_ng8 + 2 * p + 1] = lrelu01(v.y + o.y + b);
                }
            }
        }
        // num/cat columns (all threads; kh=1 half does it while kh=0 reduces)
        const int col = tid >> 1, mh = (tid & 1) * 16;
        if (col < 32) {
            const float w0 = Wn[col * 5], w1 = Wn[col * 5 + 1], w2 = Wn[col * 5 + 2],
                        w3 = Wn[col * 5 + 3], w4 = Wn[col * 5 + 4];
            const float b = bn[col];
            for (int m = 0; m < 16; m++) {
                const float* r = npr + (size_t)(n0 + mh + m) * 5;
                x_t[(64 + col) * TS + mh + m] =
                    lrelu01(r[0]*w0 + r[1]*w1 + r[2]*w2 + r[3]*w3 + r[4]*w4 + b);
            }
        } else {
            const int jj = col - 32;
            const float w0 = Wc[jj * 3], w1 = Wc[jj * 3 + 1], w2 = Wc[jj * 3 + 2];
            const float b = bc[jj];
            for (int m = 0; m < 16; m++) {
                const float* r = cpr + (size_t)(n0 + mh + m) * 3;
                x_t[(96 + jj) * TS + mh + m] = lrelu01(r[0]*w0 + r[1]*w1 + r[2]*w2 + b);
            }
        }
    }
    __syncthreads();

    const int cg4 = (tid >> 2) * 4, ng8 = (tid & 3) * 8;

    // ---- stage 2: x2 = lrelu(x @ Wi^T + bi) ---------------------------------
    {
        unsigned long long acc[4][4];
#pragma unroll
        for (int c = 0; c < 4; c++)
#pragma unroll
            for (int p = 0; p < 4; p++) acc[c][p] = 0ull;
        gemm_tile128(g_Wit, x_t, cg4, ng8, acc);
        __syncthreads();       // red/staging readers done before overwrite
#pragma unroll
        for (int c = 0; c < 4; c++) {
            const int col = cg4 + c;
            const float b = bi[col];
#pragma unroll
            for (int p = 0; p < 4; p++) {
                const float2 v = unpack2(acc[c][p]);
                x2_t[col * TS + ng8 + 2 * p]     = lrelu01(v.x + b);
                x2_t[col * TS + ng8 + 2 * p + 1] = lrelu01(v.y + b);
            }
        }
    }
    __syncthreads();

    // ---- stage 3: xw1 = x2 @ g1_W^T + logits --------------------------------
    {
        unsigned long long acc[4][4];
#pragma unroll
        for (int c = 0; c < 4; c++)
#pragma unroll
            for (int p = 0; p < 4; p++) acc[c][p] = 0ull;
        gemm_tile128(g_g1t, x2_t, cg4, ng8, acc);

        float vals[4][8];
#pragma unroll
        for (int c = 0; c < 4; c++)
#pragma unroll
            for (int p = 0; p < 4; p++) {
                const float2 v = unpack2(acc[c][p]);
                vals[c][2 * p] = v.x; vals[c][2 * p + 1] = v.y;
            }
#pragma unroll
        for (int m = 0; m < 8; m++) {
            float4 o = {vals[0][m], vals[1][m], vals[2][m], vals[3][m]};
            *(float4*)(g_xw1 + (size_t)(n0 + ng8 + m) * HID + cg4) = o;
        }
        const float a0 = g1as[cg4], a1 = g1as[cg4 + 1], a2 = g1as[cg4 + 2], a3 = g1as[cg4 + 3];
        const float d0 = g1ad[cg4], d1 = g1ad[cg4 + 1], d2 = g1ad[cg4 + 2], d3 = g1ad[cg4 + 3];
        const int w = tid >> 5, lane = tid & 31;
#pragma unroll
        for (int m = 0; m < 8; m++) {
            float ps = vals[0][m]*a0 + vals[1][m]*a1 + vals[2][m]*a2 + vals[3][m]*a3;
            float pd = vals[0][m]*d0 + vals[1][m]*d1 + vals[2][m]*d2 + vals[3][m]*d3;
#pragma unroll
            for (int o = 4; o < 32; o <<= 1) {
                ps += __shfl_xor_sync(0xffffffffu, ps, o);
                pd += __shfl_xor_sync(0xffffffffu, pd, o);
            }
            if (lane < 4) {
                g_es1[(n0 + ng8 + m) * 4 + w] = ps;
                g_ed1[(n0 + ng8 + m) * 4 + w] = pd;
            }
        }
    }
}

// ---------------- GAT1 aggregation: warp-per-dst gather, fused exp ------------
__global__ void __launch_bounds__(256) k_agg1(const float* __restrict__ g1b) {
    const int d = (blockIdx.x * blockDim.x + threadIdx.x) >> 5;
    const int lane = threadIdx.x & 31;
    if (d >= NN) return;
    const int beg = g_rs[d], end = g_rs[d + 1];
    const int h = lane >> 3;
    const float edv = g_ed1[d * 4 + h];
    float4 acc = {0.f, 0.f, 0.f, 0.f};
    float den = 0.f;
#pragma unroll 2
    for (int s = beg; s < end; s++) {
        const int src = __ldg(&g_csrc[s]);
        const float es = __ldg(&g_es1[src * 4 + h]);
        const float ev = __expf(lrelu2(es + edv));
        const float4 xs = *(const float4*)(g_xw1 + (size_t)src * HID + lane * 4);
        acc.x += xs.x * ev; acc.y += xs.y * ev;
        acc.z += xs.z * ev; acc.w += xs.w * ev;
        den += ev;
    }
    const float inv = 1.f / den;
    const float4 b = ((const float4*)g1b)[lane];
    float4 o;
    o.x = acc.x * inv + b.x; o.y = acc.y * inv + b.y;
    o.z = acc.z * inv + b.z; o.w = acc.w * inv + b.w;
    *(float4*)(g_out1 + (size_t)d * HID + lane * 4) = o;
}

// ---------------- GAT2 projection + attn logits -------------------------------
__global__ void __launch_bounds__(128) k_gat2_prep(
    const float* __restrict__ g2as, const float* __restrict__ g2ad)
{
    __shared__ __align__(16) float x_t[128 * TS];
    __shared__ float sp[2][4][NT];
    const int tid = threadIdx.x, n0 = blockIdx.x * NT;
    const int cg4 = (tid >> 2) * 4, ng8 = (tid & 3) * 8;

    for (int idx = tid; idx < NT * HID; idx += 128) {
        const int node = idx >> 7, c = idx & 127;
        x_t[c * TS + node] = g_out1[(size_t)(n0 + node) * HID + c];
    }
    __syncthreads();

    unsigned long long acc[4][4];
#pragma unroll
    for (int c = 0; c < 4; c++)
#pragma unroll
        for (int p = 0; p < 4; p++) acc[c][p] = 0ull;
    gemm_tile128(g_g2t, x_t, cg4, ng8, acc);

    float vals[4][8];
#pragma unroll
    for (int c = 0; c < 4; c++)
#pragma unroll
        for (int p = 0; p < 4; p++) {
            const float2 v = unpack2(acc[c][p]);
            vals[c][2 * p] = v.x; vals[c][2 * p + 1] = v.y;
        }
#pragma unroll
    for (int m = 0; m < 8; m++) {
        float4 o = {vals[0][m], vals[1][m], vals[2][m], vals[3][m]};
        *(float4*)(g_xw2 + (size_t)(n0 + ng8 + m) * HID + cg4) = o;
    }
    const float a0 = g2as[cg4], a1 = g2as[cg4 + 1], a2 = g2as[cg4 + 2], a3 = g2as[cg4 + 3];
    const float d0 = g2ad[cg4], d1 = g2ad[cg4 + 1], d2 = g2ad[cg4 + 2], d3 = g2ad[cg4 + 3];
    const int w = tid >> 5, lane = tid & 31;
#pragma unroll
    for (int m = 0; m < 8; m++) {
        float ps = vals[0][m]*a0 + vals[1][m]*a1 + vals[2][m]*a2 + vals[3][m]*a3;
        float pd = vals[0][m]*d0 + vals[1][m]*d1 + vals[2][m]*d2 + vals[3][m]*d3;
#pragma unroll
        for (int o = 4; o < 32; o <<= 1) {
            ps += __shfl_xor_sync(0xffffffffu, ps, o);
            pd += __shfl_xor_sync(0xffffffffu, pd, o);
        }
        if (lane < 4) { sp[0][w][ng8 + m] = ps; sp[1][w][ng8 + m] = pd; }
    }
    __syncthreads();
    if (tid < 32) {
        g_es2[n0 + tid] = sp[0][0][tid] + sp[0][1][tid] + sp[0][2][tid] + sp[0][3][tid];
    } else if (tid < 64) {
        const int m = tid - 32;
        g_ed2[n0 + m] = sp[1][0][m] + sp[1][1][m] + sp[1][2][m] + sp[1][3][m];
    }
}

// ---------------- GAT2 aggregation --------------------------------------------
__global__ void __launch_bounds__(256) k_agg2(const float* __restrict__ g2b) {
    const int d = (blockIdx.x * blockDim.x + threadIdx.x) >> 5;
    const int lane = threadIdx.x & 31;
    if (d >= NN) return;
    const int beg = g_rs[d], end = g_rs[d + 1];
    const float edv = g_ed2[d];
    float4 acc = {0.f, 0.f, 0.f, 0.f};
    float den = 0.f;
#pragma unroll 2
    for (int s = beg; s < end; s++) {
        const int src = __ldg(&g_csrc[s]);
        const float es = __ldg(&g_es2[src]);
        const float ev = __expf(lrelu2(es + edv));
        const float4 xs = *(const float4*)(g_xw2 + (size_t)src * HID + lane * 4);
        acc.x += xs.x * ev; acc.y += xs.y * ev;
        acc.z += xs.z * ev; acc.w += xs.w * ev;
        den += ev;
    }
    const float inv = 1.f / den;
    const float4 b = ((const float4*)g2b)[lane];
    float4 o;
    o.x = acc.x * inv + b.x; o.y = acc.y * inv + b.y;
    o.z = acc.z * inv + b.z; o.w = acc.w * inv + b.w;
    *(float4*)(g_out2 + (size_t)d * HID + lane * 4) = o;
}

// ---------------- output head ------------------------------------------------
__global__ void __launch_bounds__(128) k_final(
    const float* __restrict__ bo1, const float* __restrict__ Wo2,
    const float* __restrict__ bo2, float* __restrict__ out)
{
    __shared__ __align__(16) float x_t[128 * TS];
    __shared__ float sp[2][4][NT];
    const int tid = threadIdx.x, n0 = blockIdx.x * NT;
    const int cg4 = (tid >> 2) * 4, ng8 = (tid & 3) * 8;

    for (int idx = tid; idx < NT * HID; idx += 128) {
        const int node = idx >> 7, c = idx & 127;
        x_t[c * TS + node] = g_out2[(size_t)(n0 + node) * HID + c];
    }
    __syncthreads();

    unsigned long long acc[4][4];
#pragma unroll
    for (int c = 0; c < 4; c++)
#pragma unroll
        for (int p = 0; p < 4; p++) acc[c][p] = 0ull;
    gemm_tile128(g_Wo1t, x_t, cg4, ng8, acc);

    float vals[4][8];
#pragma unroll
    for (int c = 0; c < 4; c++) {
        const float b = bo1[cg4 + c];
#pragma unroll
        for (int p = 0; p < 4; p++) {
            const float2 v = unpack2(acc[c][p]);
            vals[c][2 * p]     = lrelu01(v.x + b);
            vals[c][2 * p + 1] = lrelu01(v.y + b);
        }
    }
    const float a0 = Wo2[cg4],       a1 = Wo2[cg4 + 1],       a2 = Wo2[cg4 + 2],       a3 = Wo2[cg4 + 3];
    const float d0 = Wo2[128 + cg4], d1 = Wo2[128 + cg4 + 1], d2 = Wo2[128 + cg4 + 2], d3 = Wo2[128 + cg4 + 3];
    const int w = tid >> 5, lane = tid & 31;
#pragma unroll
    for (int m = 0; m < 8; m++) {
        float v0 = vals[0][m]*a0 + vals[1][m]*a1 + vals[2][m]*a2 + vals[3][m]*a3;
        float v1 = vals[0][m]*d0 + vals[1][m]*d1 + vals[2][m]*d2 + vals[3][m]*d3;
#pragma unroll
        for (int o = 4; o < 32; o <<= 1) {
            v0 += __shfl_xor_sync(0xffffffffu, v0, o);
            v1 += __shfl_xor_sync(0xffffffffu, v1, o);
        }
        if (lane < 4) { sp[0][w][ng8 + m] = v0; sp[1][w][ng8 + m] = v1; }
    }
    __syncthreads();
    if (tid < 32) {
        out[(size_t)(n0 + tid) * 2] =
            sp[0][0][tid] + sp[0][1][tid] + sp[0][2][tid] + sp[0][3][tid] + bo2[0];
    } else if (tid < 64) {
        const int m = tid - 32;
        out[(size_t)(n0 + m) * 2 + 1] =
            sp[1][0][m] + sp[1][1][m] + sp[1][2][m] + sp[1][3][m] + bo2[1];
    }
}

// ---------------- launch ------------------------------------------------------
extern "C" void kernel_launch(void* const* d_in, const int* in_sizes, int n_in,
                              void* d_out, int out_size) {
    const float* des  = (const float*)d_in[0];
    const float* twt  = (const float*)d_in[1];
    const float* npr  = (const float*)d_in[2];
    const float* cpr  = (const float*)d_in[3];
    const int*   ei   = (const int*)d_in[4];   // JAX x64 disabled -> int32
    const float* Wd = (const float*)d_in[5];   const float* bd = (const float*)d_in[6];
    const float* Wt = (const float*)d_in[7];   const float* bt = (const float*)d_in[8];
    const float* Wn = (const float*)d_in[9];   const float* bn = (const float*)d_in[10];
    const float* Wc = (const float*)d_in[11];  const float* bc = (const float*)d_in[12];
    const float* Wi = (const float*)d_in[13];  const float* bi = (const float*)d_in[14];
    const float* g1W  = (const float*)d_in[15];
    const float* g1as = (const float*)d_in[16];
    const float* g1ad = (const float*)d_in[17];
    const float* g1b  = (const float*)d_in[18];
    const float* g2W  = (const float*)d_in[19];
    const float* g2as = (const float*)d_in[20];
    const float* g2ad = (const float*)d_in[21];
    const float* g2b  = (const float*)d_in[22];
    const float* Wo1  = (const float*)d_in[23]; const float* bo1 = (const float*)d_in[24];
    const float* Wo2  = (const float*)d_in[25]; const float* bo2 = (const float*)d_in[26];
    float* out = (float*)d_out;

    const int WPN = 768 * 64 + 4 * 128 * 128;
    k_wprep<<<(WPN + 255) / 256, 256>>>(Wd, Wt, Wi, g1W, g2W, Wo1);
    k_init_cnt<<<(NN + 255) / 256, 256>>>();
    k_count<<<(EE + 255) / 256, 256>>>(ei);
    k_features<<<NN / NT, 128>>>(des, twt, npr, cpr, bd, bt, Wn, bn, Wc, bc,
                                 bi, g1as, g1ad);          // ncu-captured slot
    k_scan<<<1, 1024>>>();
    k_fill<<<(ET + 255) / 256, 256>>>(ei);
    k_agg1<<<(NN * 32 + 255) / 256, 256>>>(g1b);
    k_gat2_prep<<<NN / NT, 128>>>(g2as, g2ad);
    k_agg2<<<(NN * 32 + 255) / 256, 256>>>(g2b);
    k_final<<<NN / NT, 128>>>(bo1, Wo2, bo2, out);
}

// round 8
// speedup vs baseline: 1.6018x; 1.2263x over previous
#include <cuda_runtime.h>
#include <cuda_bf16.h>

#define NN   100000
#define EE   1600000
#define ET   (EE + NN)
#define HID  128
#define NT   32                 // nodes per block
#define TS   36                 // transposed activation stride (floats)

// ---------------- scratch globals --------------------------------------------
__device__ __align__(16) float g_xw1 [(size_t)NN * HID];
__device__ __align__(16) float g_es1 [NN * 4];
__device__ __align__(16) float g_ed1 [NN * 4];
__device__ __align__(16) float g_out1[(size_t)NN * HID];
__device__ __align__(16) float g_xw2 [(size_t)NN * HID];
__device__ __align__(16) float g_es2 [NN];
__device__ __align__(16) float g_ed2 [NN];
__device__ __align__(16) float g_out2[(size_t)NN * HID];

// stage-1 weights: bf16 hi/lo split, layout [col][k] (col<32: Wd, else Wt)
__device__ __align__(16) __nv_bfloat16 g_W1bh[64 * 768];
__device__ __align__(16) __nv_bfloat16 g_W1bl[64 * 768];
// fp32 pre-transposed weights for FFMA2 stages: w_t[k][col]
__device__ __align__(16) float g_Wit [128 * 128];
__device__ __align__(16) float g_g1t [128 * 128];
__device__ __align__(16) float g_g2t [128 * 128];
__device__ __align__(16) float g_Wo1t[128 * 128];

// CSR (dst-grouped)
__device__ int g_cnt[NN];
__device__ int g_rs [NN + 1];
__device__ int g_cur[NN];
__device__ int g_csrc[ET];

__device__ __forceinline__ float lrelu01(float v) { return v > 0.f ? v : 0.01f * v; }
__device__ __forceinline__ float lrelu2 (float v) { return v > 0.f ? v : 0.2f  * v; }

// ---- packed fp32x2 helpers ---------------------------------------------------
__device__ __forceinline__ unsigned long long pack2(float x, float y) {
    unsigned long long r;
    asm("mov.b64 %0,{%1,%2};" : "=l"(r) : "f"(x), "f"(y));
    return r;
}
__device__ __forceinline__ float2 unpack2(unsigned long long v) {
    float2 r;
    asm("mov.b64 {%0,%1},%2;" : "=f"(r.x), "=f"(r.y) : "l"(v));
    return r;
}
__device__ __forceinline__ void ffma2(unsigned long long& d,
                                      unsigned long long a, unsigned long long b) {
    asm("fma.rn.f32x2 %0,%1,%2,%0;" : "+l"(d) : "l"(a), "l"(b));
}

// ---- bf16 mma (m16n8k16, row.col, f32 accum) --------------------------------
__device__ __forceinline__ void mma_bf16(float c[4],
                                         unsigned a0, unsigned a1, unsigned a2, unsigned a3,
                                         unsigned b0, unsigned b1) {
    asm volatile(
        "mma.sync.aligned.m16n8k16.row.col.f32.bf16.bf16.f32 "
        "{%0,%1,%2,%3},{%4,%5,%6,%7},{%8,%9},{%0,%1,%2,%3};"
        : "+f"(c[0]), "+f"(c[1]), "+f"(c[2]), "+f"(c[3])
        : "r"(a0), "r"(a1), "r"(a2), "r"(a3), "r"(b0), "r"(b1));
}

// fp32 -> (hi,lo) bf16 split, store 4 k-contiguous elems
__device__ __forceinline__ void cvt_store4(float4 v, __nv_bfloat16* ph, __nv_bfloat16* pl) {
    const __nv_bfloat16 hx = __float2bfloat16(v.x), hy = __float2bfloat16(v.y);
    const __nv_bfloat16 hz = __float2bfloat16(v.z), hw = __float2bfloat16(v.w);
    *(__nv_bfloat162*)(ph)     = __halves2bfloat162(hx, hy);
    *(__nv_bfloat162*)(ph + 2) = __halves2bfloat162(hz, hw);
    *(__nv_bfloat162*)(pl)     = __halves2bfloat162(
        __float2bfloat16(v.x - __bfloat162float(hx)),
        __float2bfloat16(v.y - __bfloat162float(hy)));
    *(__nv_bfloat162*)(pl + 2) = __halves2bfloat162(
        __float2bfloat16(v.z - __bfloat162float(hz)),
        __float2bfloat16(v.w - __bfloat162float(hw)));
}

// 4 cols x 8 nodes tile GEMM over K=128; wt global [k][128], a_t smem stride TS
__device__ __forceinline__ void gemm_tile128(const float* __restrict__ wt,
                                             const float* __restrict__ a_t,
                                             int cg4, int ng8,
                                             unsigned long long acc[4][4]) {
#pragma unroll 4
    for (int k = 0; k < 128; k++) {
        const float4 wv = *(const float4*)(wt + k * 128 + cg4);
        const ulonglong2 a01 = *(const ulonglong2*)(a_t + k * TS + ng8);
        const ulonglong2 a23 = *(const ulonglong2*)(a_t + k * TS + ng8 + 4);
        const unsigned long long w0 = pack2(wv.x, wv.x), w1 = pack2(wv.y, wv.y);
        const unsigned long long w2 = pack2(wv.z, wv.z), w3 = pack2(wv.w, wv.w);
        ffma2(acc[0][0], a01.x, w0); ffma2(acc[0][1], a01.y, w0);
        ffma2(acc[0][2], a23.x, w0); ffma2(acc[0][3], a23.y, w0);
        ffma2(acc[1][0], a01.x, w1); ffma2(acc[1][1], a01.y, w1);
        ffma2(acc[1][2], a23.x, w1); ffma2(acc[1][3], a23.y, w1);
        ffma2(acc[2][0], a01.x, w2); ffma2(acc[2][1], a01.y, w2);
        ffma2(acc[2][2], a23.x, w2); ffma2(acc[2][3], a23.y, w2);
        ffma2(acc[3][0], a01.x, w3); ffma2(acc[3][1], a01.y, w3);
        ffma2(acc[3][2], a23.x, w3); ffma2(acc[3][3], a23.y, w3);
    }
}

// ---------------- weight prep (once per launch) -------------------------------
__global__ void k_wprep(const float* __restrict__ Wd, const float* __restrict__ Wt,
                        const float* __restrict__ Wi, const float* __restrict__ g1W,
                        const float* __restrict__ g2W, const float* __restrict__ Wo1) {
    const int i = blockIdx.x * blockDim.x + threadIdx.x;
    if (i < 64 * 768) {
        const int col = i / 768, k = i - col * 768;
        const float v = (col < 32) ? Wd[col * 768 + k] : Wt[(col - 32) * 768 + k];
        const __nv_bfloat16 h = __float2bfloat16(v);
        g_W1bh[i] = h;
        g_W1bl[i] = __float2bfloat16(v - __bfloat162float(h));
    } else if (i < 64 * 768 + 4 * 128 * 128) {
        const int j = i - 64 * 768;
        const int a = j >> 14, r = j & 16383;
        const int col = r & 127, k = r >> 7;
        const float v = (a == 0 ? Wi : a == 1 ? g1W : a == 2 ? g2W : Wo1)[col * 128 + k];
        (a == 0 ? g_Wit : a == 1 ? g_g1t : a == 2 ? g_g2t : g_Wo1t)[r] = v;
    }
}

// ---------------- CSR build ---------------------------------------------------
__global__ void k_init_cnt() {
    int i = blockIdx.x * blockDim.x + threadIdx.x;
    if (i < NN) g_cnt[i] = 1;
}
__global__ void k_count(const int* __restrict__ ei) {
    int i = blockIdx.x * blockDim.x + threadIdx.x;
    if (i < EE) atomicAdd(&g_cnt[ei[EE + i]], 1);
}
__global__ void __launch_bounds__(1024, 1) k_scan() {
    __shared__ int ssum[1024];
    const int t = threadIdx.x;
    const int C = (NN + 1023) / 1024;
    const int beg = t * C;
    const int end = (beg + C < NN) ? beg + C : NN;
    int s = 0;
    for (int i = beg; i < end; i++) s += g_cnt[i];
    ssum[t] = s;
    __syncthreads();
    for (int o = 1; o < 1024; o <<= 1) {
        int v = (t >= o) ? ssum[t - o] : 0;
        __syncthreads();
        ssum[t] += v;
        __syncthreads();
    }
    int pre = (t == 0) ? 0 : ssum[t - 1];
    for (int i = beg; i < end; i++) {
        g_rs[i] = pre; g_cur[i] = pre; pre += g_cnt[i];
    }
    if (t == 0) g_rs[NN] = ET;
}
__global__ void k_fill(const int* __restrict__ ei) {
    int i = blockIdx.x * blockDim.x + threadIdx.x;
    if (i >= ET) return;
    int src, dst;
    if (i < EE) { src = ei[i]; dst = ei[EE + i]; }
    else        { src = dst = i - EE; }
    g_csrc[atomicAdd(&g_cur[dst], 1)] = src;
}

// ---------------- features -> x -> Wi -> g1 projection + attn logits ---------
__global__ void __launch_bounds__(128) k_features(
    const float* __restrict__ des, const float* __restrict__ twt,
    const float* __restrict__ npr, const float* __restrict__ cpr,
    const float* __restrict__ bd,  const float* __restrict__ bt,
    const float* __restrict__ Wn,  const float* __restrict__ bn,
    const float* __restrict__ Wc,  const float* __restrict__ bc,
    const float* __restrict__ bi,
    const float* __restrict__ g1as, const float* __restrict__ g1ad)
{
    __shared__ __align__(16) float x_t[128 * TS];        // x transposed [feat][node]
    // pool: stage-1 bf16 staging (2 sets x 2 arr x hi/lo x 32x36) == stage-2 x2_t
    __shared__ __align__(16) char pool[128 * TS * 4];

    float*         x2_t = (float*)pool;
    __nv_bfloat16* sa   = (__nv_bfloat16*)pool;
    // sa offset: ((set*2 + arr)*2 + part) * 1152, elem idx = node*36 + k

    const int tid = threadIdx.x;
    const int n0  = blockIdx.x * NT;
    const int wid = tid >> 5, lane = tid & 31;

    // stage-1 mma decode
    const int arr = wid >> 1;            // 0: des, 1: twt
    const int nb  = (wid & 1) * 16;      // col base within arr
    const int lr  = lane >> 2;           // groupID
    const int lk2 = (lane & 3) * 2;      // k-pair base

    // staging decode
    const int ld_c4 = tid & 7, ld_r0 = tid >> 3;   // nodes ld_r0, ld_r0+16

    float c[2][2][4];
#pragma unroll
    for (int m = 0; m < 2; m++)
#pragma unroll
        for (int nt = 0; nt < 2; nt++)
#pragma unroll
            for (int q = 0; q < 4; q++) c[m][nt][q] = 0.f;

    float4 pd0, pt0, pd1, pt1;
    {   // prefetch + stage chunk 0 (set 0)
        const float* dp = des + (size_t)(n0 + ld_r0) * 768 + 4 * ld_c4;
        const float* tp = twt + (size_t)(n0 + ld_r0) * 768 + 4 * ld_c4;
        pd0 = *(const float4*)(dp);
        pt0 = *(const float4*)(tp);
        pd1 = *(const float4*)(dp + 16 * 768);
        pt1 = *(const float4*)(tp + 16 * 768);
        const int off0 = ld_r0 * 36 + 4 * ld_c4;
        cvt_store4(pd0, sa + 0 * 1152 + off0, sa + 1 * 1152 + off0);          // des
        cvt_store4(pd1, sa + 0 * 1152 + off0 + 576, sa + 1 * 1152 + off0 + 576);
        cvt_store4(pt0, sa + 2 * 1152 + off0, sa + 3 * 1152 + off0);          // twt
        cvt_store4(pt1, sa + 2 * 1152 + off0 + 576, sa + 3 * 1152 + off0 + 576);
    }
    __syncthreads();

    for (int ch = 0; ch < 24; ch++) {
        if (ch < 23) {   // prefetch chunk ch+1
            const int kb2 = (ch + 1) * 32;
            const float* dp = des + (size_t)(n0 + ld_r0) * 768 + kb2 + 4 * ld_c4;
            const float* tp = twt + (size_t)(n0 + ld_r0) * 768 + kb2 + 4 * ld_c4;
            pd0 = *(const float4*)(dp);
            pt0 = *(const float4*)(tp);
            pd1 = *(const float4*)(dp + 16 * 768);
            pt1 = *(const float4*)(tp + 16 * 768);
        }
        // compute this chunk: 2 ksteps of k16, 2 m-tiles x 2 n-tiles, bf16x3
        {
            const int set = ch & 1;
            const __nv_bfloat16* sh_h = sa + ((set * 2 + arr) * 2 + 0) * 1152;
            const __nv_bfloat16* sh_l = sa + ((set * 2 + arr) * 2 + 1) * 1152;
#pragma unroll
            for (int ks = 0; ks < 2; ks++) {
                const int k0 = ks * 16 + lk2;
                unsigned ah[2][4], al[2][4];
#pragma unroll
                for (int m = 0; m < 2; m++) {
                    const __nv_bfloat16* ph = sh_h + (m * 16 + lr) * 36;
                    const __nv_bfloat16* pl = sh_l + (m * 16 + lr) * 36;
                    ah[m][0] = *(const unsigned*)(ph + k0);
                    ah[m][1] = *(const unsigned*)(ph + 288 + k0);
                    ah[m][2] = *(const unsigned*)(ph + k0 + 8);
                    ah[m][3] = *(const unsigned*)(ph + 288 + k0 + 8);
                    al[m][0] = *(const unsigned*)(pl + k0);
                    al[m][1] = *(const unsigned*)(pl + 288 + k0);
                    al[m][2] = *(const unsigned*)(pl + k0 + 8);
                    al[m][3] = *(const unsigned*)(pl + 288 + k0 + 8);
                }
#pragma unroll
                for (int nt = 0; nt < 2; nt++) {
                    const int col0 = arr * 32 + nb + nt * 8 + lr;
                    const int wo = col0 * 768 + ch * 32 + ks * 16 + lk2;
                    const unsigned bh0 = *(const unsigned*)(g_W1bh + wo);
                    const unsigned bh1 = *(const unsigned*)(g_W1bh + wo + 8);
                    const unsigned bl0 = *(const unsigned*)(g_W1bl + wo);
                    const unsigned bl1 = *(const unsigned*)(g_W1bl + wo + 8);
#pragma unroll
                    for (int m = 0; m < 2; m++) {
                        mma_bf16(c[m][nt], ah[m][0], ah[m][1], ah[m][2], ah[m][3], bh0, bh1);
                        mma_bf16(c[m][nt], ah[m][0], ah[m][1], ah[m][2], ah[m][3], bl0, bl1);
                        mma_bf16(c[m][nt], al[m][0], al[m][1], al[m][2], al[m][3], bh0, bh1);
                    }
                }
            }
        }
        if (ch < 23) {   // stage chunk ch+1 into the other set
            const int set2 = (ch + 1) & 1;
            const int off0 = ld_r0 * 36 + 4 * ld_c4;
            cvt_store4(pd0, sa + ((set2 * 2 + 0) * 2 + 0) * 1152 + off0,
                            sa + ((set2 * 2 + 0) * 2 + 1) * 1152 + off0);
            cvt_store4(pd1, sa + ((set2 * 2 + 0) * 2 + 0) * 1152 + off0 + 576,
                            sa + ((set2 * 2 + 0) * 2 + 1) * 1152 + off0 + 576);
            cvt_store4(pt0, sa + ((set2 * 2 + 1) * 2 + 0) * 1152 + off0,
                            sa + ((set2 * 2 + 1) * 2 + 1) * 1152 + off0);
            cvt_store4(pt1, sa + ((set2 * 2 + 1) * 2 + 0) * 1152 + off0 + 576,
                            sa + ((set2 * 2 + 1) * 2 + 1) * 1152 + off0 + 576);
        }
        __syncthreads();
    }

    // ---- stage-1 epilogue: bias + lrelu, write x_t [col][node] --------------
#pragma unroll
    for (int m = 0; m < 2; m++)
#pragma unroll
        for (int nt = 0; nt < 2; nt++) {
            const int col0 = arr * 32 + nb + nt * 8 + lk2;
            const int r0 = m * 16 + lr;
            const float b0 = (col0 < 32) ? bd[col0] : bt[col0 - 32];
            const float b1 = (col0 + 1 < 32) ? bd[col0 + 1] : bt[col0 + 1 - 32];
            x_t[col0 * TS + r0]           = lrelu01(c[m][nt][0] + b0);
            x_t[(col0 + 1) * TS + r0]     = lrelu01(c[m][nt][1] + b1);
            x_t[col0 * TS + r0 + 8]       = lrelu01(c[m][nt][2] + b0);
            x_t[(col0 + 1) * TS + r0 + 8] = lrelu01(c[m][nt][3] + b1);
        }
    {   // num/cat: 64 cols x 2 node-halves over 128 threads
        const int col = tid >> 1, mh = (tid & 1) * 16;
        if (col < 32) {
            const float w0 = Wn[col * 5], w1 = Wn[col * 5 + 1], w2 = Wn[col * 5 + 2],
                        w3 = Wn[col * 5 + 3], w4 = Wn[col * 5 + 4];
            const float b = bn[col];
            for (int m = 0; m < 16; m++) {
                const float* r = npr + (size_t)(n0 + mh + m) * 5;
                x_t[(64 + col) * TS + mh + m] =
                    lrelu01(r[0]*w0 + r[1]*w1 + r[2]*w2 + r[3]*w3 + r[4]*w4 + b);
            }
        } else {
            const int jj = col - 32;
            const float w0 = Wc[jj * 3], w1 = Wc[jj * 3 + 1], w2 = Wc[jj * 3 + 2];
            const float b = bc[jj];
            for (int m = 0; m < 16; m++) {
                const float* r = cpr + (size_t)(n0 + mh + m) * 3;
                x_t[(96 + jj) * TS + mh + m] = lrelu01(r[0]*w0 + r[1]*w1 + r[2]*w2 + b);
            }
        }
    }
    __syncthreads();

    const int cg4 = (tid >> 2) * 4, ng8 = (tid & 3) * 8;

    // ---- stage 2: x2 = lrelu(x @ Wi^T + bi) ---------------------------------
    {
        unsigned long long acc[4][4];
#pragma unroll
        for (int cc = 0; cc < 4; cc++)
#pragma unroll
            for (int p = 0; p < 4; p++) acc[cc][p] = 0ull;
        gemm_tile128(g_Wit, x_t, cg4, ng8, acc);
        __syncthreads();       // staging readers done before x2_t overwrite
#pragma unroll
        for (int cc = 0; cc < 4; cc++) {
            const int col = cg4 + cc;
            const float b = bi[col];
#pragma unroll
            for (int p = 0; p < 4; p++) {
                const float2 v = unpack2(acc[cc][p]);
                x2_t[col * TS + ng8 + 2 * p]     = lrelu01(v.x + b);
                x2_t[col * TS + ng8 + 2 * p + 1] = lrelu01(v.y + b);
            }
        }
    }
    __syncthreads();

    // ---- stage 3: xw1 = x2 @ g1_W^T + logits --------------------------------
    {
        unsigned long long acc[4][4];
#pragma unroll
        for (int cc = 0; cc < 4; cc++)
#pragma unroll
            for (int p = 0; p < 4; p++) acc[cc][p] = 0ull;
        gemm_tile128(g_g1t, x2_t, cg4, ng8, acc);

        float vals[4][8];
#pragma unroll
        for (int cc = 0; cc < 4; cc++)
#pragma unroll
            for (int p = 0; p < 4; p++) {
                const float2 v = unpack2(acc[cc][p]);
                vals[cc][2 * p] = v.x; vals[cc][2 * p + 1] = v.y;
            }
#pragma unroll
        for (int m = 0; m < 8; m++) {
            float4 o = {vals[0][m], vals[1][m], vals[2][m], vals[3][m]};
            *(float4*)(g_xw1 + (size_t)(n0 + ng8 + m) * HID + cg4) = o;
        }
        const float a0 = g1as[cg4], a1 = g1as[cg4 + 1], a2 = g1as[cg4 + 2], a3 = g1as[cg4 + 3];
        const float d0 = g1ad[cg4], d1 = g1ad[cg4 + 1], d2 = g1ad[cg4 + 2], d3 = g1ad[cg4 + 3];
#pragma unroll
        for (int m = 0; m < 8; m++) {
            float ps = vals[0][m]*a0 + vals[1][m]*a1 + vals[2][m]*a2 + vals[3][m]*a3;
            float pd = vals[0][m]*d0 + vals[1][m]*d1 + vals[2][m]*d2 + vals[3][m]*d3;
#pragma unroll
            for (int o = 4; o < 32; o <<= 1) {
                ps += __shfl_xor_sync(0xffffffffu, ps, o);
                pd += __shfl_xor_sync(0xffffffffu, pd, o);
            }
            if (lane < 4) {
                g_es1[(n0 + ng8 + m) * 4 + wid] = ps;
                g_ed1[(n0 + ng8 + m) * 4 + wid] = pd;
            }
        }
    }
}

// ---------------- GAT1 aggregation: warp-per-dst gather, fused exp ------------
__global__ void __launch_bounds__(256) k_agg1(const float* __restrict__ g1b) {
    const int d = (blockIdx.x * blockDim.x + threadIdx.x) >> 5;
    const int lane = threadIdx.x & 31;
    if (d >= NN) return;
    const int beg = g_rs[d], end = g_rs[d + 1];
    const int h = lane >> 3;
    const float edv = g_ed1[d * 4 + h];
    float4 acc = {0.f, 0.f, 0.f, 0.f};
    float den = 0.f;
#pragma unroll 2
    for (int s = beg; s < end; s++) {
        const int src = __ldg(&g_csrc[s]);
        const float es = __ldg(&g_es1[src * 4 + h]);
        const float ev = __expf(lrelu2(es + edv));
        const float4 xs = *(const float4*)(g_xw1 + (size_t)src * HID + lane * 4);
        acc.x += xs.x * ev; acc.y += xs.y * ev;
        acc.z += xs.z * ev; acc.w += xs.w * ev;
        den += ev;
    }
    const float inv = 1.f / den;
    const float4 b = ((const float4*)g1b)[lane];
    float4 o;
    o.x = acc.x * inv + b.x; o.y = acc.y * inv + b.y;
    o.z = acc.z * inv + b.z; o.w = acc.w * inv + b.w;
    *(float4*)(g_out1 + (size_t)d * HID + lane * 4) = o;
}

// ---------------- GAT2 projection + attn logits -------------------------------
__global__ void __launch_bounds__(128) k_gat2_prep(
    const float* __restrict__ g2as, const float* __restrict__ g2ad)
{
    __shared__ __align__(16) float x_t[128 * TS];
    __shared__ float sp[2][4][NT];
    const int tid = threadIdx.x, n0 = blockIdx.x * NT;
    const int cg4 = (tid >> 2) * 4, ng8 = (tid & 3) * 8;

    for (int idx = tid; idx < NT * HID; idx += 128) {
        const int node = idx >> 7, cc = idx & 127;
        x_t[cc * TS + node] = g_out1[(size_t)(n0 + node) * HID + cc];
    }
    __syncthreads();

    unsigned long long acc[4][4];
#pragma unroll
    for (int cc = 0; cc < 4; cc++)
#pragma unroll
        for (int p = 0; p < 4; p++) acc[cc][p] = 0ull;
    gemm_tile128(g_g2t, x_t, cg4, ng8, acc);

    float vals[4][8];
#pragma unroll
    for (int cc = 0; cc < 4; cc++)
#pragma unroll
        for (int p = 0; p < 4; p++) {
            const float2 v = unpack2(acc[cc][p]);
            vals[cc][2 * p] = v.x; vals[cc][2 * p + 1] = v.y;
        }
#pragma unroll
    for (int m = 0; m < 8; m++) {
        float4 o = {vals[0][m], vals[1][m], vals[2][m], vals[3][m]};
        *(float4*)(g_xw2 + (size_t)(n0 + ng8 + m) * HID + cg4) = o;
    }
    const float a0 = g2as[cg4], a1 = g2as[cg4 + 1], a2 = g2as[cg4 + 2], a3 = g2as[cg4 + 3];
    const float d0 = g2ad[cg4], d1 = g2ad[cg4 + 1], d2 = g2ad[cg4 + 2], d3 = g2ad[cg4 + 3];
    const int w = tid >> 5, lane = tid & 31;
#pragma unroll
    for (int m = 0; m < 8; m++) {
        float ps = vals[0][m]*a0 + vals[1][m]*a1 + vals[2][m]*a2 + vals[3][m]*a3;
        float pd = vals[0][m]*d0 + vals[1][m]*d1 + vals[2][m]*d2 + vals[3][m]*d3;
#pragma unroll
        for (int o = 4; o < 32; o <<= 1) {
            ps += __shfl_xor_sync(0xffffffffu, ps, o);
            pd += __shfl_xor_sync(0xffffffffu, pd, o);
        }
        if (lane < 4) { sp[0][w][ng8 + m] = ps; sp[1][w][ng8 + m] = pd; }
    }
    __syncthreads();
    if (tid < 32) {
        g_es2[n0 + tid] = sp[0][0][tid] + sp[0][1][tid] + sp[0][2][tid] + sp[0][3][tid];
    } else if (tid < 64) {
        const int m = tid - 32;
        g_ed2[n0 + m] = sp[1][0][m] + sp[1][1][m] + sp[1][2][m] + sp[1][3][m];
    }
}

// ---------------- GAT2 aggregation --------------------------------------------
__global__ void __launch_bounds__(256) k_agg2(const float* __restrict__ g2b) {
    const int d = (blockIdx.x * blockDim.x + threadIdx.x) >> 5;
    const int lane = threadIdx.x & 31;
    if (d >= NN) return;
    const int beg = g_rs[d], end = g_rs[d + 1];
    const float edv = g_ed2[d];
    float4 acc = {0.f, 0.f, 0.f, 0.f};
    float den = 0.f;
#pragma unroll 2
    for (int s = beg; s < end; s++) {
        const int src = __ldg(&g_csrc[s]);
        const float es = __ldg(&g_es2[src]);
        const float ev = __expf(lrelu2(es + edv));
        const float4 xs = *(const float4*)(g_xw2 + (size_t)src * HID + lane * 4);
        acc.x += xs.x * ev; acc.y += xs.y * ev;
        acc.z += xs.z * ev; acc.w += xs.w * ev;
        den += ev;
    }
    const float inv = 1.f / den;
    const float4 b = ((const float4*)g2b)[lane];
    float4 o;
    o.x = acc.x * inv + b.x; o.y = acc.y * inv + b.y;
    o.z = acc.z * inv + b.z; o.w = acc.w * inv + b.w;
    *(float4*)(g_out2 + (size_t)d * HID + lane * 4) = o;
}

// ---------------- output head ------------------------------------------------
__global__ void __launch_bounds__(128) k_final(
    const float* __restrict__ bo1, const float* __restrict__ Wo2,
    const float* __restrict__ bo2, float* __restrict__ out)
{
    __shared__ __align__(16) float x_t[128 * TS];
    __shared__ float sp[2][4][NT];
    const int tid = threadIdx.x, n0 = blockIdx.x * NT;
    const int cg4 = (tid >> 2) * 4, ng8 = (tid & 3) * 8;

    for (int idx = tid; idx < NT * HID; idx += 128) {
        const int node = idx >> 7, cc = idx & 127;
        x_t[cc * TS + node] = g_out2[(size_t)(n0 + node) * HID + cc];
    }
    __syncthreads();

    unsigned long long acc[4][4];
#pragma unroll
    for (int cc = 0; cc < 4; cc++)
#pragma unroll
        for (int p = 0; p < 4; p++) acc[cc][p] = 0ull;
    gemm_tile128(g_Wo1t, x_t, cg4, ng8, acc);

    float vals[4][8];
#pragma unroll
    for (int cc = 0; cc < 4; cc++) {
        const float b = bo1[cg4 + cc];
#pragma unroll
        for (int p = 0; p < 4; p++) {
            const float2 v = unpack2(acc[cc][p]);
            vals[cc][2 * p]     = lrelu01(v.x + b);
            vals[cc][2 * p + 1] = lrelu01(v.y + b);
        }
    }
    const float a0 = Wo2[cg4],       a1 = Wo2[cg4 + 1],       a2 = Wo2[cg4 + 2],       a3 = Wo2[cg4 + 3];
    const float d0 = Wo2[128 + cg4], d1 = Wo2[128 + cg4 + 1], d2 = Wo2[128 + cg4 + 2], d3 = Wo2[128 + cg4 + 3];
    const int w = tid >> 5, lane = tid & 31;
#pragma unroll
    for (int m = 0; m < 8; m++) {
        float v0 = vals[0][m]*a0 + vals[1][m]*a1 + vals[2][m]*a2 + vals[3][m]*a3;
        float v1 = vals[0][m]*d0 + vals[1][m]*d1 + vals[2][m]*d2 + vals[3][m]*d3;
#pragma unroll
        for (int o = 4; o < 32; o <<= 1) {
            v0 += __shfl_xor_sync(0xffffffffu, v0, o);
            v1 += __shfl_xor_sync(0xffffffffu, v1, o);
        }
        if (lane < 4) { sp[0][w][ng8 + m] = v0; sp[1][w][ng8 + m] = v1; }
    }
    __syncthreads();
    if (tid < 32) {
        out[(size_t)(n0 + tid) * 2] =
            sp[0][0][tid] + sp[0][1][tid] + sp[0][2][tid] + sp[0][3][tid] + bo2[0];
    } else if (tid < 64) {
        const int m = tid - 32;
        out[(size_t)(n0 + m) * 2 + 1] =
            sp[1][0][m] + sp[1][1][m] + sp[1][2][m] + sp[1][3][m] + bo2[1];
    }
}

// ---------------- launch ------------------------------------------------------
extern "C" void kernel_launch(void* const* d_in, const int* in_sizes, int n_in,
                              void* d_out, int out_size) {
    const float* des  = (const float*)d_in[0];
    const float* twt  = (const float*)d_in[1];
    const float* npr  = (const float*)d_in[2];
    const float* cpr  = (const float*)d_in[3];
    const int*   ei   = (const int*)d_in[4];   // JAX x64 disabled -> int32
    const float* Wd = (const float*)d_in[5];   const float* bd = (const float*)d_in[6];
    const float* Wt = (const float*)d_in[7];   const float* bt = (const float*)d_in[8];
    const float* Wn = (const float*)d_in[9];   const float* bn = (const float*)d_in[10];
    const float* Wc = (const float*)d_in[11];  const float* bc = (const float*)d_in[12];
    const float* Wi = (const float*)d_in[13];  const float* bi = (const float*)d_in[14];
    const float* g1W  = (const float*)d_in[15];
    const float* g1as = (const float*)d_in[16];
    const float* g1ad = (const float*)d_in[17];
    const float* g1b  = (const float*)d_in[18];
    const float* g2W  = (const float*)d_in[19];
    const float* g2as = (const float*)d_in[20];
    const float* g2ad = (const float*)d_in[21];
    const float* g2b  = (const float*)d_in[22];
    const float* Wo1  = (const float*)d_in[23]; const float* bo1 = (const float*)d_in[24];
    const float* Wo2  = (const float*)d_in[25]; const float* bo2 = (const float*)d_in[26];
    float* out = (float*)d_out;

    const int WPN = 64 * 768 + 4 * 128 * 128;
    k_wprep<<<(WPN + 255) / 256, 256>>>(Wd, Wt, Wi, g1W, g2W, Wo1);
    k_init_cnt<<<(NN + 255) / 256, 256>>>();
    k_count<<<(EE + 255) / 256, 256>>>(ei);
    k_features<<<NN / NT, 128>>>(des, twt, npr, cpr, bd, bt, Wn, bn, Wc, bc,
                                 bi, g1as, g1ad);          // ncu-captured slot
    k_scan<<<1, 1024>>>();
    k_fill<<<(ET + 255) / 256, 256>>>(ei);
    k_agg1<<<(NN * 32 + 255) / 256, 256>>>(g1b);
    k_gat2_prep<<<NN / NT, 128>>>(g2as, g2ad);
    k_agg2<<<(NN * 32 + 255) / 256, 256>>>(g2b);
    k_final<<<NN / NT, 128>>>(bo1, Wo2, bo2, out);
}

// round 9
// speedup vs baseline: 2.4035x; 1.5005x over previous
#include <cuda_runtime.h>
#include <cuda_bf16.h>

#define NN   100000
#define EE   1600000
#define ET   (EE + NN)
#define HID  128
#define NT   32                 // nodes per block
#define XS   136                // bf16 activation row stride (k=128 + pad)
#define SS   40                 // stage-1 staging row stride (k=32 + pad)

// ---------------- scratch globals --------------------------------------------
__device__ __align__(16) float g_xw1 [(size_t)NN * HID];
__device__ __align__(16) float g_es1 [NN * 4];
__device__ __align__(16) float g_ed1 [NN * 4];
__device__ __align__(16) float g_out1[(size_t)NN * HID];
__device__ __align__(16) float g_xw2 [(size_t)NN * HID];
__device__ __align__(16) float g_es2 [NN];
__device__ __align__(16) float g_ed2 [NN];
__device__ __align__(16) float g_out2[(size_t)NN * HID];

// fragment-packed weights: [col][kstep][quad] -> 16B {hi01,hi89,lo01,lo89}
__device__ __align__(16) __nv_bfloat16 g_W1p [64 * 48 * 4 * 8];   // stage1 (K=768)
__device__ __align__(16) __nv_bfloat16 g_Wip [128 * 8 * 4 * 8];
__device__ __align__(16) __nv_bfloat16 g_g1p [128 * 8 * 4 * 8];
__device__ __align__(16) __nv_bfloat16 g_g2p [128 * 8 * 4 * 8];
__device__ __align__(16) __nv_bfloat16 g_Wo1p[128 * 8 * 4 * 8];

// CSR (dst-grouped)
__device__ int g_cnt[NN];
__device__ int g_rs [NN + 1];
__device__ int g_cur[NN];
__device__ int g_csrc[ET];

__device__ __forceinline__ float lrelu01(float v) { return v > 0.f ? v : 0.01f * v; }
__device__ __forceinline__ float lrelu2 (float v) { return v > 0.f ? v : 0.2f  * v; }

__device__ __forceinline__ unsigned cvta_s(const void* p) {
    return (unsigned)__cvta_generic_to_shared(p);
}
__device__ __forceinline__ void ldm_x4(uint4& v, unsigned addr) {
    asm volatile("ldmatrix.sync.aligned.m8n8.x4.shared.b16 {%0,%1,%2,%3}, [%4];"
                 : "=r"(v.x), "=r"(v.y), "=r"(v.z), "=r"(v.w) : "r"(addr));
}
__device__ __forceinline__ void mma_bf16(float c[4], const uint4& a,
                                         unsigned b0, unsigned b1) {
    asm volatile(
        "mma.sync.aligned.m16n8k16.row.col.f32.bf16.bf16.f32 "
        "{%0,%1,%2,%3},{%4,%5,%6,%7},{%8,%9},{%0,%1,%2,%3};"
        : "+f"(c[0]), "+f"(c[1]), "+f"(c[2]), "+f"(c[3])
        : "r"(a.x), "r"(a.y), "r"(a.z), "r"(a.w), "r"(b0), "r"(b1));
}

// f32x4 -> bf16 hi/lo packed pairs
__device__ __forceinline__ void split4(float4 v, uint2& h, uint2& l) {
    const __nv_bfloat16 hx = __float2bfloat16(v.x), hy = __float2bfloat16(v.y);
    const __nv_bfloat16 hz = __float2bfloat16(v.z), hw = __float2bfloat16(v.w);
    __nv_bfloat162 t;
    t = __halves2bfloat162(hx, hy); h.x = *(unsigned*)&t;
    t = __halves2bfloat162(hz, hw); h.y = *(unsigned*)&t;
    t = __halves2bfloat162(__float2bfloat16(v.x - __bfloat162float(hx)),
                           __float2bfloat16(v.y - __bfloat162float(hy)));
    l.x = *(unsigned*)&t;
    t = __halves2bfloat162(__float2bfloat16(v.z - __bfloat162float(hz)),
                           __float2bfloat16(v.w - __bfloat162float(hw)));
    l.y = *(unsigned*)&t;
}
__device__ __forceinline__ unsigned pack_bf2(float a, float b) {
    __nv_bfloat162 t = __halves2bfloat162(__float2bfloat16(a), __float2bfloat16(b));
    return *(unsigned*)&t;
}

// shared 3-term bf16 GEMM: 32 nodes x 32 cols (per warp) x K=128
// abuf: bf16 [64][XS], hi rows 0-31, lo rows 32-63. wp: fragment-packed weights.
__device__ __forceinline__ void mma_gemm128(const __nv_bfloat16* abuf,
                                            const __nv_bfloat16* __restrict__ wp,
                                            int wid, int lane, float c[2][4][4]) {
    const int row_l = (lane & 7) + ((lane >> 3) & 1) * 8;
    const int koff  = (lane >> 4) * 8;
    const int nrow  = lane >> 2, q = lane & 3;
    const unsigned sb = cvta_s(abuf);
#pragma unroll
    for (int ks = 0; ks < 8; ks++) {
        uint4 ah[2], al[2];
#pragma unroll
        for (int m = 0; m < 2; m++) {
            ldm_x4(ah[m], sb + ((m * 16 + row_l) * XS + ks * 16 + koff) * 2);
            ldm_x4(al[m], sb + ((32 + m * 16 + row_l) * XS + ks * 16 + koff) * 2);
        }
#pragma unroll
        for (int nt = 0; nt < 4; nt++) {
            const int col = wid * 32 + nt * 8 + nrow;
            const uint4 b = *(const uint4*)(wp + ((size_t)(col * 8 + ks) * 4 + q) * 8);
#pragma unroll
            for (int m = 0; m < 2; m++) {
                mma_bf16(c[m][nt], ah[m], b.x, b.y);
                mma_bf16(c[m][nt], ah[m], b.z, b.w);
                mma_bf16(c[m][nt], al[m], b.x, b.y);
            }
        }
    }
}

// ---------------- weight prep (once per launch) -------------------------------
__device__ __forceinline__ uint4 pack_frag(float v0, float v1, float v2, float v3) {
    uint4 r;
    const __nv_bfloat16 h0 = __float2bfloat16(v0), h1 = __float2bfloat16(v1);
    const __nv_bfloat16 h2 = __float2bfloat16(v2), h3 = __float2bfloat16(v3);
    __nv_bfloat162 t;
    t = __halves2bfloat162(h0, h1); r.x = *(unsigned*)&t;
    t = __halves2bfloat162(h2, h3); r.y = *(unsigned*)&t;
    t = __halves2bfloat162(__float2bfloat16(v0 - __bfloat162float(h0)),
                           __float2bfloat16(v1 - __bfloat162float(h1)));
    r.z = *(unsigned*)&t;
    t = __halves2bfloat162(__float2bfloat16(v2 - __bfloat162float(h2)),
                           __float2bfloat16(v3 - __bfloat162float(h3)));
    r.w = *(unsigned*)&t;
    return r;
}

__global__ void k_wprep(const float* __restrict__ Wd, const float* __restrict__ Wt,
                        const float* __restrict__ Wi, const float* __restrict__ g1W,
                        const float* __restrict__ g2W, const float* __restrict__ Wo1) {
    const int i = blockIdx.x * blockDim.x + threadIdx.x;
    if (i < 64 * 48 * 4) {
        const int col = i / 192, ks = (i % 192) / 4, q = i % 4;
        const int k0 = ks * 16 + q * 2;
        const float* src = (col < 32) ? Wd + (size_t)col * 768
                                      : Wt + (size_t)(col - 32) * 768;
        *(uint4*)(g_W1p + (size_t)i * 8) =
            pack_frag(src[k0], src[k0 + 1], src[k0 + 8], src[k0 + 9]);
    } else if (i < 64 * 48 * 4 + 4 * 128 * 8 * 4) {
        const int j = i - 64 * 48 * 4;
        const int mat = j >> 12, r = j & 4095;
        const int col = r / 32, ks = (r % 32) / 4, q = r % 4;
        const int k0 = ks * 16 + q * 2;
        const float* W = (mat == 0 ? Wi : mat == 1 ? g1W : mat == 2 ? g2W : Wo1)
                       + (size_t)col * 128;
        __nv_bfloat16* dst = (mat == 0 ? g_Wip : mat == 1 ? g_g1p
                              : mat == 2 ? g_g2p : g_Wo1p);
        *(uint4*)(dst + (size_t)r * 8) =
            pack_frag(W[k0], W[k0 + 1], W[k0 + 8], W[k0 + 9]);
    }
}

// ---------------- CSR build ---------------------------------------------------
__global__ void k_init_cnt() {
    int i = blockIdx.x * blockDim.x + threadIdx.x;
    if (i < NN) g_cnt[i] = 1;
}
__global__ void k_count(const int* __restrict__ ei) {
    int i = blockIdx.x * blockDim.x + threadIdx.x;
    if (i < EE) atomicAdd(&g_cnt[ei[EE + i]], 1);
}
__global__ void __launch_bounds__(1024, 1) k_scan() {
    __shared__ int ssum[1024];
    const int t = threadIdx.x;
    const int C = (NN + 1023) / 1024;
    const int beg = t * C;
    const int end = (beg + C < NN) ? beg + C : NN;
    int s = 0;
    for (int i = beg; i < end; i++) s += g_cnt[i];
    ssum[t] = s;
    __syncthreads();
    for (int o = 1; o < 1024; o <<= 1) {
        int v = (t >= o) ? ssum[t - o] : 0;
        __syncthreads();
        ssum[t] += v;
        __syncthreads();
    }
    int pre = (t == 0) ? 0 : ssum[t - 1];
    for (int i = beg; i < end; i++) {
        g_rs[i] = pre; g_cur[i] = pre; pre += g_cnt[i];
    }
    if (t == 0) g_rs[NN] = ET;
}
__global__ void k_fill(const int* __restrict__ ei) {
    int i = blockIdx.x * blockDim.x + threadIdx.x;
    if (i >= ET) return;
    int src, dst;
    if (i < EE) { src = ei[i]; dst = ei[EE + i]; }
    else        { src = dst = i - EE; }
    g_csrc[atomicAdd(&g_cur[dst], 1)] = src;
}

// ---------------- features -> x -> Wi -> g1 projection + attn logits ---------
__global__ void __launch_bounds__(128) k_features(
    const float* __restrict__ des, const float* __restrict__ twt,
    const float* __restrict__ npr, const float* __restrict__ cpr,
    const float* __restrict__ bd,  const float* __restrict__ bt,
    const float* __restrict__ Wn,  const float* __restrict__ bn,
    const float* __restrict__ Wc,  const float* __restrict__ bc,
    const float* __restrict__ bi,
    const float* __restrict__ g1as, const float* __restrict__ g1ad)
{
    // pool: xb [64][XS] bf16 @0 (17408B), x2b @17408 (17408B).
    // stage-1 staging (4 x 64x SS x2B = 20480B) aliases @0 (dead before xb write).
    __shared__ __align__(16) char pool[34816];
    __nv_bfloat16* xb  = (__nv_bfloat16*)pool;
    __nv_bfloat16* x2b = (__nv_bfloat16*)(pool + 17408);
    __nv_bfloat16* sa  = (__nv_bfloat16*)pool;

    const int tid = threadIdx.x;
    const int n0  = blockIdx.x * NT;
    const int wid = tid >> 5, lane = tid & 31;

    // stage-1 decode
    const int arr = wid >> 1;            // 0: des, 1: twt
    const int nb  = (wid & 1) * 16;
    const int lr  = lane >> 2, lq2 = (lane & 3) * 2;
    const int row_l = (lane & 7) + ((lane >> 3) & 1) * 8;
    const int koff  = (lane >> 4) * 8;
    // staging decode
    const int ld_c4 = tid & 7, ld_r0 = tid >> 3;

    float c1[2][2][4];
#pragma unroll
    for (int m = 0; m < 2; m++)
#pragma unroll
        for (int nt = 0; nt < 2; nt++)
#pragma unroll
            for (int q = 0; q < 4; q++) c1[m][nt][q] = 0.f;

    float4 pd0, pt0, pd1, pt1;
    {   // prefetch + stage chunk 0 (set 0)
        const float* dp = des + (size_t)(n0 + ld_r0) * 768 + 4 * ld_c4;
        const float* tp = twt + (size_t)(n0 + ld_r0) * 768 + 4 * ld_c4;
        pd0 = *(const float4*)(dp);
        pt0 = *(const float4*)(tp);
        pd1 = *(const float4*)(dp + 16 * 768);
        pt1 = *(const float4*)(tp + 16 * 768);
        uint2 h, l;
        __nv_bfloat16* s0 = sa;                 // set0 arr0
        __nv_bfloat16* s1 = sa + 2560;          // set0 arr1
        split4(pd0, h, l);
        *(uint2*)(s0 + ld_r0 * SS + 4 * ld_c4) = h;
        *(uint2*)(s0 + (32 + ld_r0) * SS + 4 * ld_c4) = l;
        split4(pd1, h, l);
        *(uint2*)(s0 + (ld_r0 + 16) * SS + 4 * ld_c4) = h;
        *(uint2*)(s0 + (48 + ld_r0) * SS + 4 * ld_c4) = l;
        split4(pt0, h, l);
        *(uint2*)(s1 + ld_r0 * SS + 4 * ld_c4) = h;
        *(uint2*)(s1 + (32 + ld_r0) * SS + 4 * ld_c4) = l;
        split4(pt1, h, l);
        *(uint2*)(s1 + (ld_r0 + 16) * SS + 4 * ld_c4) = h;
        *(uint2*)(s1 + (48 + ld_r0) * SS + 4 * ld_c4) = l;
    }
    __syncthreads();

    for (int ch = 0; ch < 24; ch++) {
        if (ch < 23) {
            const int kb2 = (ch + 1) * 32;
            const float* dp = des + (size_t)(n0 + ld_r0) * 768 + kb2 + 4 * ld_c4;
            const float* tp = twt + (size_t)(n0 + ld_r0) * 768 + kb2 + 4 * ld_c4;
            pd0 = *(const float4*)(dp);
            pt0 = *(const float4*)(tp);
            pd1 = *(const float4*)(dp + 16 * 768);
            pt1 = *(const float4*)(tp + 16 * 768);
        }
        {   // compute: A via ldmatrix, B via packed LDG.128
            const unsigned sb = cvta_s(sa) + (((ch & 1) * 2 + arr) * 2560) * 2;
#pragma unroll
            for (int ks = 0; ks < 2; ks++) {
                const int kb = ks * 16;
                uint4 ah[2], al[2];
#pragma unroll
                for (int m = 0; m < 2; m++) {
                    ldm_x4(ah[m], sb + ((m * 16 + row_l) * SS + kb + koff) * 2);
                    ldm_x4(al[m], sb + ((32 + m * 16 + row_l) * SS + kb + koff) * 2);
                }
#pragma unroll
                for (int nt = 0; nt < 2; nt++) {
                    const int col = arr * 32 + nb + nt * 8 + lr;
                    const uint4 b = *(const uint4*)(g_W1p +
                        ((size_t)(col * 48 + ch * 2 + ks) * 4 + (lane & 3)) * 8);
#pragma unroll
                    for (int m = 0; m < 2; m++) {
                        mma_bf16(c1[m][nt], ah[m], b.x, b.y);
                        mma_bf16(c1[m][nt], ah[m], b.z, b.w);
                        mma_bf16(c1[m][nt], al[m], b.x, b.y);
                    }
                }
            }
        }
        if (ch < 23) {   // stage ch+1 into the other set
            __nv_bfloat16* s0 = sa + (((ch + 1) & 1) * 2 + 0) * 2560;
            __nv_bfloat16* s1 = sa + (((ch + 1) & 1) * 2 + 1) * 2560;
            uint2 h, l;
            split4(pd0, h, l);
            *(uint2*)(s0 + ld_r0 * SS + 4 * ld_c4) = h;
            *(uint2*)(s0 + (32 + ld_r0) * SS + 4 * ld_c4) = l;
            split4(pd1, h, l);
            *(uint2*)(s0 + (ld_r0 + 16) * SS + 4 * ld_c4) = h;
            *(uint2*)(s0 + (48 + ld_r0) * SS + 4 * ld_c4) = l;
            split4(pt0, h, l);
            *(uint2*)(s1 + ld_r0 * SS + 4 * ld_c4) = h;
            *(uint2*)(s1 + (32 + ld_r0) * SS + 4 * ld_c4) = l;
            split4(pt1, h, l);
            *(uint2*)(s1 + (ld_r0 + 16) * SS + 4 * ld_c4) = h;
            *(uint2*)(s1 + (48 + ld_r0) * SS + 4 * ld_c4) = l;
        }
        __syncthreads();
    }

    // ---- stage-1 epilogue: bias + lrelu -> xb bf16 hi/lo [node][col] --------
#pragma unroll
    for (int m = 0; m < 2; m++)
#pragma unroll
        for (int nt = 0; nt < 2; nt++) {
            const int cb = arr * 32 + nb + nt * 8 + lq2;
            const float b0 = (cb < 32) ? bd[cb] : bt[cb - 32];
            const float b1 = (cb + 1 < 32) ? bd[cb + 1] : bt[cb - 31];
            const int r0 = m * 16 + lr;
            float v00 = lrelu01(c1[m][nt][0] + b0), v01 = lrelu01(c1[m][nt][1] + b1);
            float v10 = lrelu01(c1[m][nt][2] + b0), v11 = lrelu01(c1[m][nt][3] + b1);
            *(unsigned*)(xb + r0 * XS + cb)        = pack_bf2(v00, v01);
            *(unsigned*)(xb + (32 + r0) * XS + cb) = pack_bf2(v00 - __bfloat162float(__float2bfloat16(v00)),
                                                              v01 - __bfloat162float(__float2bfloat16(v01)));
            *(unsigned*)(xb + (r0 + 8) * XS + cb)  = pack_bf2(v10, v11);
            *(unsigned*)(xb + (40 + r0) * XS + cb) = pack_bf2(v10 - __bfloat162float(__float2bfloat16(v10)),
                                                              v11 - __bfloat162float(__float2bfloat16(v11)));
        }
    {   // num/cat cols 64-127
        const int col = tid >> 1, mh = (tid & 1) * 16;
        if (col < 32) {
            const float w0 = Wn[col * 5], w1 = Wn[col * 5 + 1], w2 = Wn[col * 5 + 2],
                        w3 = Wn[col * 5 + 3], w4 = Wn[col * 5 + 4];
            const float b = bn[col];
            for (int m = 0; m < 16; m++) {
                const float* r = npr + (size_t)(n0 + mh + m) * 5;
                const float v = lrelu01(r[0]*w0 + r[1]*w1 + r[2]*w2 + r[3]*w3 + r[4]*w4 + b);
                const __nv_bfloat16 h = __float2bfloat16(v);
                xb[(mh + m) * XS + 64 + col] = h;
                xb[(32 + mh + m) * XS + 64 + col] = __float2bfloat16(v - __bfloat162float(h));
            }
        } else {
            const int jj = col - 32;
            const float w0 = Wc[jj * 3], w1 = Wc[jj * 3 + 1], w2 = Wc[jj * 3 + 2];
            const float b = bc[jj];
            for (int m = 0; m < 16; m++) {
                const float* r = cpr + (size_t)(n0 + mh + m) * 3;
                const float v = lrelu01(r[0]*w0 + r[1]*w1 + r[2]*w2 + b);
                const __nv_bfloat16 h = __float2bfloat16(v);
                xb[(mh + m) * XS + 96 + jj] = h;
                xb[(32 + mh + m) * XS + 96 + jj] = __float2bfloat16(v - __bfloat162float(h));
            }
        }
    }
    __syncthreads();

    // ---- stage 2: x2 = lrelu(x @ Wi^T + bi) ---------------------------------
    {
        float c[2][4][4];
#pragma unroll
        for (int m = 0; m < 2; m++)
#pragma unroll
            for (int nt = 0; nt < 4; nt++)
#pragma unroll
                for (int q = 0; q < 4; q++) c[m][nt][q] = 0.f;
        mma_gemm128(xb, g_Wip, wid, lane, c);
#pragma unroll
        for (int m = 0; m < 2; m++)
#pragma unroll
            for (int nt = 0; nt < 4; nt++) {
                const int cb = wid * 32 + nt * 8 + lq2;
                const float b0 = bi[cb], b1 = bi[cb + 1];
                const int r0 = m * 16 + lr;
                float v00 = lrelu01(c[m][nt][0] + b0), v01 = lrelu01(c[m][nt][1] + b1);
                float v10 = lrelu01(c[m][nt][2] + b0), v11 = lrelu01(c[m][nt][3] + b1);
                *(unsigned*)(x2b + r0 * XS + cb)        = pack_bf2(v00, v01);
                *(unsigned*)(x2b + (32 + r0) * XS + cb) = pack_bf2(
                    v00 - __bfloat162float(__float2bfloat16(v00)),
                    v01 - __bfloat162float(__float2bfloat16(v01)));
                *(unsigned*)(x2b + (r0 + 8) * XS + cb)  = pack_bf2(v10, v11);
                *(unsigned*)(x2b + (40 + r0) * XS + cb) = pack_bf2(
                    v10 - __bfloat162float(__float2bfloat16(v10)),
                    v11 - __bfloat162float(__float2bfloat16(v11)));
            }
    }
    __syncthreads();

    // ---- stage 3: xw1 = x2 @ g1_W^T + per-head logits -----------------------
    {
        float c[2][4][4];
#pragma unroll
        for (int m = 0; m < 2; m++)
#pragma unroll
            for (int nt = 0; nt < 4; nt++)
#pragma unroll
                for (int q = 0; q < 4; q++) c[m][nt][q] = 0.f;
        mma_gemm128(x2b, g_g1p, wid, lane, c);

        float ps[2][2] = {{0,0},{0,0}}, pd[2][2] = {{0,0},{0,0}};
#pragma unroll
        for (int m = 0; m < 2; m++)
#pragma unroll
            for (int nt = 0; nt < 4; nt++) {
                const int cb = wid * 32 + nt * 8 + lq2;
                const int node = n0 + m * 16 + lr;
                *(float2*)(g_xw1 + (size_t)node * HID + cb) =
                    make_float2(c[m][nt][0], c[m][nt][1]);
                *(float2*)(g_xw1 + (size_t)(node + 8) * HID + cb) =
                    make_float2(c[m][nt][2], c[m][nt][3]);
                const float a0 = g1as[cb], a1 = g1as[cb + 1];
                const float d0 = g1ad[cb], d1 = g1ad[cb + 1];
                ps[m][0] += c[m][nt][0]*a0 + c[m][nt][1]*a1;
                ps[m][1] += c[m][nt][2]*a0 + c[m][nt][3]*a1;
                pd[m][0] += c[m][nt][0]*d0 + c[m][nt][1]*d1;
                pd[m][1] += c[m][nt][2]*d0 + c[m][nt][3]*d1;
            }
#pragma unroll
        for (int m = 0; m < 2; m++)
#pragma unroll
            for (int rr = 0; rr < 2; rr++) {
#pragma unroll
                for (int o = 1; o < 4; o <<= 1) {
                    ps[m][rr] += __shfl_xor_sync(0xffffffffu, ps[m][rr], o);
                    pd[m][rr] += __shfl_xor_sync(0xffffffffu, pd[m][rr], o);
                }
            }
        if ((lane & 3) == 0) {
#pragma unroll
            for (int m = 0; m < 2; m++) {
                const int node = n0 + m * 16 + lr;
                g_es1[node * 4 + wid] = ps[m][0];
                g_ed1[node * 4 + wid] = pd[m][0];
                g_es1[(node + 8) * 4 + wid] = ps[m][1];
                g_ed1[(node + 8) * 4 + wid] = pd[m][1];
            }
        }
    }
}

// ---------------- GAT1 aggregation: warp-per-dst gather, fused exp ------------
__global__ void __launch_bounds__(256) k_agg1(const float* __restrict__ g1b) {
    const int d = (blockIdx.x * blockDim.x + threadIdx.x) >> 5;
    const int lane = threadIdx.x & 31;
    if (d >= NN) return;
    const int beg = g_rs[d], end = g_rs[d + 1];
    const int h = lane >> 3;
    const float edv = g_ed1[d * 4 + h];
    float4 acc = {0.f, 0.f, 0.f, 0.f};
    float den = 0.f;
#pragma unroll 2
    for (int s = beg; s < end; s++) {
        const int src = __ldg(&g_csrc[s]);
        const float es = __ldg(&g_es1[src * 4 + h]);
        const float ev = __expf(lrelu2(es + edv));
        const float4 xs = *(const float4*)(g_xw1 + (size_t)src * HID + lane * 4);
        acc.x += xs.x * ev; acc.y += xs.y * ev;
        acc.z += xs.z * ev; acc.w += xs.w * ev;
        den += ev;
    }
    const float inv = 1.f / den;
    const float4 b = ((const float4*)g1b)[lane];
    float4 o;
    o.x = acc.x * inv + b.x; o.y = acc.y * inv + b.y;
    o.z = acc.z * inv + b.z; o.w = acc.w * inv + b.w;
    *(float4*)(g_out1 + (size_t)d * HID + lane * 4) = o;
}

// ---------------- GAT2 projection + attn logits -------------------------------
__global__ void __launch_bounds__(128) k_gat2_prep(
    const float* __restrict__ g2as, const float* __restrict__ g2ad)
{
    __shared__ __align__(16) __nv_bfloat16 ab[64 * XS];
    __shared__ float sp[2][4][NT];
    const int tid = threadIdx.x, n0 = blockIdx.x * NT;
    const int wid = tid >> 5, lane = tid & 31;
    const int lr = lane >> 2, lq2 = (lane & 3) * 2;

    for (int i = 0; i < 8; i++) {
        const int idx = tid + i * 128;          // 1024 float4
        const int node = idx >> 5, c4 = idx & 31;
        const float4 v = *(const float4*)(g_out1 + (size_t)(n0 + node) * HID + 4 * c4);
        uint2 h, l;
        split4(v, h, l);
        *(uint2*)(ab + node * XS + 4 * c4) = h;
        *(uint2*)(ab + (32 + node) * XS + 4 * c4) = l;
    }
    __syncthreads();

    float c[2][4][4];
#pragma unroll
    for (int m = 0; m < 2; m++)
#pragma unroll
        for (int nt = 0; nt < 4; nt++)
#pragma unroll
            for (int q = 0; q < 4; q++) c[m][nt][q] = 0.f;
    mma_gemm128(ab, g_g2p, wid, lane, c);

    float ps[2][2] = {{0,0},{0,0}}, pd[2][2] = {{0,0},{0,0}};
#pragma unroll
    for (int m = 0; m < 2; m++)
#pragma unroll
        for (int nt = 0; nt < 4; nt++) {
            const int cb = wid * 32 + nt * 8 + lq2;
            const int node = n0 + m * 16 + lr;
            *(float2*)(g_xw2 + (size_t)node * HID + cb) =
                make_float2(c[m][nt][0], c[m][nt][1]);
            *(float2*)(g_xw2 + (size_t)(node + 8) * HID + cb) =
                make_float2(c[m][nt][2], c[m][nt][3]);
            const float a0 = g2as[cb], a1 = g2as[cb + 1];
            const float d0 = g2ad[cb], d1 = g2ad[cb + 1];
            ps[m][0] += c[m][nt][0]*a0 + c[m][nt][1]*a1;
            ps[m][1] += c[m][nt][2]*a0 + c[m][nt][3]*a1;
            pd[m][0] += c[m][nt][0]*d0 + c[m][nt][1]*d1;
            pd[m][1] += c[m][nt][2]*d0 + c[m][nt][3]*d1;
        }
#pragma unroll
    for (int m = 0; m < 2; m++)
#pragma unroll
        for (int rr = 0; rr < 2; rr++) {
#pragma unroll
            for (int o = 1; o < 4; o <<= 1) {
                ps[m][rr] += __shfl_xor_sync(0xffffffffu, ps[m][rr], o);
                pd[m][rr] += __shfl_xor_sync(0xffffffffu, pd[m][rr], o);
            }
        }
    if ((lane & 3) == 0) {
#pragma unroll
        for (int m = 0; m < 2; m++) {
            sp[0][wid][m * 16 + lr]     = ps[m][0];
            sp[0][wid][m * 16 + lr + 8] = ps[m][1];
            sp[1][wid][m * 16 + lr]     = pd[m][0];
            sp[1][wid][m * 16 + lr + 8] = pd[m][1];
        }
    }
    __syncthreads();
    if (tid < 32) {
        g_es2[n0 + tid] = sp[0][0][tid] + sp[0][1][tid] + sp[0][2][tid] + sp[0][3][tid];
    } else if (tid < 64) {
        const int m = tid - 32;
        g_ed2[n0 + m] = sp[1][0][m] + sp[1][1][m] + sp[1][2][m] + sp[1][3][m];
    }
}

// ---------------- GAT2 aggregation --------------------------------------------
__global__ void __launch_bounds__(256) k_agg2(const float* __restrict__ g2b) {
    const int d = (blockIdx.x * blockDim.x + threadIdx.x) >> 5;
    const int lane = threadIdx.x & 31;
    if (d >= NN) return;
    const int beg = g_rs[d], end = g_rs[d + 1];
    const float edv = g_ed2[d];
    float4 acc = {0.f, 0.f, 0.f, 0.f};
    float den = 0.f;
#pragma unroll 2
    for (int s = beg; s < end; s++) {
        const int src = __ldg(&g_csrc[s]);
        const float es = __ldg(&g_es2[src]);
        const float ev = __expf(lrelu2(es + edv));
        const float4 xs = *(const float4*)(g_xw2 + (size_t)src * HID + lane * 4);
        acc.x += xs.x * ev; acc.y += xs.y * ev;
        acc.z += xs.z * ev; acc.w += xs.w * ev;
        den += ev;
    }
    const float inv = 1.f / den;
    const float4 b = ((const float4*)g2b)[lane];
    float4 o;
    o.x = acc.x * inv + b.x; o.y = acc.y * inv + b.y;
    o.z = acc.z * inv + b.z; o.w = acc.w * inv + b.w;
    *(float4*)(g_out2 + (size_t)d * HID + lane * 4) = o;
}

// ---------------- output head ------------------------------------------------
__global__ void __launch_bounds__(128) k_final(
    const float* __restrict__ bo1, const float* __restrict__ Wo2,
    const float* __restrict__ bo2, float* __restrict__ out)
{
    __shared__ __align__(16) __nv_bfloat16 ab[64 * XS];
    __shared__ float sp[2][4][NT];
    const int tid = threadIdx.x, n0 = blockIdx.x * NT;
    const int wid = tid >> 5, lane = tid & 31;
    const int lr = lane >> 2, lq2 = (lane & 3) * 2;

    for (int i = 0; i < 8; i++) {
        const int idx = tid + i * 128;
        const int node = idx >> 5, c4 = idx & 31;
        const float4 v = *(const float4*)(g_out2 + (size_t)(n0 + node) * HID + 4 * c4);
        uint2 h, l;
        split4(v, h, l);
        *(uint2*)(ab + node * XS + 4 * c4) = h;
        *(uint2*)(ab + (32 + node) * XS + 4 * c4) = l;
    }
    __syncthreads();

    float c[2][4][4];
#pragma unroll
    for (int m = 0; m < 2; m++)
#pragma unroll
        for (int nt = 0; nt < 4; nt++)
#pragma unroll
            for (int q = 0; q < 4; q++) c[m][nt][q] = 0.f;
    mma_gemm128(ab, g_Wo1p, wid, lane, c);

    float p0[2][2] = {{0,0},{0,0}}, p1[2][2] = {{0,0},{0,0}};
#pragma unroll
    for (int m = 0; m < 2; m++)
#pragma unroll
        for (int nt = 0; nt < 4; nt++) {
            const int cb = wid * 32 + nt * 8 + lq2;
            const float b0 = bo1[cb], b1 = bo1[cb + 1];
            const float w00 = Wo2[cb], w01 = Wo2[cb + 1];
            const float w10 = Wo2[128 + cb], w11 = Wo2[128 + cb + 1];
            const float y00 = lrelu01(c[m][nt][0] + b0), y01 = lrelu01(c[m][nt][1] + b1);
            const float y10 = lrelu01(c[m][nt][2] + b0), y11 = lrelu01(c[m][nt][3] + b1);
            p0[m][0] += y00*w00 + y01*w01;  p0[m][1] += y10*w00 + y11*w01;
            p1[m][0] += y00*w10 + y01*w11;  p1[m][1] += y10*w10 + y11*w11;
        }
#pragma unroll
    for (int m = 0; m < 2; m++)
#pragma unroll
        for (int rr = 0; rr < 2; rr++) {
#pragma unroll
            for (int o = 1; o < 4; o <<= 1) {
                p0[m][rr] += __shfl_xor_sync(0xffffffffu, p0[m][rr], o);
                p1[m][rr] += __shfl_xor_sync(0xffffffffu, p1[m][rr], o);
            }
        }
    if ((lane & 3) == 0) {
#pragma unroll
        for (int m = 0; m < 2; m++) {
            sp[0][wid][m * 16 + lr]     = p0[m][0];
            sp[0][wid][m * 16 + lr + 8] = p0[m][1];
            sp[1][wid][m * 16 + lr]     = p1[m][0];
            sp[1][wid][m * 16 + lr + 8] = p1[m][1];
        }
    }
    __syncthreads();
    if (tid < 32) {
        out[(size_t)(n0 + tid) * 2] =
            sp[0][0][tid] + sp[0][1][tid] + sp[0][2][tid] + sp[0][3][tid] + bo2[0];
    } else if (tid < 64) {
        const int m = tid - 32;
        out[(size_t)(n0 + m) * 2 + 1] =
            sp[1][0][m] + sp[1][1][m] + sp[1][2][m] + sp[1][3][m] + bo2[1];
    }
}

// ---------------- launch ------------------------------------------------------
extern "C" void kernel_launch(void* const* d_in, const int* in_sizes, int n_in,
                              void* d_out, int out_size) {
    const float* des  = (const float*)d_in[0];
    const float* twt  = (const float*)d_in[1];
    const float* npr  = (const float*)d_in[2];
    const float* cpr  = (const float*)d_in[3];
    const int*   ei   = (const int*)d_in[4];   // JAX x64 disabled -> int32
    const float* Wd = (const float*)d_in[5];   const float* bd = (const float*)d_in[6];
    const float* Wt = (const float*)d_in[7];   const float* bt = (const float*)d_in[8];
    const float* Wn = (const float*)d_in[9];   const float* bn = (const float*)d_in[10];
    const float* Wc = (const float*)d_in[11];  const float* bc = (const float*)d_in[12];
    const float* Wi = (const float*)d_in[13];  const float* bi = (const float*)d_in[14];
    const float* g1W  = (const float*)d_in[15];
    const float* g1as = (const float*)d_in[16];
    const float* g1ad = (const float*)d_in[17];
    const float* g1b  = (const float*)d_in[18];
    const float* g2W  = (const float*)d_in[19];
    const float* g2as = (const float*)d_in[20];
    const float* g2ad = (const float*)d_in[21];
    const float* g2b  = (const float*)d_in[22];
    const float* Wo1  = (const float*)d_in[23]; const float* bo1 = (const float*)d_in[24];
    const float* Wo2  = (const float*)d_in[25]; const float* bo2 = (const float*)d_in[26];
    float* out = (float*)d_out;

    const int WPN = 64 * 48 * 4 + 4 * 128 * 8 * 4;    // 28672
    k_wprep<<<(WPN + 255) / 256, 256>>>(Wd, Wt, Wi, g1W, g2W, Wo1);
    k_init_cnt<<<(NN + 255) / 256, 256>>>();
    k_count<<<(EE + 255) / 256, 256>>>(ei);
    k_features<<<NN / NT, 128>>>(des, twt, npr, cpr, bd, bt, Wn, bn, Wc, bc,
                                 bi, g1as, g1ad);          // ncu-captured slot
    k_scan<<<1, 1024>>>();
    k_fill<<<(ET + 255) / 256, 256>>>(ei);
    k_agg1<<<(NN * 32 + 255) / 256, 256>>>(g1b);
    k_gat2_prep<<<NN / NT, 128>>>(g2as, g2ad);
    k_agg2<<<(NN * 32 + 255) / 256, 256>>>(g2b);
    k_final<<<NN / NT, 128>>>(bo1, Wo2, bo2, out);
}

// round 10
// speedup vs baseline: 3.1147x; 1.2959x over previous
#include <cuda_runtime.h>
#include <cuda_bf16.h>

#define NN   100000
#define EE   1600000
#define ET   (EE + NN)
#define HID  128
#define NT   32                 // nodes per block
#define XS   136                // bf16 activation row stride (k=128 + pad)
#define SCB  100                // scan blocks
#define SCL  1000               // nodes per scan block

// ---------------- scratch globals --------------------------------------------
__device__ __align__(16) float g_xw1 [(size_t)NN * HID];
__device__ __align__(16) float g_es1 [NN * 4];
__device__ __align__(16) float g_ed1 [NN * 4];
__device__ __align__(16) float g_out1[(size_t)NN * HID];
__device__ __align__(16) float g_xw2 [(size_t)NN * HID];
__device__ __align__(16) float g_es2 [NN];
__device__ __align__(16) float g_ed2 [NN];
__device__ __align__(16) float g_out2[(size_t)NN * HID];

// fragment-packed weights: [col][kstep][quad] -> 16B {hi01,hi89,lo01,lo89}
__device__ __align__(16) __nv_bfloat16 g_W1p [64 * 48 * 4 * 8];   // stage1 (K=768)
__device__ __align__(16) __nv_bfloat16 g_Wip [128 * 8 * 4 * 8];
__device__ __align__(16) __nv_bfloat16 g_g1p [128 * 8 * 4 * 8];
__device__ __align__(16) __nv_bfloat16 g_g2p [128 * 8 * 4 * 8];
__device__ __align__(16) __nv_bfloat16 g_Wo1p[128 * 8 * 4 * 8];

// CSR (dst-grouped)
__device__ int g_cnt[NN];
__device__ int g_rs [NN + 1];
__device__ int g_cur[NN];
__device__ int g_csrc[ET];
__device__ int g_part[SCB];

__device__ __forceinline__ float lrelu01(float v) { return v > 0.f ? v : 0.01f * v; }
__device__ __forceinline__ float lrelu2 (float v) { return v > 0.f ? v : 0.2f  * v; }

__device__ __forceinline__ unsigned cvta_s(const void* p) {
    return (unsigned)__cvta_generic_to_shared(p);
}
__device__ __forceinline__ void ldm_x4(uint4& v, unsigned addr) {
    asm volatile("ldmatrix.sync.aligned.m8n8.x4.shared.b16 {%0,%1,%2,%3}, [%4];"
                 : "=r"(v.x), "=r"(v.y), "=r"(v.z), "=r"(v.w) : "r"(addr));
}
__device__ __forceinline__ void mma_bf16(float c[4], const uint4& a,
                                         unsigned b0, unsigned b1) {
    asm volatile(
        "mma.sync.aligned.m16n8k16.row.col.f32.bf16.bf16.f32 "
        "{%0,%1,%2,%3},{%4,%5,%6,%7},{%8,%9},{%0,%1,%2,%3};"
        : "+f"(c[0]), "+f"(c[1]), "+f"(c[2]), "+f"(c[3])
        : "r"(a.x), "r"(a.y), "r"(a.z), "r"(a.w), "r"(b0), "r"(b1));
}

// f32x2 -> bf16x2 hi + lo
__device__ __forceinline__ void cvt2(float2 v, unsigned& h, unsigned& l) {
    __nv_bfloat162 hb = __float22bfloat162_rn(v);
    h = *(unsigned*)&hb;
    const float2 hf = __bfloat1622float2(hb);
    __nv_bfloat162 lb = __float22bfloat162_rn(make_float2(v.x - hf.x, v.y - hf.y));
    l = *(unsigned*)&lb;
}
// f32x4 -> bf16 hi/lo packed pairs
__device__ __forceinline__ void split4(float4 v, uint2& h, uint2& l) {
    cvt2(make_float2(v.x, v.y), h.x, l.x);
    cvt2(make_float2(v.z, v.w), h.y, l.y);
}
__device__ __forceinline__ unsigned pack_bf2(float a, float b) {
    __nv_bfloat162 t = __halves2bfloat162(__float2bfloat16(a), __float2bfloat16(b));
    return *(unsigned*)&t;
}

// shared 3-term bf16 GEMM: 32 nodes x 32 cols (per warp) x K=128
// abuf: bf16 [64][XS], hi rows 0-31, lo rows 32-63. wp: fragment-packed weights.
__device__ __forceinline__ void mma_gemm128(const __nv_bfloat16* abuf,
                                            const __nv_bfloat16* __restrict__ wp,
                                            int wid, int lane, float c[2][4][4]) {
    const int row_l = (lane & 7) + ((lane >> 3) & 1) * 8;
    const int koff  = (lane >> 4) * 8;
    const int nrow  = lane >> 2, q = lane & 3;
    const unsigned sb = cvta_s(abuf);
#pragma unroll
    for (int ks = 0; ks < 8; ks++) {
        uint4 ah[2], al[2];
#pragma unroll
        for (int m = 0; m < 2; m++) {
            ldm_x4(ah[m], sb + ((m * 16 + row_l) * XS + ks * 16 + koff) * 2);
            ldm_x4(al[m], sb + ((32 + m * 16 + row_l) * XS + ks * 16 + koff) * 2);
        }
#pragma unroll
        for (int nt = 0; nt < 4; nt++) {
            const int col = wid * 32 + nt * 8 + nrow;
            const uint4 b = *(const uint4*)(wp + ((size_t)(col * 8 + ks) * 4 + q) * 8);
#pragma unroll
            for (int m = 0; m < 2; m++) {
                mma_bf16(c[m][nt], ah[m], b.x, b.y);
                mma_bf16(c[m][nt], ah[m], b.z, b.w);
                mma_bf16(c[m][nt], al[m], b.x, b.y);
            }
        }
    }
}

// ---------------- weight prep (once per launch) -------------------------------
__device__ __forceinline__ uint4 pack_frag(float v0, float v1, float v2, float v3) {
    uint4 r; uint2 h, l;
    cvt2(make_float2(v0, v1), h.x, l.x);
    cvt2(make_float2(v2, v3), h.y, l.y);
    r.x = h.x; r.y = h.y; r.z = l.x; r.w = l.y;
    return r;
}

__global__ void k_wprep(const float* __restrict__ Wd, const float* __restrict__ Wt,
                        const float* __restrict__ Wi, const float* __restrict__ g1W,
                        const float* __restrict__ g2W, const float* __restrict__ Wo1) {
    const int i = blockIdx.x * blockDim.x + threadIdx.x;
    if (i < 64 * 48 * 4) {
        const int col = i / 192, ks = (i % 192) / 4, q = i % 4;
        const int k0 = ks * 16 + q * 2;
        const float* src = (col < 32) ? Wd + (size_t)col * 768
                                      : Wt + (size_t)(col - 32) * 768;
        *(uint4*)(g_W1p + (size_t)i * 8) =
            pack_frag(src[k0], src[k0 + 1], src[k0 + 8], src[k0 + 9]);
    } else if (i < 64 * 48 * 4 + 4 * 128 * 8 * 4) {
        const int j = i - 64 * 48 * 4;
        const int mat = j >> 12, r = j & 4095;
        const int col = r / 32, ks = (r % 32) / 4, q = r % 4;
        const int k0 = ks * 16 + q * 2;
        const float* W = (mat == 0 ? Wi : mat == 1 ? g1W : mat == 2 ? g2W : Wo1)
                       + (size_t)col * 128;
        __nv_bfloat16* dst = (mat == 0 ? g_Wip : mat == 1 ? g_g1p
                              : mat == 2 ? g_g2p : g_Wo1p);
        *(uint4*)(dst + (size_t)r * 8) =
            pack_frag(W[k0], W[k0 + 1], W[k0 + 8], W[k0 + 9]);
    }
}

// ---------------- CSR build ---------------------------------------------------
__global__ void k_init_cnt() {
    int i = blockIdx.x * blockDim.x + threadIdx.x;
    if (i < NN) g_cnt[i] = 1;
}
__global__ void k_count(const int* __restrict__ ei) {
    int i = blockIdx.x * blockDim.x + threadIdx.x;
    if (i < EE) atomicAdd(&g_cnt[ei[EE + i]], 1);
}
__global__ void k_scan1() {           // grid SCB, 256 thr: block partial sums
    __shared__ int sh[256];
    const int b = blockIdx.x, t = threadIdx.x;
    const int base = b * SCL;
    int s = 0;
    for (int i = t; i < SCL; i += 256) s += g_cnt[base + i];
    sh[t] = s;
    __syncthreads();
    for (int o = 128; o > 0; o >>= 1) {
        if (t < o) sh[t] += sh[t + o];
        __syncthreads();
    }
    if (t == 0) g_part[b] = sh[0];
}
__global__ void k_scan2() {           // 1 block: exclusive scan of partials
    if (threadIdx.x == 0) {
        int acc = 0;
        for (int i = 0; i < SCB; i++) { int v = g_part[i]; g_part[i] = acc; acc += v; }
        g_rs[NN] = ET;
    }
}
__global__ void k_scan3() {           // grid SCB: per-block exclusive scan + write
    __shared__ int sh[256];
    const int b = blockIdx.x, t = threadIdx.x;
    const int base = b * SCL;
    int loc[4];
    int s = 0;
#pragma unroll
    for (int j = 0; j < 4; j++) {
        const int idx = t * 4 + j;
        loc[j] = (idx < SCL) ? g_cnt[base + idx] : 0;
        s += loc[j];
    }
    sh[t] = s;
    __syncthreads();
    for (int o = 1; o < 256; o <<= 1) {
        int v = (t >= o) ? sh[t - o] : 0;
        __syncthreads();
        sh[t] += v;
        __syncthreads();
    }
    int pre = g_part[b] + (t ? sh[t - 1] : 0);
#pragma unroll
    for (int j = 0; j < 4; j++) {
        const int idx = t * 4 + j;
        if (idx < SCL) {
            g_rs[base + idx] = pre;
            g_cur[base + idx] = pre;
            pre += loc[j];
        }
    }
}
__global__ void k_fill(const int* __restrict__ ei) {
    int i = blockIdx.x * blockDim.x + threadIdx.x;
    if (i >= ET) return;
    int src, dst;
    if (i < EE) { src = ei[i]; dst = ei[EE + i]; }
    else        { src = dst = i - EE; }
    g_csrc[atomicAdd(&g_cur[dst], 1)] = src;
}

// ---------------- features -> x -> Wi -> g1 projection + attn logits ---------
__global__ void __launch_bounds__(128) k_features(
    const float* __restrict__ des, const float* __restrict__ twt,
    const float* __restrict__ npr, const float* __restrict__ cpr,
    const float* __restrict__ bd,  const float* __restrict__ bt,
    const float* __restrict__ Wn,  const float* __restrict__ bn,
    const float* __restrict__ Wc,  const float* __restrict__ bc,
    const float* __restrict__ bi,
    const float* __restrict__ g1as, const float* __restrict__ g1ad)
{
    __shared__ __align__(16) __nv_bfloat16 xb [64 * XS];
    __shared__ __align__(16) __nv_bfloat16 x2b[64 * XS];

    const int tid = threadIdx.x;
    const int n0  = blockIdx.x * NT;
    const int wid = tid >> 5, lane = tid & 31;
    const int lr = lane >> 2, lq = lane & 3, lq2 = lq * 2;

    // ---- stage 1: direct register fragments from global ---------------------
    // warp = (m-tile, array); each input element loaded exactly once per block
    const int mt  = wid >> 1;            // nodes mt*16 .. mt*16+15
    const int arr = wid & 1;             // 0: des, 1: twt

    float c1[4][4];
#pragma unroll
    for (int nt = 0; nt < 4; nt++)
#pragma unroll
        for (int q = 0; q < 4; q++) c1[nt][q] = 0.f;

    {
        const float* Abase = (arr ? twt : des)
                           + (size_t)(n0 + mt * 16 + lr) * 768 + lq2;
#pragma unroll 2
        for (int ks = 0; ks < 48; ks++) {
            const int kk = ks * 16;
            const float2 v0 = *(const float2*)(Abase + kk);
            const float2 v1 = *(const float2*)(Abase + 8 * 768 + kk);
            const float2 v2 = *(const float2*)(Abase + kk + 8);
            const float2 v3 = *(const float2*)(Abase + 8 * 768 + kk + 8);
            uint4 ah, al;
            cvt2(v0, ah.x, al.x);
            cvt2(v1, ah.y, al.y);
            cvt2(v2, ah.z, al.z);
            cvt2(v3, ah.w, al.w);
#pragma unroll
            for (int nt = 0; nt < 4; nt++) {
                const int col = arr * 32 + nt * 8 + lr;
                const uint4 b = *(const uint4*)(g_W1p +
                    ((size_t)(col * 48 + ks) * 4 + lq) * 8);
                mma_bf16(c1[nt], ah, b.x, b.y);
                mma_bf16(c1[nt], ah, b.z, b.w);
                mma_bf16(c1[nt], al, b.x, b.y);
            }
        }
    }

    // ---- stage-1 epilogue: bias + lrelu -> xb bf16 hi/lo [node][col] --------
#pragma unroll
    for (int nt = 0; nt < 4; nt++) {
        const int cb = arr * 32 + nt * 8 + lq2;
        const float b0 = (cb < 32) ? bd[cb] : bt[cb - 32];
        const float b1 = (cb + 1 < 32) ? bd[cb + 1] : bt[cb - 31];
        const int r0 = mt * 16 + lr;
        const float v00 = lrelu01(c1[nt][0] + b0), v01 = lrelu01(c1[nt][1] + b1);
        const float v10 = lrelu01(c1[nt][2] + b0), v11 = lrelu01(c1[nt][3] + b1);
        *(unsigned*)(xb + r0 * XS + cb)        = pack_bf2(v00, v01);
        *(unsigned*)(xb + (32 + r0) * XS + cb) = pack_bf2(
            v00 - __bfloat162float(__float2bfloat16(v00)),
            v01 - __bfloat162float(__float2bfloat16(v01)));
        *(unsigned*)(xb + (r0 + 8) * XS + cb)  = pack_bf2(v10, v11);
        *(unsigned*)(xb + (40 + r0) * XS + cb) = pack_bf2(
            v10 - __bfloat162float(__float2bfloat16(v10)),
            v11 - __bfloat162float(__float2bfloat16(v11)));
    }
    {   // num/cat cols 64-127
        const int col = tid >> 1, mh = (tid & 1) * 16;
        if (col < 32) {
            const float w0 = Wn[col * 5], w1 = Wn[col * 5 + 1], w2 = Wn[col * 5 + 2],
                        w3 = Wn[col * 5 + 3], w4 = Wn[col * 5 + 4];
            const float b = bn[col];
            for (int m = 0; m < 16; m++) {
                const float* r = npr + (size_t)(n0 + mh + m) * 5;
                const float v = lrelu01(r[0]*w0 + r[1]*w1 + r[2]*w2 + r[3]*w3 + r[4]*w4 + b);
                const __nv_bfloat16 h = __float2bfloat16(v);
                xb[(mh + m) * XS + 64 + col] = h;
                xb[(32 + mh + m) * XS + 64 + col] = __float2bfloat16(v - __bfloat162float(h));
            }
        } else {
            const int jj = col - 32;
            const float w0 = Wc[jj * 3], w1 = Wc[jj * 3 + 1], w2 = Wc[jj * 3 + 2];
            const float b = bc[jj];
            for (int m = 0; m < 16; m++) {
                const float* r = cpr + (size_t)(n0 + mh + m) * 3;
                const float v = lrelu01(r[0]*w0 + r[1]*w1 + r[2]*w2 + b);
                const __nv_bfloat16 h = __float2bfloat16(v);
                xb[(mh + m) * XS + 96 + jj] = h;
                xb[(32 + mh + m) * XS + 96 + jj] = __float2bfloat16(v - __bfloat162float(h));
            }
        }
    }
    __syncthreads();

    // ---- stage 2: x2 = lrelu(x @ Wi^T + bi) ---------------------------------
    {
        float c[2][4][4];
#pragma unroll
        for (int m = 0; m < 2; m++)
#pragma unroll
            for (int nt = 0; nt < 4; nt++)
#pragma unroll
                for (int q = 0; q < 4; q++) c[m][nt][q] = 0.f;
        mma_gemm128(xb, g_Wip, wid, lane, c);
#pragma unroll
        for (int m = 0; m < 2; m++)
#pragma unroll
            for (int nt = 0; nt < 4; nt++) {
                const int cb = wid * 32 + nt * 8 + lq2;
                const float b0 = bi[cb], b1 = bi[cb + 1];
                const int r0 = m * 16 + lr;
                const float v00 = lrelu01(c[m][nt][0] + b0), v01 = lrelu01(c[m][nt][1] + b1);
                const float v10 = lrelu01(c[m][nt][2] + b0), v11 = lrelu01(c[m][nt][3] + b1);
                *(unsigned*)(x2b + r0 * XS + cb)        = pack_bf2(v00, v01);
                *(unsigned*)(x2b + (32 + r0) * XS + cb) = pack_bf2(
                    v00 - __bfloat162float(__float2bfloat16(v00)),
                    v01 - __bfloat162float(__float2bfloat16(v01)));
                *(unsigned*)(x2b + (r0 + 8) * XS + cb)  = pack_bf2(v10, v11);
                *(unsigned*)(x2b + (40 + r0) * XS + cb) = pack_bf2(
                    v10 - __bfloat162float(__float2bfloat16(v10)),
                    v11 - __bfloat162float(__float2bfloat16(v11)));
            }
    }
    __syncthreads();

    // ---- stage 3: xw1 = x2 @ g1_W^T + per-head logits -----------------------
    {
        float c[2][4][4];
#pragma unroll
        for (int m = 0; m < 2; m++)
#pragma unroll
            for (int nt = 0; nt < 4; nt++)
#pragma unroll
                for (int q = 0; q < 4; q++) c[m][nt][q] = 0.f;
        mma_gemm128(x2b, g_g1p, wid, lane, c);

        float ps[2][2] = {{0,0},{0,0}}, pd[2][2] = {{0,0},{0,0}};
#pragma unroll
        for (int m = 0; m < 2; m++)
#pragma unroll
            for (int nt = 0; nt < 4; nt++) {
                const int cb = wid * 32 + nt * 8 + lq2;
                const int node = n0 + m * 16 + lr;
                *(float2*)(g_xw1 + (size_t)node * HID + cb) =
                    make_float2(c[m][nt][0], c[m][nt][1]);
                *(float2*)(g_xw1 + (size_t)(node + 8) * HID + cb) =
                    make_float2(c[m][nt][2], c[m][nt][3]);
                const float a0 = g1as[cb], a1 = g1as[cb + 1];
                const float d0 = g1ad[cb], d1 = g1ad[cb + 1];
                ps[m][0] += c[m][nt][0]*a0 + c[m][nt][1]*a1;
                ps[m][1] += c[m][nt][2]*a0 + c[m][nt][3]*a1;
                pd[m][0] += c[m][nt][0]*d0 + c[m][nt][1]*d1;
                pd[m][1] += c[m][nt][2]*d0 + c[m][nt][3]*d1;
            }
#pragma unroll
        for (int m = 0; m < 2; m++)
#pragma unroll
            for (int rr = 0; rr < 2; rr++) {
#pragma unroll
                for (int o = 1; o < 4; o <<= 1) {
                    ps[m][rr] += __shfl_xor_sync(0xffffffffu, ps[m][rr], o);
                    pd[m][rr] += __shfl_xor_sync(0xffffffffu, pd[m][rr], o);
                }
            }
        if ((lane & 3) == 0) {
#pragma unroll
            for (int m = 0; m < 2; m++) {
                const int node = n0 + m * 16 + lr;
                g_es1[node * 4 + wid] = ps[m][0];
                g_ed1[node * 4 + wid] = pd[m][0];
                g_es1[(node + 8) * 4 + wid] = ps[m][1];
                g_ed1[(node + 8) * 4 + wid] = pd[m][1];
            }
        }
    }
}

// ---------------- GAT1 aggregation: warp-per-dst gather, fused exp ------------
__global__ void __launch_bounds__(256) k_agg1(const float* __restrict__ g1b) {
    const int d = (blockIdx.x * blockDim.x + threadIdx.x) >> 5;
    const int lane = threadIdx.x & 31;
    if (d >= NN) return;
    const int beg = g_rs[d], end = g_rs[d + 1];
    const int h = lane >> 3;
    const float edv = g_ed1[d * 4 + h];
    float4 acc = {0.f, 0.f, 0.f, 0.f};
    float den = 0.f;
#pragma unroll 2
    for (int s = beg; s < end; s++) {
        const int src = __ldg(&g_csrc[s]);
        const float es = __ldg(&g_es1[src * 4 + h]);
        const float ev = __expf(lrelu2(es + edv));
        const float4 xs = *(const float4*)(g_xw1 + (size_t)src * HID + lane * 4);
        acc.x += xs.x * ev; acc.y += xs.y * ev;
        acc.z += xs.z * ev; acc.w += xs.w * ev;
        den += ev;
    }
    const float inv = 1.f / den;
    const float4 b = ((const float4*)g1b)[lane];
    float4 o;
    o.x = acc.x * inv + b.x; o.y = acc.y * inv + b.y;
    o.z = acc.z * inv + b.z; o.w = acc.w * inv + b.w;
    *(float4*)(g_out1 + (size_t)d * HID + lane * 4) = o;
}

// ---------------- GAT2 projection + attn logits -------------------------------
__global__ void __launch_bounds__(128) k_gat2_prep(
    const float* __restrict__ g2as, const float* __restrict__ g2ad)
{
    __shared__ __align__(16) __nv_bfloat16 ab[64 * XS];
    __shared__ float sp[2][4][NT];
    const int tid = threadIdx.x, n0 = blockIdx.x * NT;
    const int wid = tid >> 5, lane = tid & 31;
    const int lr = lane >> 2, lq2 = (lane & 3) * 2;

    for (int i = 0; i < 8; i++) {
        const int idx = tid + i * 128;          // 1024 float4
        const int node = idx >> 5, c4 = idx & 31;
        const float4 v = *(const float4*)(g_out1 + (size_t)(n0 + node) * HID + 4 * c4);
        uint2 h, l;
        split4(v, h, l);
        *(uint2*)(ab + node * XS + 4 * c4) = h;
        *(uint2*)(ab + (32 + node) * XS + 4 * c4) = l;
    }
    __syncthreads();

    float c[2][4][4];
#pragma unroll
    for (int m = 0; m < 2; m++)
#pragma unroll
        for (int nt = 0; nt < 4; nt++)
#pragma unroll
            for (int q = 0; q < 4; q++) c[m][nt][q] = 0.f;
    mma_gemm128(ab, g_g2p, wid, lane, c);

    float ps[2][2] = {{0,0},{0,0}}, pd[2][2] = {{0,0},{0,0}};
#pragma unroll
    for (int m = 0; m < 2; m++)
#pragma unroll
        for (int nt = 0; nt < 4; nt++) {
            const int cb = wid * 32 + nt * 8 + lq2;
            const int node = n0 + m * 16 + lr;
            *(float2*)(g_xw2 + (size_t)node * HID + cb) =
                make_float2(c[m][nt][0], c[m][nt][1]);
            *(float2*)(g_xw2 + (size_t)(node + 8) * HID + cb) =
                make_float2(c[m][nt][2], c[m][nt][3]);
            const float a0 = g2as[cb], a1 = g2as[cb + 1];
            const float d0 = g2ad[cb], d1 = g2ad[cb + 1];
            ps[m][0] += c[m][nt][0]*a0 + c[m][nt][1]*a1;
            ps[m][1] += c[m][nt][2]*a0 + c[m][nt][3]*a1;
            pd[m][0] += c[m][nt][0]*d0 + c[m][nt][1]*d1;
            pd[m][1] += c[m][nt][2]*d0 + c[m][nt][3]*d1;
        }
#pragma unroll
    for (int m = 0; m < 2; m++)
#pragma unroll
        for (int rr = 0; rr < 2; rr++) {
#pragma unroll
            for (int o = 1; o < 4; o <<= 1) {
                ps[m][rr] += __shfl_xor_sync(0xffffffffu, ps[m][rr], o);
                pd[m][rr] += __shfl_xor_sync(0xffffffffu, pd[m][rr], o);
            }
        }
    if ((lane & 3) == 0) {
#pragma unroll
        for (int m = 0; m < 2; m++) {
            sp[0][wid][m * 16 + lr]     = ps[m][0];
            sp[0][wid][m * 16 + lr + 8] = ps[m][1];
            sp[1][wid][m * 16 + lr]     = pd[m][0];
            sp[1][wid][m * 16 + lr + 8] = pd[m][1];
        }
    }
    __syncthreads();
    if (tid < 32) {
        g_es2[n0 + tid] = sp[0][0][tid] + sp[0][1][tid] + sp[0][2][tid] + sp[0][3][tid];
    } else if (tid < 64) {
        const int m = tid - 32;
        g_ed2[n0 + m] = sp[1][0][m] + sp[1][1][m] + sp[1][2][m] + sp[1][3][m];
    }
}

// ---------------- GAT2 aggregation --------------------------------------------
__global__ void __launch_bounds__(256) k_agg2(const float* __restrict__ g2b) {
    const int d = (blockIdx.x * blockDim.x + threadIdx.x) >> 5;
    const int lane = threadIdx.x & 31;
    if (d >= NN) return;
    const int beg = g_rs[d], end = g_rs[d + 1];
    const float edv = g_ed2[d];
    float4 acc = {0.f, 0.f, 0.f, 0.f};
    float den = 0.f;
#pragma unroll 2
    for (int s = beg; s < end; s++) {
        const int src = __ldg(&g_csrc[s]);
        const float es = __ldg(&g_es2[src]);
        const float ev = __expf(lrelu2(es + edv));
        const float4 xs = *(const float4*)(g_xw2 + (size_t)src * HID + lane * 4);
        acc.x += xs.x * ev; acc.y += xs.y * ev;
        acc.z += xs.z * ev; acc.w += xs.w * ev;
        den += ev;
    }
    const float inv = 1.f / den;
    const float4 b = ((const float4*)g2b)[lane];
    float4 o;
    o.x = acc.x * inv + b.x; o.y = acc.y * inv + b.y;
    o.z = acc.z * inv + b.z; o.w = acc.w * inv + b.w;
    *(float4*)(g_out2 + (size_t)d * HID + lane * 4) = o;
}

// ---------------- output head ------------------------------------------------
__global__ void __launch_bounds__(128) k_final(
    const float* __restrict__ bo1, const float* __restrict__ Wo2,
    const float* __restrict__ bo2, float* __restrict__ out)
{
    __shared__ __align__(16) __nv_bfloat16 ab[64 * XS];
    __shared__ float sp[2][4][NT];
    const int tid = threadIdx.x, n0 = blockIdx.x * NT;
    const int wid = tid >> 5, lane = tid & 31;
    const int lr = lane >> 2, lq2 = (lane & 3) * 2;

    for (int i = 0; i < 8; i++) {
        const int idx = tid + i * 128;
        const int node = idx >> 5, c4 = idx & 31;
        const float4 v = *(const float4*)(g_out2 + (size_t)(n0 + node) * HID + 4 * c4);
        uint2 h, l;
        split4(v, h, l);
        *(uint2*)(ab + node * XS + 4 * c4) = h;
        *(uint2*)(ab + (32 + node) * XS + 4 * c4) = l;
    }
    __syncthreads();

    float c[2][4][4];
#pragma unroll
    for (int m = 0; m < 2; m++)
#pragma unroll
        for (int nt = 0; nt < 4; nt++)
#pragma unroll
            for (int q = 0; q < 4; q++) c[m][nt][q] = 0.f;
    mma_gemm128(ab, g_Wo1p, wid, lane, c);

    float p0[2][2] = {{0,0},{0,0}}, p1[2][2] = {{0,0},{0,0}};
#pragma unroll
    for (int m = 0; m < 2; m++)
#pragma unroll
        for (int nt = 0; nt < 4; nt++) {
            const int cb = wid * 32 + nt * 8 + lq2;
            const float b0 = bo1[cb], b1 = bo1[cb + 1];
            const float w00 = Wo2[cb], w01 = Wo2[cb + 1];
            const float w10 = Wo2[128 + cb], w11 = Wo2[128 + cb + 1];
            const float y00 = lrelu01(c[m][nt][0] + b0), y01 = lrelu01(c[m][nt][1] + b1);
            const float y10 = lrelu01(c[m][nt][2] + b0), y11 = lrelu01(c[m][nt][3] + b1);
            p0[m][0] += y00*w00 + y01*w01;  p0[m][1] += y10*w00 + y11*w01;
            p1[m][0] += y00*w10 + y01*w11;  p1[m][1] += y10*w10 + y11*w11;
        }
#pragma unroll
    for (int m = 0; m < 2; m++)
#pragma unroll
        for (int rr = 0; rr < 2; rr++) {
#pragma unroll
            for (int o = 1; o < 4; o <<= 1) {
                p0[m][rr] += __shfl_xor_sync(0xffffffffu, p0[m][rr], o);
                p1[m][rr] += __shfl_xor_sync(0xffffffffu, p1[m][rr], o);
            }
        }
    if ((lane & 3) == 0) {
#pragma unroll
        for (int m = 0; m < 2; m++) {
            sp[0][wid][m * 16 + lr]     = p0[m][0];
            sp[0][wid][m * 16 + lr + 8] = p0[m][1];
            sp[1][wid][m * 16 + lr]     = p1[m][0];
            sp[1][wid][m * 16 + lr + 8] = p1[m][1];
        }
    }
    __syncthreads();
    if (tid < 32) {
        out[(size_t)(n0 + tid) * 2] =
            sp[0][0][tid] + sp[0][1][tid] + sp[0][2][tid] + sp[0][3][tid] + bo2[0];
    } else if (tid < 64) {
        const int m = tid - 32;
        out[(size_t)(n0 + m) * 2 + 1] =
            sp[1][0][m] + sp[1][1][m] + sp[1][2][m] + sp[1][3][m] + bo2[1];
    }
}

// ---------------- launch ------------------------------------------------------
extern "C" void kernel_launch(void* const* d_in, const int* in_sizes, int n_in,
                              void* d_out, int out_size) {
    const float* des  = (const float*)d_in[0];
    const float* twt  = (const float*)d_in[1];
    const float* npr  = (const float*)d_in[2];
    const float* cpr  = (const float*)d_in[3];
    const int*   ei   = (const int*)d_in[4];   // JAX x64 disabled -> int32
    const float* Wd = (const float*)d_in[5];   const float* bd = (const float*)d_in[6];
    const float* Wt = (const float*)d_in[7];   const float* bt = (const float*)d_in[8];
    const float* Wn = (const float*)d_in[9];   const float* bn = (const float*)d_in[10];
    const float* Wc = (const float*)d_in[11];  const float* bc = (const float*)d_in[12];
    const float* Wi = (const float*)d_in[13];  const float* bi = (const float*)d_in[14];
    const float* g1W  = (const float*)d_in[15];
    const float* g1as = (const float*)d_in[16];
    const float* g1ad = (const float*)d_in[17];
    const float* g1b  = (const float*)d_in[18];
    const float* g2W  = (const float*)d_in[19];
    const float* g2as = (const float*)d_in[20];
    const float* g2ad = (const float*)d_in[21];
    const float* g2b  = (const float*)d_in[22];
    const float* Wo1  = (const float*)d_in[23]; const float* bo1 = (const float*)d_in[24];
    const float* Wo2  = (const float*)d_in[25]; const float* bo2 = (const float*)d_in[26];
    float* out = (float*)d_out;

    const int WPN = 64 * 48 * 4 + 4 * 128 * 8 * 4;    // 28672
    k_wprep<<<(WPN + 255) / 256, 256>>>(Wd, Wt, Wi, g1W, g2W, Wo1);
    k_init_cnt<<<(NN + 255) / 256, 256>>>();
    k_count<<<(EE + 255) / 256, 256>>>(ei);
    k_features<<<NN / NT, 128>>>(des, twt, npr, cpr, bd, bt, Wn, bn, Wc, bc,
                                 bi, g1as, g1ad);          // ncu-captured slot (idx 3)
    k_scan1<<<SCB, 256>>>();
    k_scan2<<<1, 32>>>();
    k_scan3<<<SCB, 256>>>();
    k_fill<<<(ET + 255) / 256, 256>>>(ei);
    k_agg1<<<(NN * 32 + 255) / 256, 256>>>(g1b);
    k_gat2_prep<<<NN / NT, 128>>>(g2as, g2ad);
    k_agg2<<<(NN * 32 + 255) / 256, 256>>>(g2b);
    k_final<<<NN / NT, 128>>>(bo1, Wo2, bo2, out);
}

// round 11
// speedup vs baseline: 3.3194x; 1.0657x over previous
#include <cuda_runtime.h>
#include <cuda_bf16.h>

#define NN   100000
#define EE   1600000
#define ET   (EE + NN)
#define HID  128
#define NT   64                 // nodes per block (node kernels)
#define XS   136                // bf16 activation row stride (k=128 + pad)
#define SCB  100                // scan blocks
#define SCL  1000               // nodes per scan block

// ---------------- scratch globals --------------------------------------------
__device__ __align__(16) float g_xw1 [(size_t)NN * HID];
__device__ __align__(16) float g_es1 [NN * 4];
__device__ __align__(16) float g_ed1 [NN * 4];
__device__ __align__(16) float g_out1[(size_t)NN * HID];
__device__ __align__(16) float g_xw2 [(size_t)NN * HID];
__device__ __align__(16) float g_es2 [NN];
__device__ __align__(16) float g_ed2 [NN];
__device__ __align__(16) float g_out2[(size_t)NN * HID];

// fragment-packed weights: [col][kstep][quad] -> 16B {hi01,hi89,lo01,lo89}
__device__ __align__(16) __nv_bfloat16 g_W1p [64 * 48 * 4 * 8];   // stage1 (K=768)
__device__ __align__(16) __nv_bfloat16 g_Wip [128 * 8 * 4 * 8];
__device__ __align__(16) __nv_bfloat16 g_g1p [128 * 8 * 4 * 8];
__device__ __align__(16) __nv_bfloat16 g_g2p [128 * 8 * 4 * 8];
__device__ __align__(16) __nv_bfloat16 g_Wo1p[128 * 8 * 4 * 8];

// CSR (dst-grouped)
__device__ int g_cnt[NN];
__device__ int g_rs [NN + 1];
__device__ int g_cur[NN];
__device__ int g_csrc[ET];
__device__ int g_part[SCB];

__device__ __forceinline__ float lrelu01(float v) { return v > 0.f ? v : 0.01f * v; }
__device__ __forceinline__ float lrelu2 (float v) { return v > 0.f ? v : 0.2f  * v; }

__device__ __forceinline__ unsigned cvta_s(const void* p) {
    return (unsigned)__cvta_generic_to_shared(p);
}
__device__ __forceinline__ void ldm_x4(uint4& v, unsigned addr) {
    asm volatile("ldmatrix.sync.aligned.m8n8.x4.shared.b16 {%0,%1,%2,%3}, [%4];"
                 : "=r"(v.x), "=r"(v.y), "=r"(v.z), "=r"(v.w) : "r"(addr));
}
__device__ __forceinline__ void mma_bf16(float c[4], const uint4& a,
                                         unsigned b0, unsigned b1) {
    asm volatile(
        "mma.sync.aligned.m16n8k16.row.col.f32.bf16.bf16.f32 "
        "{%0,%1,%2,%3},{%4,%5,%6,%7},{%8,%9},{%0,%1,%2,%3};"
        : "+f"(c[0]), "+f"(c[1]), "+f"(c[2]), "+f"(c[3])
        : "r"(a.x), "r"(a.y), "r"(a.z), "r"(a.w), "r"(b0), "r"(b1));
}

// f32x2 -> bf16x2 hi + lo
__device__ __forceinline__ void cvt2(float2 v, unsigned& h, unsigned& l) {
    __nv_bfloat162 hb = __float22bfloat162_rn(v);
    h = *(unsigned*)&hb;
    const float2 hf = __bfloat1622float2(hb);
    __nv_bfloat162 lb = __float22bfloat162_rn(make_float2(v.x - hf.x, v.y - hf.y));
    l = *(unsigned*)&lb;
}
__device__ __forceinline__ void split4(float4 v, uint2& h, uint2& l) {
    cvt2(make_float2(v.x, v.y), h.x, l.x);
    cvt2(make_float2(v.z, v.w), h.y, l.y);
}
__device__ __forceinline__ unsigned pack_bf2(float a, float b) {
    __nv_bfloat162 t = __halves2bfloat162(__float2bfloat16(a), __float2bfloat16(b));
    return *(unsigned*)&t;
}

// 3-term bf16 GEMM: MT*16 nodes x 32 cols (per warp) x K=128.
// abuf: bf16 [2*MT*16][XS], hi rows 0..MT*16-1, lo rows MT*16..2*MT*16-1.
template <int MT>
__device__ __forceinline__ void mma_gemmT(const __nv_bfloat16* abuf,
                                          const __nv_bfloat16* __restrict__ wp,
                                          int wid, int lane, float c[MT][4][4]) {
    const int row_l = (lane & 7) + ((lane >> 3) & 1) * 8;
    const int koff  = (lane >> 4) * 8;
    const int nrow  = lane >> 2, q = lane & 3;
    const unsigned sb = cvta_s(abuf);
    const int LO = MT * 16;
#pragma unroll
    for (int ks = 0; ks < 8; ks++) {
        uint4 ah[MT], al[MT];
#pragma unroll
        for (int m = 0; m < MT; m++) {
            ldm_x4(ah[m], sb + ((m * 16 + row_l) * XS + ks * 16 + koff) * 2);
            ldm_x4(al[m], sb + ((LO + m * 16 + row_l) * XS + ks * 16 + koff) * 2);
        }
#pragma unroll
        for (int nt = 0; nt < 4; nt++) {
            const int col = wid * 32 + nt * 8 + nrow;
            const uint4 b = *(const uint4*)(wp + ((size_t)(col * 8 + ks) * 4 + q) * 8);
#pragma unroll
            for (int m = 0; m < MT; m++) {
                mma_bf16(c[m][nt], ah[m], b.x, b.y);
                mma_bf16(c[m][nt], ah[m], b.z, b.w);
                mma_bf16(c[m][nt], al[m], b.x, b.y);
            }
        }
    }
}

// ---------------- weight prep + cnt init (once per launch) --------------------
__device__ __forceinline__ uint4 pack_frag(float v0, float v1, float v2, float v3) {
    uint4 r; uint2 h, l;
    cvt2(make_float2(v0, v1), h.x, l.x);
    cvt2(make_float2(v2, v3), h.y, l.y);
    r.x = h.x; r.y = h.y; r.z = l.x; r.w = l.y;
    return r;
}

__global__ void k_wprep(const float* __restrict__ Wd, const float* __restrict__ Wt,
                        const float* __restrict__ Wi, const float* __restrict__ g1W,
                        const float* __restrict__ g2W, const float* __restrict__ Wo1) {
    const int i = blockIdx.x * blockDim.x + threadIdx.x;
    if (i < NN) g_cnt[i] = 1;            // self loop pre-counted
    if (i < 64 * 48 * 4) {
        const int col = i / 192, ks = (i % 192) / 4, q = i % 4;
        const int k0 = ks * 16 + q * 2;
        const float* src = (col < 32) ? Wd + (size_t)col * 768
                                      : Wt + (size_t)(col - 32) * 768;
        *(uint4*)(g_W1p + (size_t)i * 8) =
            pack_frag(src[k0], src[k0 + 1], src[k0 + 8], src[k0 + 9]);
    } else if (i < 64 * 48 * 4 + 4 * 128 * 8 * 4) {
        const int j = i - 64 * 48 * 4;
        const int mat = j >> 12, r = j & 4095;
        const int col = r / 32, ks = (r % 32) / 4, q = r % 4;
        const int k0 = ks * 16 + q * 2;
        const float* W = (mat == 0 ? Wi : mat == 1 ? g1W : mat == 2 ? g2W : Wo1)
                       + (size_t)col * 128;
        __nv_bfloat16* dst = (mat == 0 ? g_Wip : mat == 1 ? g_g1p
                              : mat == 2 ? g_g2p : g_Wo1p);
        *(uint4*)(dst + (size_t)r * 8) =
            pack_frag(W[k0], W[k0 + 1], W[k0 + 8], W[k0 + 9]);
    }
}

// ---------------- CSR build ---------------------------------------------------
__global__ void k_count(const int* __restrict__ ei) {
    int i = blockIdx.x * blockDim.x + threadIdx.x;
    if (i < EE) atomicAdd(&g_cnt[ei[EE + i]], 1);
}
__global__ void k_scan1() {
    __shared__ int sh[256];
    const int b = blockIdx.x, t = threadIdx.x;
    const int base = b * SCL;
    int s = 0;
    for (int i = t; i < SCL; i += 256) s += g_cnt[base + i];
    sh[t] = s;
    __syncthreads();
    for (int o = 128; o > 0; o >>= 1) {
        if (t < o) sh[t] += sh[t + o];
        __syncthreads();
    }
    if (t == 0) g_part[b] = sh[0];
}
__global__ void k_scan2() {
    if (threadIdx.x == 0) {
        int acc = 0;
        for (int i = 0; i < SCB; i++) { int v = g_part[i]; g_part[i] = acc; acc += v; }
        g_rs[NN] = ET;
    }
}
__global__ void k_scan3() {
    __shared__ int sh[256];
    const int b = blockIdx.x, t = threadIdx.x;
    const int base = b * SCL;
    int loc[4];
    int s = 0;
#pragma unroll
    for (int j = 0; j < 4; j++) {
        const int idx = t * 4 + j;
        loc[j] = (idx < SCL) ? g_cnt[base + idx] : 0;
        s += loc[j];
    }
    sh[t] = s;
    __syncthreads();
    for (int o = 1; o < 256; o <<= 1) {
        int v = (t >= o) ? sh[t - o] : 0;
        __syncthreads();
        sh[t] += v;
        __syncthreads();
    }
    int pre = g_part[b] + (t ? sh[t - 1] : 0);
#pragma unroll
    for (int j = 0; j < 4; j++) {
        const int idx = t * 4 + j;
        if (idx < SCL) {
            g_rs[base + idx] = pre;
            g_cur[base + idx] = pre;
            pre += loc[j];
        }
    }
}
__global__ void k_fill(const int* __restrict__ ei) {
    int i = blockIdx.x * blockDim.x + threadIdx.x;
    if (i >= ET) return;
    int src, dst;
    if (i < EE) { src = ei[i]; dst = ei[EE + i]; }
    else        { src = dst = i - EE; }
    g_csrc[atomicAdd(&g_cur[dst], 1)] = src;
}

// ---------------- features -> x -> Wi -> g1 projection + attn logits ---------
__global__ void __launch_bounds__(128) k_features(
    const float* __restrict__ des, const float* __restrict__ twt,
    const float* __restrict__ npr, const float* __restrict__ cpr,
    const float* __restrict__ bd,  const float* __restrict__ bt,
    const float* __restrict__ Wn,  const float* __restrict__ bn,
    const float* __restrict__ Wc,  const float* __restrict__ bc,
    const float* __restrict__ bi,
    const float* __restrict__ g1as, const float* __restrict__ g1ad)
{
    __shared__ __align__(16) __nv_bfloat16 xb[128 * XS];   // hi rows 0-63, lo 64-127

    const int tid = threadIdx.x;
    const int n0  = blockIdx.x * NT;
    const int wid = tid >> 5, lane = tid & 31;
    const int lr = lane >> 2, lq = lane & 3, lq2 = lq * 2;

    // ---- stage 1: direct register fragments, warp = (arr, node-half) --------
    const int arr = wid & 1;
    const int mh  = wid >> 1;            // nodes mh*32 .. mh*32+31

    float c1[2][4][4];
#pragma unroll
    for (int m = 0; m < 2; m++)
#pragma unroll
        for (int nt = 0; nt < 4; nt++)
#pragma unroll
            for (int q = 0; q < 4; q++) c1[m][nt][q] = 0.f;

    {
        const float* A = arr ? twt : des;
        const float* rp[2][2];
#pragma unroll
        for (int m = 0; m < 2; m++) {
            int r0 = n0 + mh * 32 + m * 16 + lr;
            int r1 = r0 + 8;
            if (r0 >= NN) r0 = NN - 1;
            if (r1 >= NN) r1 = NN - 1;
            rp[m][0] = A + (size_t)r0 * 768 + lq2;
            rp[m][1] = A + (size_t)r1 * 768 + lq2;
        }
#pragma unroll 2
        for (int ks = 0; ks < 48; ks++) {
            const int kk = ks * 16;
            uint4 ah[2], al[2];
#pragma unroll
            for (int m = 0; m < 2; m++) {
                const float2 v0 = *(const float2*)(rp[m][0] + kk);
                const float2 v1 = *(const float2*)(rp[m][1] + kk);
                const float2 v2 = *(const float2*)(rp[m][0] + kk + 8);
                const float2 v3 = *(const float2*)(rp[m][1] + kk + 8);
                cvt2(v0, ah[m].x, al[m].x);
                cvt2(v1, ah[m].y, al[m].y);
                cvt2(v2, ah[m].z, al[m].z);
                cvt2(v3, ah[m].w, al[m].w);
            }
#pragma unroll
            for (int nt = 0; nt < 4; nt++) {
                const int col = arr * 32 + nt * 8 + lr;
                const uint4 b = *(const uint4*)(g_W1p +
                    ((size_t)(col * 48 + ks) * 4 + lq) * 8);
#pragma unroll
                for (int m = 0; m < 2; m++) {
                    mma_bf16(c1[m][nt], ah[m], b.x, b.y);
                    mma_bf16(c1[m][nt], ah[m], b.z, b.w);
                    mma_bf16(c1[m][nt], al[m], b.x, b.y);
                }
            }
        }
    }

    // ---- stage-1 epilogue: bias + lrelu -> xb hi/lo [node][col] -------------
#pragma unroll
    for (int m = 0; m < 2; m++)
#pragma unroll
        for (int nt = 0; nt < 4; nt++) {
            const int cb = arr * 32 + nt * 8 + lq2;
            const float b0 = (cb < 32) ? bd[cb] : bt[cb - 32];
            const float b1 = (cb + 1 < 32) ? bd[cb + 1] : bt[cb - 31];
            const int r0 = mh * 32 + m * 16 + lr;
            const float v00 = lrelu01(c1[m][nt][0] + b0), v01 = lrelu01(c1[m][nt][1] + b1);
            const float v10 = lrelu01(c1[m][nt][2] + b0), v11 = lrelu01(c1[m][nt][3] + b1);
            *(unsigned*)(xb + r0 * XS + cb)        = pack_bf2(v00, v01);
            *(unsigned*)(xb + (64 + r0) * XS + cb) = pack_bf2(
                v00 - __bfloat162float(__float2bfloat16(v00)),
                v01 - __bfloat162float(__float2bfloat16(v01)));
            *(unsigned*)(xb + (r0 + 8) * XS + cb)  = pack_bf2(v10, v11);
            *(unsigned*)(xb + (72 + r0) * XS + cb) = pack_bf2(
                v10 - __bfloat162float(__float2bfloat16(v10)),
                v11 - __bfloat162float(__float2bfloat16(v11)));
        }
    {   // num/cat cols 64-127 over 64 nodes
        const int col = tid >> 1, nh = (tid & 1) * 32;
        if (col < 32) {
            const float w0 = Wn[col * 5], w1 = Wn[col * 5 + 1], w2 = Wn[col * 5 + 2],
                        w3 = Wn[col * 5 + 3], w4 = Wn[col * 5 + 4];
            const float b = bn[col];
            for (int m = 0; m < 32; m++) {
                int gr = n0 + nh + m; if (gr >= NN) gr = NN - 1;
                const float* r = npr + (size_t)gr * 5;
                const float v = lrelu01(r[0]*w0 + r[1]*w1 + r[2]*w2 + r[3]*w3 + r[4]*w4 + b);
                const __nv_bfloat16 h = __float2bfloat16(v);
                xb[(nh + m) * XS + 64 + col] = h;
                xb[(64 + nh + m) * XS + 64 + col] = __float2bfloat16(v - __bfloat162float(h));
            }
        } else {
            const int jj = col - 32;
            const float w0 = Wc[jj * 3], w1 = Wc[jj * 3 + 1], w2 = Wc[jj * 3 + 2];
            const float b = bc[jj];
            for (int m = 0; m < 32; m++) {
                int gr = n0 + nh + m; if (gr >= NN) gr = NN - 1;
                const float* r = cpr + (size_t)gr * 3;
                const float v = lrelu01(r[0]*w0 + r[1]*w1 + r[2]*w2 + b);
                const __nv_bfloat16 h = __float2bfloat16(v);
                xb[(nh + m) * XS + 96 + jj] = h;
                xb[(64 + nh + m) * XS + 96 + jj] = __float2bfloat16(v - __bfloat162float(h));
            }
        }
    }
    __syncthreads();

    // ---- stage 2: x2 = lrelu(x @ Wi^T + bi), write back into xb -------------
    {
        float c[4][4][4];
#pragma unroll
        for (int m = 0; m < 4; m++)
#pragma unroll
            for (int nt = 0; nt < 4; nt++)
#pragma unroll
                for (int q = 0; q < 4; q++) c[m][nt][q] = 0.f;
        mma_gemmT<4>(xb, g_Wip, wid, lane, c);
        __syncthreads();          // all reads of xb complete
#pragma unroll
        for (int m = 0; m < 4; m++)
#pragma unroll
            for (int nt = 0; nt < 4; nt++) {
                const int cb = wid * 32 + nt * 8 + lq2;
                const float b0 = bi[cb], b1 = bi[cb + 1];
                const int r0 = m * 16 + lr;
                const float v00 = lrelu01(c[m][nt][0] + b0), v01 = lrelu01(c[m][nt][1] + b1);
                const float v10 = lrelu01(c[m][nt][2] + b0), v11 = lrelu01(c[m][nt][3] + b1);
                *(unsigned*)(xb + r0 * XS + cb)        = pack_bf2(v00, v01);
                *(unsigned*)(xb + (64 + r0) * XS + cb) = pack_bf2(
                    v00 - __bfloat162float(__float2bfloat16(v00)),
                    v01 - __bfloat162float(__float2bfloat16(v01)));
                *(unsigned*)(xb + (r0 + 8) * XS + cb)  = pack_bf2(v10, v11);
                *(unsigned*)(xb + (72 + r0) * XS + cb) = pack_bf2(
                    v10 - __bfloat162float(__float2bfloat16(v10)),
                    v11 - __bfloat162float(__float2bfloat16(v11)));
            }
    }
    __syncthreads();

    // ---- stage 3: xw1 = x2 @ g1_W^T + per-head logits -----------------------
    {
        float c[4][4][4];
#pragma unroll
        for (int m = 0; m < 4; m++)
#pragma unroll
            for (int nt = 0; nt < 4; nt++)
#pragma unroll
                for (int q = 0; q < 4; q++) c[m][nt][q] = 0.f;
        mma_gemmT<4>(xb, g_g1p, wid, lane, c);

        float ps[4][2], pd[4][2];
#pragma unroll
        for (int m = 0; m < 4; m++) { ps[m][0]=ps[m][1]=pd[m][0]=pd[m][1]=0.f; }
#pragma unroll
        for (int m = 0; m < 4; m++)
#pragma unroll
            for (int nt = 0; nt < 4; nt++) {
                const int cb = wid * 32 + nt * 8 + lq2;
                const int node = n0 + m * 16 + lr;
                if (node < NN)
                    *(float2*)(g_xw1 + (size_t)node * HID + cb) =
                        make_float2(c[m][nt][0], c[m][nt][1]);
                if (node + 8 < NN)
                    *(float2*)(g_xw1 + (size_t)(node + 8) * HID + cb) =
                        make_float2(c[m][nt][2], c[m][nt][3]);
                const float a0 = g1as[cb], a1 = g1as[cb + 1];
                const float d0 = g1ad[cb], d1 = g1ad[cb + 1];
                ps[m][0] += c[m][nt][0]*a0 + c[m][nt][1]*a1;
                ps[m][1] += c[m][nt][2]*a0 + c[m][nt][3]*a1;
                pd[m][0] += c[m][nt][0]*d0 + c[m][nt][1]*d1;
                pd[m][1] += c[m][nt][2]*d0 + c[m][nt][3]*d1;
            }
#pragma unroll
        for (int m = 0; m < 4; m++)
#pragma unroll
            for (int rr = 0; rr < 2; rr++) {
#pragma unroll
                for (int o = 1; o < 4; o <<= 1) {
                    ps[m][rr] += __shfl_xor_sync(0xffffffffu, ps[m][rr], o);
                    pd[m][rr] += __shfl_xor_sync(0xffffffffu, pd[m][rr], o);
                }
            }
        if ((lane & 3) == 0) {
#pragma unroll
            for (int m = 0; m < 4; m++) {
                const int node = n0 + m * 16 + lr;
                if (node < NN) {
                    g_es1[node * 4 + wid] = ps[m][0];
                    g_ed1[node * 4 + wid] = pd[m][0];
                }
                if (node + 8 < NN) {
                    g_es1[(node + 8) * 4 + wid] = ps[m][1];
                    g_ed1[(node + 8) * 4 + wid] = pd[m][1];
                }
            }
        }
    }
}

// ---------------- GAT1 aggregation: warp-per-dst gather, fused exp ------------
__global__ void __launch_bounds__(256) k_agg1(const float* __restrict__ g1b) {
    const int d = (blockIdx.x * blockDim.x + threadIdx.x) >> 5;
    const int lane = threadIdx.x & 31;
    if (d >= NN) return;
    const int beg = g_rs[d], end = g_rs[d + 1];
    const int h = lane >> 3;
    const float edv = g_ed1[d * 4 + h];
    float4 acc = {0.f, 0.f, 0.f, 0.f};
    float den = 0.f;
#pragma unroll 2
    for (int s = beg; s < end; s++) {
        const int src = __ldg(&g_csrc[s]);
        const float es = __ldg(&g_es1[src * 4 + h]);
        const float ev = __expf(lrelu2(es + edv));
        const float4 xs = *(const float4*)(g_xw1 + (size_t)src * HID + lane * 4);
        acc.x += xs.x * ev; acc.y += xs.y * ev;
        acc.z += xs.z * ev; acc.w += xs.w * ev;
        den += ev;
    }
    const float inv = 1.f / den;
    const float4 b = ((const float4*)g1b)[lane];
    float4 o;
    o.x = acc.x * inv + b.x; o.y = acc.y * inv + b.y;
    o.z = acc.z * inv + b.z; o.w = acc.w * inv + b.w;
    *(float4*)(g_out1 + (size_t)d * HID + lane * 4) = o;
}

// ---------------- GAT2 projection + attn logits -------------------------------
__global__ void __launch_bounds__(128) k_gat2_prep(
    const float* __restrict__ g2as, const float* __restrict__ g2ad)
{
    __shared__ __align__(16) __nv_bfloat16 ab[128 * XS];
    __shared__ float sp[2][4][NT];
    const int tid = threadIdx.x, n0 = blockIdx.x * NT;
    const int wid = tid >> 5, lane = tid & 31;
    const int lr = lane >> 2, lq2 = (lane & 3) * 2;

    for (int i = 0; i < 16; i++) {
        const int idx = tid + i * 128;          // 2048 float4
        const int node = idx >> 5, c4 = idx & 31;
        int gr = n0 + node; if (gr >= NN) gr = NN - 1;
        const float4 v = *(const float4*)(g_out1 + (size_t)gr * HID + 4 * c4);
        uint2 h, l;
        split4(v, h, l);
        *(uint2*)(ab + node * XS + 4 * c4) = h;
        *(uint2*)(ab + (64 + node) * XS + 4 * c4) = l;
    }
    __syncthreads();

    float c[4][4][4];
#pragma unroll
    for (int m = 0; m < 4; m++)
#pragma unroll
        for (int nt = 0; nt < 4; nt++)
#pragma unroll
            for (int q = 0; q < 4; q++) c[m][nt][q] = 0.f;
    mma_gemmT<4>(ab, g_g2p, wid, lane, c);

    float ps[4][2], pd[4][2];
#pragma unroll
    for (int m = 0; m < 4; m++) { ps[m][0]=ps[m][1]=pd[m][0]=pd[m][1]=0.f; }
#pragma unroll
    for (int m = 0; m < 4; m++)
#pragma unroll
        for (int nt = 0; nt < 4; nt++) {
            const int cb = wid * 32 + nt * 8 + lq2;
            const int node = n0 + m * 16 + lr;
            if (node < NN)
                *(float2*)(g_xw2 + (size_t)node * HID + cb) =
                    make_float2(c[m][nt][0], c[m][nt][1]);
            if (node + 8 < NN)
                *(float2*)(g_xw2 + (size_t)(node + 8) * HID + cb) =
                    make_float2(c[m][nt][2], c[m][nt][3]);
            const float a0 = g2as[cb], a1 = g2as[cb + 1];
            const float d0 = g2ad[cb], d1 = g2ad[cb + 1];
            ps[m][0] += c[m][nt][0]*a0 + c[m][nt][1]*a1;
            ps[m][1] += c[m][nt][2]*a0 + c[m][nt][3]*a1;
            pd[m][0] += c[m][nt][0]*d0 + c[m][nt][1]*d1;
            pd[m][1] += c[m][nt][2]*d0 + c[m][nt][3]*d1;
        }
#pragma unroll
    for (int m = 0; m < 4; m++)
#pragma unroll
        for (int rr = 0; rr < 2; rr++) {
#pragma unroll
            for (int o = 1; o < 4; o <<= 1) {
                ps[m][rr] += __shfl_xor_sync(0xffffffffu, ps[m][rr], o);
                pd[m][rr] += __shfl_xor_sync(0xffffffffu, pd[m][rr], o);
            }
        }
    if ((lane & 3) == 0) {
#pragma unroll
        for (int m = 0; m < 4; m++) {
            sp[0][wid][m * 16 + lr]     = ps[m][0];
            sp[0][wid][m * 16 + lr + 8] = ps[m][1];
            sp[1][wid][m * 16 + lr]     = pd[m][0];
            sp[1][wid][m * 16 + lr + 8] = pd[m][1];
        }
    }
    __syncthreads();
    if (tid < NT) {
        if (n0 + tid < NN)
            g_es2[n0 + tid] = sp[0][0][tid] + sp[0][1][tid] + sp[0][2][tid] + sp[0][3][tid];
    } else {
        const int m = tid - NT;
        if (n0 + m < NN)
            g_ed2[n0 + m] = sp[1][0][m] + sp[1][1][m] + sp[1][2][m] + sp[1][3][m];
    }
}

// ---------------- GAT2 aggregation --------------------------------------------
__global__ void __launch_bounds__(256) k_agg2(const float* __restrict__ g2b) {
    const int d = (blockIdx.x * blockDim.x + threadIdx.x) >> 5;
    const int lane = threadIdx.x & 31;
    if (d >= NN) return;
    const int beg = g_rs[d], end = g_rs[d + 1];
    const float edv = g_ed2[d];
    float4 acc = {0.f, 0.f, 0.f, 0.f};
    float den = 0.f;
#pragma unroll 2
    for (int s = beg; s < end; s++) {
        const int src = __ldg(&g_csrc[s]);
        const float es = __ldg(&g_es2[src]);
        const float ev = __expf(lrelu2(es + edv));
        const float4 xs = *(const float4*)(g_xw2 + (size_t)src * HID + lane * 4);
        acc.x += xs.x * ev; acc.y += xs.y * ev;
        acc.z += xs.z * ev; acc.w += xs.w * ev;
        den += ev;
    }
    const float inv = 1.f / den;
    const float4 b = ((const float4*)g2b)[lane];
    float4 o;
    o.x = acc.x * inv + b.x; o.y = acc.y * inv + b.y;
    o.z = acc.z * inv + b.z; o.w = acc.w * inv + b.w;
    *(float4*)(g_out2 + (size_t)d * HID + lane * 4) = o;
}

// ---------------- output head ------------------------------------------------
__global__ void __launch_bounds__(128) k_final(
    const float* __restrict__ bo1, const float* __restrict__ Wo2,
    const float* __restrict__ bo2, float* __restrict__ out)
{
    __shared__ __align__(16) __nv_bfloat16 ab[128 * XS];
    __shared__ float sp[2][4][NT];
    const int tid = threadIdx.x, n0 = blockIdx.x * NT;
    const int wid = tid >> 5, lane = tid & 31;
    const int lr = lane >> 2, lq2 = (lane & 3) * 2;

    for (int i = 0; i < 16; i++) {
        const int idx = tid + i * 128;
        const int node = idx >> 5, c4 = idx & 31;
        int gr = n0 + node; if (gr >= NN) gr = NN - 1;
        const float4 v = *(const float4*)(g_out2 + (size_t)gr * HID + 4 * c4);
        uint2 h, l;
        split4(v, h, l);
        *(uint2*)(ab + node * XS + 4 * c4) = h;
        *(uint2*)(ab + (64 + node) * XS + 4 * c4) = l;
    }
    __syncthreads();

    float c[4][4][4];
#pragma unroll
    for (int m = 0; m < 4; m++)
#pragma unroll
        for (int nt = 0; nt < 4; nt++)
#pragma unroll
            for (int q = 0; q < 4; q++) c[m][nt][q] = 0.f;
    mma_gemmT<4>(ab, g_Wo1p, wid, lane, c);

    float p0[4][2], p1[4][2];
#pragma unroll
    for (int m = 0; m < 4; m++) { p0[m][0]=p0[m][1]=p1[m][0]=p1[m][1]=0.f; }
#pragma unroll
    for (int m = 0; m < 4; m++)
#pragma unroll
        for (int nt = 0; nt < 4; nt++) {
            const int cb = wid * 32 + nt * 8 + lq2;
            const float b0 = bo1[cb], b1 = bo1[cb + 1];
            const float w00 = Wo2[cb], w01 = Wo2[cb + 1];
            const float w10 = Wo2[128 + cb], w11 = Wo2[128 + cb + 1];
            const float y00 = lrelu01(c[m][nt][0] + b0), y01 = lrelu01(c[m][nt][1] + b1);
            const float y10 = lrelu01(c[m][nt][2] + b0), y11 = lrelu01(c[m][nt][3] + b1);
            p0[m][0] += y00*w00 + y01*w01;  p0[m][1] += y10*w00 + y11*w01;
            p1[m][0] += y00*w10 + y01*w11;  p1[m][1] += y10*w10 + y11*w11;
        }
#pragma unroll
    for (int m = 0; m < 4; m++)
#pragma unroll
        for (int rr = 0; rr < 2; rr++) {
#pragma unroll
            for (int o = 1; o < 4; o <<= 1) {
                p0[m][rr] += __shfl_xor_sync(0xffffffffu, p0[m][rr], o);
                p1[m][rr] += __shfl_xor_sync(0xffffffffu, p1[m][rr], o);
            }
        }
    if ((lane & 3) == 0) {
#pragma unroll
        for (int m = 0; m < 4; m++) {
            sp[0][wid][m * 16 + lr]     = p0[m][0];
            sp[0][wid][m * 16 + lr + 8] = p0[m][1];
            sp[1][wid][m * 16 + lr]     = p1[m][0];
            sp[1][wid][m * 16 + lr + 8] = p1[m][1];
        }
    }
    __syncthreads();
    if (tid < NT) {
        if (n0 + tid < NN)
            out[(size_t)(n0 + tid) * 2] =
                sp[0][0][tid] + sp[0][1][tid] + sp[0][2][tid] + sp[0][3][tid] + bo2[0];
    } else {
        const int m = tid - NT;
        if (n0 + m < NN)
            out[(size_t)(n0 + m) * 2 + 1] =
                sp[1][0][m] + sp[1][1][m] + sp[1][2][m] + sp[1][3][m] + bo2[1];
    }
}

// ---------------- launch ------------------------------------------------------
extern "C" void kernel_launch(void* const* d_in, const int* in_sizes, int n_in,
                              void* d_out, int out_size) {
    const float* des  = (const float*)d_in[0];
    const float* twt  = (const float*)d_in[1];
    const float* npr  = (const float*)d_in[2];
    const float* cpr  = (const float*)d_in[3];
    const int*   ei   = (const int*)d_in[4];   // JAX x64 disabled -> int32
    const float* Wd = (const float*)d_in[5];   const float* bd = (const float*)d_in[6];
    const float* Wt = (const float*)d_in[7];   const float* bt = (const float*)d_in[8];
    const float* Wn = (const float*)d_in[9];   const float* bn = (const float*)d_in[10];
    const float* Wc = (const float*)d_in[11];  const float* bc = (const float*)d_in[12];
    const float* Wi = (const float*)d_in[13];  const float* bi = (const float*)d_in[14];
    const float* g1W  = (const float*)d_in[15];
    const float* g1as = (const float*)d_in[16];
    const float* g1ad = (const float*)d_in[17];
    const float* g1b  = (const float*)d_in[18];
    const float* g2W  = (const float*)d_in[19];
    const float* g2as = (const float*)d_in[20];
    const float* g2ad = (const float*)d_in[21];
    const float* g2b  = (const float*)d_in[22];
    const float* Wo1  = (const float*)d_in[23]; const float* bo1 = (const float*)d_in[24];
    const float* Wo2  = (const float*)d_in[25]; const float* bo2 = (const float*)d_in[26];
    float* out = (float*)d_out;

    const int NB = (NN + NT - 1) / NT;        // 1563 node blocks
    k_wprep<<<(NN + 255) / 256, 256>>>(Wd, Wt, Wi, g1W, g2W, Wo1);  // + cnt init
    k_count<<<(EE + 255) / 256, 256>>>(ei);
    k_scan1<<<SCB, 256>>>();
    k_features<<<NB, 128>>>(des, twt, npr, cpr, bd, bt, Wn, bn, Wc, bc,
                            bi, g1as, g1ad);          // ncu-captured slot (idx 3)
    k_scan2<<<1, 32>>>();
    k_scan3<<<SCB, 256>>>();
    k_fill<<<(ET + 255) / 256, 256>>>(ei);
    k_agg1<<<(NN * 32 + 255) / 256, 256>>>(g1b);
    k_gat2_prep<<<NB, 128>>>(g2as, g2ad);
    k_agg2<<<(NN * 32 + 255) / 256, 256>>>(g2b);
    k_final<<<NB, 128>>>(bo1, Wo2, bo2, out);
}